// round 1
// baseline (speedup 1.0000x reference)
#include <cuda_runtime.h>
#include <math.h>

#define BSZ 32
#define TT  512
#define HH  1024
#define DHH 64
#define NHH 16
#define MTOT (BSZ*TT)   // 16384

// Scratch (device globals: allocation-free contract)
__device__ float g_q[(size_t)MTOT * HH];   // 64 MB
__device__ float g_k[(size_t)MTOT * HH];   // 64 MB
__device__ float g_v[(size_t)MTOT * DHH];  //  4 MB
__device__ float g_m[(size_t)MTOT * DHH];  //  4 MB

// ---------------------------------------------------------------------------
// SGEMM with optional bias: C[M,N] = A[M,K] @ B[K,N] (+ bias[N])
// 128x128 tile, BK=16, 256 threads, 8x8 per thread (split 4+4 rows/cols).
// Requires M%128==0, K%16==0. N guarded (for N=64 case).
// ---------------------------------------------------------------------------
__global__ __launch_bounds__(256) void sgemm_bias(
    const float* __restrict__ A, const float* __restrict__ B,
    const float* __restrict__ bias, float* __restrict__ C,
    int M, int N, int K)
{
    __shared__ float As[16][128];   // As[k][m]
    __shared__ float Bs[16][128];   // Bs[k][n]

    const int tid = threadIdx.x;
    const int tx = tid & 15;        // col group
    const int ty = tid >> 4;        // row group
    const int m0 = blockIdx.y * 128;
    const int n0 = blockIdx.x * 128;

    float acc[8][8];
    #pragma unroll
    for (int i = 0; i < 8; i++)
        #pragma unroll
        for (int j = 0; j < 8; j++) acc[i][j] = 0.f;

    for (int k0 = 0; k0 < K; k0 += 16) {
        // Load A tile (128x16) transposed into As
        #pragma unroll
        for (int it = 0; it < 2; it++) {
            int idx = tid * 2 + it;            // 0..511
            int r   = idx >> 2;                // 0..127
            int c4  = idx & 3;                 // 0..3
            float4 a = *(const float4*)&A[(size_t)(m0 + r) * K + k0 + c4 * 4];
            As[c4*4+0][r] = a.x;
            As[c4*4+1][r] = a.y;
            As[c4*4+2][r] = a.z;
            As[c4*4+3][r] = a.w;
        }
        // Load B tile (16x128)
        #pragma unroll
        for (int it = 0; it < 2; it++) {
            int idx = tid * 2 + it;
            int r   = idx >> 5;                // 0..15
            int c4  = idx & 31;                // 0..31
            int col = n0 + c4 * 4;
            float4 bvv = make_float4(0.f, 0.f, 0.f, 0.f);
            if (col < N) bvv = *(const float4*)&B[(size_t)(k0 + r) * N + col];
            *(float4*)&Bs[r][c4*4] = bvv;
        }
        __syncthreads();

        #pragma unroll
        for (int kk = 0; kk < 16; kk++) {
            float a[8], b[8];
            *(float4*)&a[0] = *(const float4*)&As[kk][ty*4];
            *(float4*)&a[4] = *(const float4*)&As[kk][64 + ty*4];
            *(float4*)&b[0] = *(const float4*)&Bs[kk][tx*4];
            *(float4*)&b[4] = *(const float4*)&Bs[kk][64 + tx*4];
            #pragma unroll
            for (int i = 0; i < 8; i++)
                #pragma unroll
                for (int j = 0; j < 8; j++)
                    acc[i][j] += a[i] * b[j];
        }
        __syncthreads();
    }

    // Bias
    float bb[8];
    #pragma unroll
    for (int j = 0; j < 8; j++) {
        int col = n0 + ((j < 4) ? (tx*4 + j) : (64 + tx*4 + j - 4));
        bb[j] = (bias != nullptr && col < N) ? bias[col] : 0.f;
    }
    // Store
    #pragma unroll
    for (int i = 0; i < 8; i++) {
        int row = m0 + ((i < 4) ? (ty*4 + i) : (64 + ty*4 + i - 4));
        #pragma unroll
        for (int g = 0; g < 2; g++) {
            int col = n0 + g*64 + tx*4;
            if (col < N) {
                float4 o;
                o.x = acc[i][g*4+0] + bb[g*4+0];
                o.y = acc[i][g*4+1] + bb[g*4+1];
                o.z = acc[i][g*4+2] + bb[g*4+2];
                o.w = acc[i][g*4+3] + bb[g*4+3];
                *(float4*)&C[(size_t)row * N + col] = o;
            }
        }
    }
}

// ---------------------------------------------------------------------------
// Fused causal flash-attention per (b, head, 64-row q tile).
// q,k: [MTOT, HH] (head h occupies cols h*64..h*64+63). v: [MTOT, 64].
// Writes attn_vec [b, h, t, d] fp32.
// Thread (ty,tx): S rows ty*4+i, S cols / O cols tx*4+j.
// KtS aliases Kt (K transposed) then P (prob tile).
// ---------------------------------------------------------------------------
__global__ __launch_bounds__(256, 2) void attn_kernel(
    const float* __restrict__ q, const float* __restrict__ k,
    const float* __restrict__ v, float* __restrict__ attn_out)
{
    __shared__ float Qt[64*64];    // Qt[d][qr]
    __shared__ float KtS[64*64];   // Kt[d][kc]  then  P[qr][kc]
    __shared__ float Vs[64*64];    // Vs[kc][d]

    const int b  = blockIdx.z;
    const int h  = blockIdx.y;
    const int qi = blockIdx.x;
    const int tid = threadIdx.x;
    const int tx = tid & 15;
    const int ty = tid >> 4;

    // Load Q tile transposed
    {
        const int r  = tid >> 2;
        const int d0 = (tid & 3) << 4;
        const float* qp = q + ((size_t)(b*TT + qi*64 + r) * HH + h*DHH + d0);
        #pragma unroll
        for (int j4 = 0; j4 < 4; j4++) {
            float4 val = *(const float4*)(qp + j4*4);
            Qt[(d0 + j4*4 + 0)*64 + r] = val.x;
            Qt[(d0 + j4*4 + 1)*64 + r] = val.y;
            Qt[(d0 + j4*4 + 2)*64 + r] = val.z;
            Qt[(d0 + j4*4 + 3)*64 + r] = val.w;
        }
    }

    float m_run[4], l_run[4], Oacc[4][4];
    #pragma unroll
    for (int i = 0; i < 4; i++) {
        m_run[i] = -1e30f; l_run[i] = 0.f;
        #pragma unroll
        for (int j = 0; j < 4; j++) Oacc[i][j] = 0.f;
    }

    for (int kt = 0; kt <= qi; kt++) {
        __syncthreads();   // previous iteration done reading KtS/Vs (also covers Qt stores)
        {
            const int r  = tid >> 2;
            const int d0 = (tid & 3) << 4;
            const float* kp = k + ((size_t)(b*TT + kt*64 + r) * HH + h*DHH + d0);
            const float* vp = v + ((size_t)(b*TT + kt*64 + r) * DHH + d0);
            #pragma unroll
            for (int j4 = 0; j4 < 4; j4++) {
                float4 kv = *(const float4*)(kp + j4*4);
                KtS[(d0 + j4*4 + 0)*64 + r] = kv.x;
                KtS[(d0 + j4*4 + 1)*64 + r] = kv.y;
                KtS[(d0 + j4*4 + 2)*64 + r] = kv.z;
                KtS[(d0 + j4*4 + 3)*64 + r] = kv.w;
                float4 vv = *(const float4*)(vp + j4*4);
                *(float4*)&Vs[r*64 + d0 + j4*4] = vv;
            }
        }
        __syncthreads();

        // S = Q @ K^T (this 64x64 tile)
        float s[4][4];
        #pragma unroll
        for (int i = 0; i < 4; i++)
            #pragma unroll
            for (int j = 0; j < 4; j++) s[i][j] = 0.f;

        #pragma unroll 8
        for (int d = 0; d < 64; d++) {
            float4 qv = *(const float4*)&Qt[d*64 + ty*4];
            float4 kv = *(const float4*)&KtS[d*64 + tx*4];
            float qa[4] = {qv.x, qv.y, qv.z, qv.w};
            float ka[4] = {kv.x, kv.y, kv.z, kv.w};
            #pragma unroll
            for (int i = 0; i < 4; i++)
                #pragma unroll
                for (int j = 0; j < 4; j++)
                    s[i][j] += qa[i] * ka[j];
        }

        // scale + causal mask
        #pragma unroll
        for (int i = 0; i < 4; i++) {
            int qg = qi*64 + ty*4 + i;
            #pragma unroll
            for (int j = 0; j < 4; j++) {
                int kg = kt*64 + tx*4 + j;
                s[i][j] = (kg > qg) ? -1e30f : s[i][j] * 0.125f;
            }
        }

        // online softmax update
        float p[4][4];
        #pragma unroll
        for (int i = 0; i < 4; i++) {
            float rmax = fmaxf(fmaxf(s[i][0], s[i][1]), fmaxf(s[i][2], s[i][3]));
            rmax = fmaxf(rmax, __shfl_xor_sync(0xffffffffu, rmax, 8));
            rmax = fmaxf(rmax, __shfl_xor_sync(0xffffffffu, rmax, 4));
            rmax = fmaxf(rmax, __shfl_xor_sync(0xffffffffu, rmax, 2));
            rmax = fmaxf(rmax, __shfl_xor_sync(0xffffffffu, rmax, 1));
            float mnew = fmaxf(m_run[i], rmax);
            float corr = __expf(m_run[i] - mnew);
            float rsum = 0.f;
            #pragma unroll
            for (int j = 0; j < 4; j++) {
                p[i][j] = __expf(s[i][j] - mnew);
                rsum += p[i][j];
            }
            rsum += __shfl_xor_sync(0xffffffffu, rsum, 8);
            rsum += __shfl_xor_sync(0xffffffffu, rsum, 4);
            rsum += __shfl_xor_sync(0xffffffffu, rsum, 2);
            rsum += __shfl_xor_sync(0xffffffffu, rsum, 1);
            m_run[i] = mnew;
            l_run[i] = l_run[i] * corr + rsum;
            #pragma unroll
            for (int j = 0; j < 4; j++) Oacc[i][j] *= corr;
        }

        __syncthreads();   // everyone done reading Kt
        #pragma unroll
        for (int i = 0; i < 4; i++)
            *(float4*)&KtS[(ty*4 + i)*64 + tx*4] = *(float4*)&p[i][0];
        __syncthreads();

        // O += P @ V
        #pragma unroll 8
        for (int kc = 0; kc < 64; kc++) {
            float4 vv = *(const float4*)&Vs[kc*64 + tx*4];
            #pragma unroll
            for (int i = 0; i < 4; i++) {
                float pv = KtS[(ty*4 + i)*64 + kc];
                Oacc[i][0] += pv * vv.x;
                Oacc[i][1] += pv * vv.y;
                Oacc[i][2] += pv * vv.z;
                Oacc[i][3] += pv * vv.w;
            }
        }
    }

    // normalize + write attn_vec [b, h, qg, d]
    #pragma unroll
    for (int i = 0; i < 4; i++) {
        float inv = 1.f / l_run[i];
        int qg = qi*64 + ty*4 + i;
        float4 o;
        o.x = Oacc[i][0] * inv;
        o.y = Oacc[i][1] * inv;
        o.z = Oacc[i][2] * inv;
        o.w = Oacc[i][3] * inv;
        *(float4*)&attn_out[(((size_t)b*NHH + h)*TT + qg)*DHH + tx*4] = o;
    }
}

// ---------------------------------------------------------------------------
// Head-mean pooling: m[b,t,d] = mean_h attn[b,h,t,d]
// ---------------------------------------------------------------------------
__global__ __launch_bounds__(256) void head_mean(
    const float* __restrict__ attn, float* __restrict__ mout)
{
    int idx = blockIdx.x * blockDim.x + threadIdx.x;   // over MTOT * (DHH/4)
    int d4 = idx & 15;
    int bt = idx >> 4;
    int b  = bt / TT;
    int t  = bt % TT;
    float4 acc = make_float4(0.f, 0.f, 0.f, 0.f);
    #pragma unroll
    for (int h = 0; h < NHH; h++) {
        float4 vv = *(const float4*)&attn[(((size_t)b*NHH + h)*TT + t)*DHH + d4*4];
        acc.x += vv.x; acc.y += vv.y; acc.z += vv.z; acc.w += vv.w;
    }
    const float inv = 1.f / (float)NHH;
    float4 o = make_float4(acc.x*inv, acc.y*inv, acc.z*inv, acc.w*inv);
    *(float4*)&mout[(size_t)bt * DHH + d4*4] = o;
}

// ---------------------------------------------------------------------------
extern "C" void kernel_launch(void* const* d_in, const int* in_sizes, int n_in,
                              void* d_out, int out_size)
{
    const float* x  = (const float*)d_in[0];
    const float* Wq = (const float*)d_in[1];
    const float* bq = (const float*)d_in[2];
    const float* Wk = (const float*)d_in[3];
    const float* bk = (const float*)d_in[4];
    const float* Wv = (const float*)d_in[5];
    const float* bv = (const float*)d_in[6];
    const float* Wo = (const float*)d_in[7];

    float* out  = (float*)d_out;                      // [32,512,1024]
    float* attn = out + (size_t)MTOT * HH;            // [32,16,512,64]

    float *q, *k, *v, *m;
    cudaGetSymbolAddress((void**)&q, g_q);
    cudaGetSymbolAddress((void**)&k, g_k);
    cudaGetSymbolAddress((void**)&v, g_v);
    cudaGetSymbolAddress((void**)&m, g_m);

    dim3 blk(256);

    // Projections
    sgemm_bias<<<dim3(HH/128, MTOT/128), blk>>>(x, Wq, bq, q, MTOT, HH, HH);
    sgemm_bias<<<dim3(HH/128, MTOT/128), blk>>>(x, Wk, bk, k, MTOT, HH, HH);
    sgemm_bias<<<dim3(1,      MTOT/128), blk>>>(x, Wv, bv, v, MTOT, DHH, HH);

    // Fused causal attention -> attn_vec
    attn_kernel<<<dim3(TT/64, NHH, BSZ), blk>>>(q, k, v, attn);

    // Head mean + out projection
    head_mean<<<dim3((MTOT * (DHH/4)) / 256), blk>>>(attn, m);
    sgemm_bias<<<dim3(HH/128, MTOT/128), blk>>>(m, Wo, nullptr, out, MTOT, HH, DHH);
}

// round 3
// speedup vs baseline: 1.8982x; 1.8982x over previous
#include <cuda_runtime.h>
#include <cuda_bf16.h>
#include <math.h>
#include <stdint.h>

#define BSZ 32
#define TT  512
#define HH  1024
#define DHH 64
#define NHH 16
#define MTOT (BSZ*TT)   // 16384

// ---------------------------------------------------------------------------
// Scratch (device globals: allocation-free contract)
// ---------------------------------------------------------------------------
__device__ float g_q[(size_t)MTOT * HH];             // 64 MB
__device__ float g_k[(size_t)MTOT * HH];             // 64 MB
__device__ float g_v[(size_t)MTOT * DHH];            //  4 MB
__device__ float g_m[(size_t)MTOT * DHH];            //  4 MB
__device__ __nv_bfloat16 g_xh[(size_t)MTOT * HH];    // 32 MB
__device__ __nv_bfloat16 g_xl[(size_t)MTOT * HH];    // 32 MB
__device__ __nv_bfloat16 g_wth[(size_t)2 * HH * HH]; //  4 MB (Wq^T, Wk^T hi)
__device__ __nv_bfloat16 g_wtl[(size_t)2 * HH * HH]; //  4 MB (lo)

// ---------------------------------------------------------------------------
// Baseline-ISA PTX helpers (compute_103-safe: mma.sync / ldmatrix / cp.async)
// ---------------------------------------------------------------------------
__device__ __forceinline__ uint32_t su32(const void* p) {
    uint32_t a;
    asm("{ .reg .u64 t; cvta.to.shared.u64 t, %1; cvt.u32.u64 %0, t; }"
        : "=r"(a) : "l"(p));
    return a;
}
#define CP16(dst, src) \
    asm volatile("cp.async.cg.shared.global [%0], [%1], 16;" \
                 :: "r"(dst), "l"(src))
#define CP_COMMIT() asm volatile("cp.async.commit_group;" ::: "memory")
#define CP_WAIT1()  asm volatile("cp.async.wait_group 1;" ::: "memory")
#define CP_WAIT0()  asm volatile("cp.async.wait_group 0;" ::: "memory")
#define LDSM4(r0, r1, r2, r3, addr) \
    asm volatile("ldmatrix.sync.aligned.m8n8.x4.shared.b16 {%0,%1,%2,%3}, [%4];" \
                 : "=r"(r0), "=r"(r1), "=r"(r2), "=r"(r3) : "r"(addr))
#define MMA16816(d, a, b) \
    asm volatile("mma.sync.aligned.m16n8k16.row.col.f32.bf16.bf16.f32 " \
                 "{%0,%1,%2,%3}, {%4,%5,%6,%7}, {%8,%9}, {%0,%1,%2,%3};" \
                 : "+f"((d)[0]), "+f"((d)[1]), "+f"((d)[2]), "+f"((d)[3]) \
                 : "r"((a)[0]), "r"((a)[1]), "r"((a)[2]), "r"((a)[3]), \
                   "r"((b)[0]), "r"((b)[1]))

__device__ __forceinline__ uint32_t sw128(uint32_t off) {
    return off ^ ((off >> 3) & 0x70u);
}

// ---------------------------------------------------------------------------
// Split fp32 -> bf16 hi + bf16 lo (x layout unchanged)
// ---------------------------------------------------------------------------
__global__ __launch_bounds__(256) void convert_x(
    const float* __restrict__ x, __nv_bfloat16* __restrict__ xh,
    __nv_bfloat16* __restrict__ xl)
{
    size_t i = ((size_t)blockIdx.x * blockDim.x + threadIdx.x) * 4;
    float4 v = *(const float4*)(x + i);
    __nv_bfloat16 h0 = __float2bfloat16(v.x);
    __nv_bfloat16 h1 = __float2bfloat16(v.y);
    __nv_bfloat16 h2 = __float2bfloat16(v.z);
    __nv_bfloat16 h3 = __float2bfloat16(v.w);
    __nv_bfloat162 hp0; hp0.x = h0; hp0.y = h1;
    __nv_bfloat162 hp1; hp1.x = h2; hp1.y = h3;
    __nv_bfloat162 lp0, lp1;
    lp0.x = __float2bfloat16(v.x - __bfloat162float(h0));
    lp0.y = __float2bfloat16(v.y - __bfloat162float(h1));
    lp1.x = __float2bfloat16(v.z - __bfloat162float(h2));
    lp1.y = __float2bfloat16(v.w - __bfloat162float(h3));
    *(__nv_bfloat162*)(xh + i)     = hp0;
    *(__nv_bfloat162*)(xh + i + 2) = hp1;
    *(__nv_bfloat162*)(xl + i)     = lp0;
    *(__nv_bfloat162*)(xl + i + 2) = lp1;
}

// ---------------------------------------------------------------------------
// Transpose + split Wq/Wk: W[k][n] -> Wt[n][k] in bf16 hi/lo
// ---------------------------------------------------------------------------
__global__ __launch_bounds__(256) void convert_w(
    const float* __restrict__ wq, const float* __restrict__ wk,
    __nv_bfloat16* __restrict__ wth, __nv_bfloat16* __restrict__ wtl)
{
    __shared__ float t[32][33];
    const float* w = blockIdx.z ? wk : wq;
    __nv_bfloat16* oh = wth + (size_t)blockIdx.z * HH * HH;
    __nv_bfloat16* ol = wtl + (size_t)blockIdx.z * HH * HH;
    int n0 = blockIdx.x * 32, k0 = blockIdx.y * 32;
    int tx = threadIdx.x & 31, ty = threadIdx.x >> 5;
    #pragma unroll
    for (int j = 0; j < 4; j++)
        t[ty + j*8][tx] = w[(size_t)(k0 + ty + j*8) * HH + n0 + tx];
    __syncthreads();
    #pragma unroll
    for (int j = 0; j < 4; j++) {
        int n = n0 + ty + j*8, k = k0 + tx;
        float v = t[tx][ty + j*8];
        __nv_bfloat16 h = __float2bfloat16(v);
        oh[(size_t)n * HH + k] = h;
        ol[(size_t)n * HH + k] = __float2bfloat16(v - __bfloat162float(h));
    }
}

// ---------------------------------------------------------------------------
// Fused Q+K projection: mma.sync bf16, 3-MMA fp32-compensated split.
// Block tile M=128, N=128, BK=64. 8 warps (4 M x 2 N), warp tile 32x64.
// Double-buffered cp.async stages of 64 KB:
//   stage: Ah[128x128B] Al Bh Bl (16 KB each)
// grid: x = ntile (0..15: 0-7 -> Q col tiles, 8-15 -> K), y = mtile (0..127)
// ---------------------------------------------------------------------------
#define QK_STAGE 65536
#define QK_SMEM  (2 * QK_STAGE)

__global__ __launch_bounds__(256, 1) void qk_gemm(
    const __nv_bfloat16* __restrict__ xh, const __nv_bfloat16* __restrict__ xl,
    const __nv_bfloat16* __restrict__ wth, const __nv_bfloat16* __restrict__ wtl,
    const float* __restrict__ bq, const float* __restrict__ bk,
    float* __restrict__ qo, float* __restrict__ ko)
{
    extern __shared__ char smem[];
    const uint32_t sb = su32(smem);
    const int tid = threadIdx.x;
    const int lane = tid & 31;
    const int wid = tid >> 5;
    const int warp_m = wid & 3;          // 4 warps along M
    const int warp_n = wid >> 2;         // 2 warps along N

    const int ntile = blockIdx.x;
    const int which = ntile >> 3;
    const int n0 = (ntile & 7) * 128;    // col offset within this proj
    const int m0 = blockIdx.y * 128;

    const __nv_bfloat16* wh = wth + (size_t)which * HH * HH;
    const __nv_bfloat16* wl = wtl + (size_t)which * HH * HH;
    const float* bias = which ? bk : bq;
    float* out = which ? ko : qo;

    float c[2][8][4];
    #pragma unroll
    for (int tm = 0; tm < 2; tm++)
        #pragma unroll
        for (int j = 0; j < 8; j++)
            #pragma unroll
            for (int r = 0; r < 4; r++) c[tm][j][r] = 0.f;

    // ---- stage loader ----
    auto load_stage = [&](int stage, int k0) {
        const uint32_t sa = sb + stage * QK_STAGE;
        #pragma unroll
        for (int i = 0; i < 4; i++) {
            int s = tid + (i << 8);
            int r = s >> 3, ch = s & 7;
            uint32_t off = sw128((uint32_t)(r * 128 + ch * 16));
            const size_t ga = (size_t)(m0 + r) * HH + k0 + ch * 8;
            const size_t gb = (size_t)(n0 + r) * HH + k0 + ch * 8;
            CP16(sa + off,         xh + ga);
            CP16(sa + 16384 + off, xl + ga);
            CP16(sa + 32768 + off, wh + gb);
            CP16(sa + 49152 + off, wl + gb);
        }
        CP_COMMIT();
    };

    load_stage(0, 0);

    for (int cch = 0; cch < 16; cch++) {
        if (cch + 1 < 16) { load_stage((cch + 1) & 1, (cch + 1) * 64); CP_WAIT1(); }
        else              { CP_WAIT0(); }
        __syncthreads();

        const uint32_t sa = sb + (cch & 1) * QK_STAGE;
        #pragma unroll
        for (int kk = 0; kk < 4; kk++) {
            const int kc0 = kk * 2;   // 16B-chunk index of this k16
            // A fragments (hi + lo), 2 m-tiles
            uint32_t ah[2][4], al[2][4];
            {
                const int mat = lane >> 3, rin = lane & 7;
                #pragma unroll
                for (int tm = 0; tm < 2; tm++) {
                    int row = warp_m * 32 + tm * 16 + (mat & 1) * 8 + rin;
                    int ch  = kc0 + (mat >> 1);
                    uint32_t off = sw128((uint32_t)(row * 128 + ch * 16));
                    LDSM4(ah[tm][0], ah[tm][1], ah[tm][2], ah[tm][3], sa + off);
                    LDSM4(al[tm][0], al[tm][1], al[tm][2], al[tm][3],
                          sa + 16384 + off);
                }
            }
            // B fragments (hi + lo), 8 n-groups (2 per ldmatrix.x4)
            uint32_t bh[8][2], bl[8][2];
            {
                const int mat = lane >> 3, rin = lane & 7;
                #pragma unroll
                for (int jp = 0; jp < 4; jp++) {
                    int grp = jp * 2 + (mat >> 1);
                    int ch  = kc0 + (mat & 1);
                    int row = warp_n * 64 + grp * 8 + rin;
                    uint32_t off = sw128((uint32_t)(row * 128 + ch * 16));
                    uint32_t r0, r1, r2, r3;
                    LDSM4(r0, r1, r2, r3, sa + 32768 + off);
                    bh[jp*2][0] = r0; bh[jp*2][1] = r1;
                    bh[jp*2+1][0] = r2; bh[jp*2+1][1] = r3;
                    LDSM4(r0, r1, r2, r3, sa + 49152 + off);
                    bl[jp*2][0] = r0; bl[jp*2][1] = r1;
                    bl[jp*2+1][0] = r2; bl[jp*2+1][1] = r3;
                }
            }
            // 3-pass compensated MMAs
            #pragma unroll
            for (int tm = 0; tm < 2; tm++)
                #pragma unroll
                for (int j = 0; j < 8; j++) {
                    MMA16816(c[tm][j], ah[tm], bh[j]);
                    MMA16816(c[tm][j], ah[tm], bl[j]);
                    MMA16816(c[tm][j], al[tm], bh[j]);
                }
        }
        __syncthreads();
    }

    // ---- epilogue: bias add + store ----
    #pragma unroll
    for (int tm = 0; tm < 2; tm++) {
        #pragma unroll
        for (int j = 0; j < 8; j++) {
            int gn = n0 + warp_n * 64 + j * 8 + 2 * (lane & 3);
            float2 bv = *(const float2*)&bias[gn];
            int gm0 = m0 + warp_m * 32 + tm * 16 + (lane >> 2);
            float2 o0, o1;
            o0.x = c[tm][j][0] + bv.x;
            o0.y = c[tm][j][1] + bv.y;
            o1.x = c[tm][j][2] + bv.x;
            o1.y = c[tm][j][3] + bv.y;
            *(float2*)&out[(size_t)gm0 * HH + gn]       = o0;
            *(float2*)&out[(size_t)(gm0 + 8) * HH + gn] = o1;
        }
    }
}

// ---------------------------------------------------------------------------
// fp32 SGEMM with optional bias (kept for V and O projections)
// ---------------------------------------------------------------------------
__global__ __launch_bounds__(256) void sgemm_bias(
    const float* __restrict__ A, const float* __restrict__ B,
    const float* __restrict__ bias, float* __restrict__ C,
    int M, int N, int K)
{
    __shared__ float As[16][128];
    __shared__ float Bs[16][128];

    const int tid = threadIdx.x;
    const int tx = tid & 15;
    const int ty = tid >> 4;
    const int m0 = blockIdx.y * 128;
    const int n0 = blockIdx.x * 128;

    float acc[8][8];
    #pragma unroll
    for (int i = 0; i < 8; i++)
        #pragma unroll
        for (int j = 0; j < 8; j++) acc[i][j] = 0.f;

    for (int k0 = 0; k0 < K; k0 += 16) {
        #pragma unroll
        for (int it = 0; it < 2; it++) {
            int idx = tid * 2 + it;
            int r = idx >> 2, c4 = idx & 3;
            float4 a = *(const float4*)&A[(size_t)(m0 + r) * K + k0 + c4 * 4];
            As[c4*4+0][r] = a.x; As[c4*4+1][r] = a.y;
            As[c4*4+2][r] = a.z; As[c4*4+3][r] = a.w;
        }
        #pragma unroll
        for (int it = 0; it < 2; it++) {
            int idx = tid * 2 + it;
            int r = idx >> 5, c4 = idx & 31;
            int col = n0 + c4 * 4;
            float4 bvv = make_float4(0.f, 0.f, 0.f, 0.f);
            if (col < N) bvv = *(const float4*)&B[(size_t)(k0 + r) * N + col];
            *(float4*)&Bs[r][c4*4] = bvv;
        }
        __syncthreads();
        #pragma unroll
        for (int kk = 0; kk < 16; kk++) {
            float a[8], b[8];
            *(float4*)&a[0] = *(const float4*)&As[kk][ty*4];
            *(float4*)&a[4] = *(const float4*)&As[kk][64 + ty*4];
            *(float4*)&b[0] = *(const float4*)&Bs[kk][tx*4];
            *(float4*)&b[4] = *(const float4*)&Bs[kk][64 + tx*4];
            #pragma unroll
            for (int i = 0; i < 8; i++)
                #pragma unroll
                for (int j = 0; j < 8; j++)
                    acc[i][j] += a[i] * b[j];
        }
        __syncthreads();
    }
    float bb[8];
    #pragma unroll
    for (int j = 0; j < 8; j++) {
        int col = n0 + ((j < 4) ? (tx*4 + j) : (64 + tx*4 + j - 4));
        bb[j] = (bias != nullptr && col < N) ? bias[col] : 0.f;
    }
    #pragma unroll
    for (int i = 0; i < 8; i++) {
        int row = m0 + ((i < 4) ? (ty*4 + i) : (64 + ty*4 + i - 4));
        #pragma unroll
        for (int g = 0; g < 2; g++) {
            int col = n0 + g*64 + tx*4;
            if (col < N) {
                float4 o;
                o.x = acc[i][g*4+0] + bb[g*4+0];
                o.y = acc[i][g*4+1] + bb[g*4+1];
                o.z = acc[i][g*4+2] + bb[g*4+2];
                o.w = acc[i][g*4+3] + bb[g*4+3];
                *(float4*)&C[(size_t)row * N + col] = o;
            }
        }
    }
}

// ---------------------------------------------------------------------------
// Fused causal flash-attention (fp32 SIMT)
// ---------------------------------------------------------------------------
__global__ __launch_bounds__(256, 3) void attn_kernel(
    const float* __restrict__ q, const float* __restrict__ k,
    const float* __restrict__ v, float* __restrict__ attn_out)
{
    __shared__ float Qt[64*64];
    __shared__ float KtS[64*64];
    __shared__ float Vs[64*64];

    const int b  = blockIdx.z;
    const int h  = blockIdx.y;
    const int qi = blockIdx.x;
    const int tid = threadIdx.x;
    const int tx = tid & 15;
    const int ty = tid >> 4;

    {
        const int r  = tid >> 2;
        const int d0 = (tid & 3) << 4;
        const float* qp = q + ((size_t)(b*TT + qi*64 + r) * HH + h*DHH + d0);
        #pragma unroll
        for (int j4 = 0; j4 < 4; j4++) {
            float4 val = *(const float4*)(qp + j4*4);
            Qt[(d0 + j4*4 + 0)*64 + r] = val.x;
            Qt[(d0 + j4*4 + 1)*64 + r] = val.y;
            Qt[(d0 + j4*4 + 2)*64 + r] = val.z;
            Qt[(d0 + j4*4 + 3)*64 + r] = val.w;
        }
    }

    float m_run[4], l_run[4], Oacc[4][4];
    #pragma unroll
    for (int i = 0; i < 4; i++) {
        m_run[i] = -1e30f; l_run[i] = 0.f;
        #pragma unroll
        for (int j = 0; j < 4; j++) Oacc[i][j] = 0.f;
    }

    for (int kt = 0; kt <= qi; kt++) {
        __syncthreads();
        {
            const int r  = tid >> 2;
            const int d0 = (tid & 3) << 4;
            const float* kp = k + ((size_t)(b*TT + kt*64 + r) * HH + h*DHH + d0);
            const float* vp = v + ((size_t)(b*TT + kt*64 + r) * DHH + d0);
            #pragma unroll
            for (int j4 = 0; j4 < 4; j4++) {
                float4 kv = *(const float4*)(kp + j4*4);
                KtS[(d0 + j4*4 + 0)*64 + r] = kv.x;
                KtS[(d0 + j4*4 + 1)*64 + r] = kv.y;
                KtS[(d0 + j4*4 + 2)*64 + r] = kv.z;
                KtS[(d0 + j4*4 + 3)*64 + r] = kv.w;
                float4 vv = *(const float4*)(vp + j4*4);
                *(float4*)&Vs[r*64 + d0 + j4*4] = vv;
            }
        }
        __syncthreads();

        float s[4][4];
        #pragma unroll
        for (int i = 0; i < 4; i++)
            #pragma unroll
            for (int j = 0; j < 4; j++) s[i][j] = 0.f;

        #pragma unroll 8
        for (int d = 0; d < 64; d++) {
            float4 qv = *(const float4*)&Qt[d*64 + ty*4];
            float4 kv = *(const float4*)&KtS[d*64 + tx*4];
            float qa[4] = {qv.x, qv.y, qv.z, qv.w};
            float ka[4] = {kv.x, kv.y, kv.z, kv.w};
            #pragma unroll
            for (int i = 0; i < 4; i++)
                #pragma unroll
                for (int j = 0; j < 4; j++)
                    s[i][j] += qa[i] * ka[j];
        }

        #pragma unroll
        for (int i = 0; i < 4; i++) {
            int qg = qi*64 + ty*4 + i;
            #pragma unroll
            for (int j = 0; j < 4; j++) {
                int kg = kt*64 + tx*4 + j;
                s[i][j] = (kg > qg) ? -1e30f : s[i][j] * 0.125f;
            }
        }

        float p[4][4];
        #pragma unroll
        for (int i = 0; i < 4; i++) {
            float rmax = fmaxf(fmaxf(s[i][0], s[i][1]), fmaxf(s[i][2], s[i][3]));
            rmax = fmaxf(rmax, __shfl_xor_sync(0xffffffffu, rmax, 8));
            rmax = fmaxf(rmax, __shfl_xor_sync(0xffffffffu, rmax, 4));
            rmax = fmaxf(rmax, __shfl_xor_sync(0xffffffffu, rmax, 2));
            rmax = fmaxf(rmax, __shfl_xor_sync(0xffffffffu, rmax, 1));
            float mnew = fmaxf(m_run[i], rmax);
            float corr = __expf(m_run[i] - mnew);
            float rsum = 0.f;
            #pragma unroll
            for (int j = 0; j < 4; j++) {
                p[i][j] = __expf(s[i][j] - mnew);
                rsum += p[i][j];
            }
            rsum += __shfl_xor_sync(0xffffffffu, rsum, 8);
            rsum += __shfl_xor_sync(0xffffffffu, rsum, 4);
            rsum += __shfl_xor_sync(0xffffffffu, rsum, 2);
            rsum += __shfl_xor_sync(0xffffffffu, rsum, 1);
            m_run[i] = mnew;
            l_run[i] = l_run[i] * corr + rsum;
            #pragma unroll
            for (int j = 0; j < 4; j++) Oacc[i][j] *= corr;
        }

        __syncthreads();
        #pragma unroll
        for (int i = 0; i < 4; i++)
            *(float4*)&KtS[(ty*4 + i)*64 + tx*4] = *(float4*)&p[i][0];
        __syncthreads();

        #pragma unroll 8
        for (int kc = 0; kc < 64; kc++) {
            float4 vv = *(const float4*)&Vs[kc*64 + tx*4];
            #pragma unroll
            for (int i = 0; i < 4; i++) {
                float pv = KtS[(ty*4 + i)*64 + kc];
                Oacc[i][0] += pv * vv.x;
                Oacc[i][1] += pv * vv.y;
                Oacc[i][2] += pv * vv.z;
                Oacc[i][3] += pv * vv.w;
            }
        }
    }

    #pragma unroll
    for (int i = 0; i < 4; i++) {
        float inv = 1.f / l_run[i];
        int qg = qi*64 + ty*4 + i;
        float4 o;
        o.x = Oacc[i][0] * inv;
        o.y = Oacc[i][1] * inv;
        o.z = Oacc[i][2] * inv;
        o.w = Oacc[i][3] * inv;
        *(float4*)&attn_out[(((size_t)b*NHH + h)*TT + qg)*DHH + tx*4] = o;
    }
}

// ---------------------------------------------------------------------------
__global__ __launch_bounds__(256) void head_mean(
    const float* __restrict__ attn, float* __restrict__ mout)
{
    int idx = blockIdx.x * blockDim.x + threadIdx.x;
    int d4 = idx & 15;
    int bt = idx >> 4;
    int b  = bt / TT;
    int t  = bt % TT;
    float4 acc = make_float4(0.f, 0.f, 0.f, 0.f);
    #pragma unroll
    for (int h = 0; h < NHH; h++) {
        float4 vv = *(const float4*)&attn[(((size_t)b*NHH + h)*TT + t)*DHH + d4*4];
        acc.x += vv.x; acc.y += vv.y; acc.z += vv.z; acc.w += vv.w;
    }
    const float inv = 1.f / (float)NHH;
    float4 o = make_float4(acc.x*inv, acc.y*inv, acc.z*inv, acc.w*inv);
    *(float4*)&mout[(size_t)bt * DHH + d4*4] = o;
}

// ---------------------------------------------------------------------------
extern "C" void kernel_launch(void* const* d_in, const int* in_sizes, int n_in,
                              void* d_out, int out_size)
{
    const float* x  = (const float*)d_in[0];
    const float* Wq = (const float*)d_in[1];
    const float* bq = (const float*)d_in[2];
    const float* Wk = (const float*)d_in[3];
    const float* bk = (const float*)d_in[4];
    const float* Wv = (const float*)d_in[5];
    const float* bv = (const float*)d_in[6];
    const float* Wo = (const float*)d_in[7];

    float* out  = (float*)d_out;                      // [32,512,1024]
    float* attn = out + (size_t)MTOT * HH;            // [32,16,512,64]

    float *q, *k, *v, *m;
    __nv_bfloat16 *xh, *xl, *wth, *wtl;
    cudaGetSymbolAddress((void**)&q, g_q);
    cudaGetSymbolAddress((void**)&k, g_k);
    cudaGetSymbolAddress((void**)&v, g_v);
    cudaGetSymbolAddress((void**)&m, g_m);
    cudaGetSymbolAddress((void**)&xh, g_xh);
    cudaGetSymbolAddress((void**)&xl, g_xl);
    cudaGetSymbolAddress((void**)&wth, g_wth);
    cudaGetSymbolAddress((void**)&wtl, g_wtl);

    cudaFuncSetAttribute(qk_gemm, cudaFuncAttributeMaxDynamicSharedMemorySize,
                         QK_SMEM);

    dim3 blk(256);

    // bf16 splits
    convert_x<<<dim3(((size_t)MTOT*HH/4)/256), blk>>>(x, xh, xl);
    convert_w<<<dim3(32, 32, 2), blk>>>(Wq, Wk, wth, wtl);

    // V projection (fp32)
    sgemm_bias<<<dim3(1, MTOT/128), blk>>>(x, Wv, bv, v, MTOT, DHH, HH);

    // Q+K projections (mma.sync bf16 x3)
    qk_gemm<<<dim3(16, MTOT/128), blk, QK_SMEM>>>(xh, xl, wth, wtl,
                                                  bq, bk, q, k);

    // Fused causal attention -> attn_vec
    attn_kernel<<<dim3(TT/64, NHH, BSZ), blk>>>(q, k, v, attn);

    // Head mean + out projection
    head_mean<<<dim3((MTOT * (DHH/4)) / 256), blk>>>(attn, m);
    sgemm_bias<<<dim3(HH/128, MTOT/128), blk>>>(m, Wo, nullptr, out, MTOT, HH, DHH);
}

// round 4
// speedup vs baseline: 2.6628x; 1.4028x over previous
#include <cuda_runtime.h>
#include <cuda_bf16.h>
#include <math.h>
#include <stdint.h>

#define BSZ 32
#define TT  512
#define HH  1024
#define DHH 64
#define NHH 16
#define MTOT (BSZ*TT)   // 16384

// ---------------------------------------------------------------------------
// Scratch (device globals: allocation-free contract)
// g_q holds qh|ql bf16 splits (q pre-scaled by 0.125), g_k holds kh|kl,
// g_v holds vh|vl, g_m holds v fp32 (temp) then head-mean output.
// ---------------------------------------------------------------------------
__device__ float g_q[(size_t)MTOT * HH];             // 64 MB -> qh/ql
__device__ float g_k[(size_t)MTOT * HH];             // 64 MB -> kh/kl
__device__ float g_v[(size_t)MTOT * DHH];            //  4 MB -> vh/vl
__device__ float g_m[(size_t)MTOT * DHH];            //  4 MB
__device__ __nv_bfloat16 g_xh[(size_t)MTOT * HH];    // 32 MB
__device__ __nv_bfloat16 g_xl[(size_t)MTOT * HH];    // 32 MB
__device__ __nv_bfloat16 g_wth[(size_t)2 * HH * HH]; //  4 MB
__device__ __nv_bfloat16 g_wtl[(size_t)2 * HH * HH]; //  4 MB

// ---------------------------------------------------------------------------
// Baseline-ISA PTX helpers
// ---------------------------------------------------------------------------
__device__ __forceinline__ uint32_t su32(const void* p) {
    uint32_t a;
    asm("{ .reg .u64 t; cvta.to.shared.u64 t, %1; cvt.u32.u64 %0, t; }"
        : "=r"(a) : "l"(p));
    return a;
}
#define CP16(dst, src) \
    asm volatile("cp.async.cg.shared.global [%0], [%1], 16;" \
                 :: "r"(dst), "l"(src))
#define CP_COMMIT() asm volatile("cp.async.commit_group;" ::: "memory")
#define CP_WAIT1()  asm volatile("cp.async.wait_group 1;" ::: "memory")
#define CP_WAIT0()  asm volatile("cp.async.wait_group 0;" ::: "memory")
#define LDSM4(r0, r1, r2, r3, addr) \
    asm volatile("ldmatrix.sync.aligned.m8n8.x4.shared.b16 {%0,%1,%2,%3}, [%4];" \
                 : "=r"(r0), "=r"(r1), "=r"(r2), "=r"(r3) : "r"(addr))
#define LDSM4T(r0, r1, r2, r3, addr) \
    asm volatile("ldmatrix.sync.aligned.m8n8.x4.trans.shared.b16 {%0,%1,%2,%3}, [%4];" \
                 : "=r"(r0), "=r"(r1), "=r"(r2), "=r"(r3) : "r"(addr))
#define MMA16816(d, a, b) \
    asm volatile("mma.sync.aligned.m16n8k16.row.col.f32.bf16.bf16.f32 " \
                 "{%0,%1,%2,%3}, {%4,%5,%6,%7}, {%8,%9}, {%0,%1,%2,%3};" \
                 : "+f"((d)[0]), "+f"((d)[1]), "+f"((d)[2]), "+f"((d)[3]) \
                 : "r"((a)[0]), "r"((a)[1]), "r"((a)[2]), "r"((a)[3]), \
                   "r"((b)[0]), "r"((b)[1]))

__device__ __forceinline__ uint32_t sw128(uint32_t off) {
    return off ^ ((off >> 3) & 0x70u);
}
// split two floats into bf16x2 hi + bf16x2 lo (a -> low half, b -> high half)
__device__ __forceinline__ void split2(float a, float b,
                                       uint32_t& hi, uint32_t& lo) {
    __nv_bfloat162 h = __floats2bfloat162_rn(a, b);
    float ra = a - __bfloat162float(h.x);
    float rb = b - __bfloat162float(h.y);
    __nv_bfloat162 l = __floats2bfloat162_rn(ra, rb);
    hi = *(uint32_t*)&h;
    lo = *(uint32_t*)&l;
}

// ---------------------------------------------------------------------------
// Split fp32 -> bf16 hi + bf16 lo
// ---------------------------------------------------------------------------
__global__ __launch_bounds__(256) void convert_x(
    const float* __restrict__ x, __nv_bfloat16* __restrict__ xh,
    __nv_bfloat16* __restrict__ xl)
{
    size_t i = ((size_t)blockIdx.x * blockDim.x + threadIdx.x) * 4;
    float4 v = *(const float4*)(x + i);
    uint32_t h0, l0, h1, l1;
    split2(v.x, v.y, h0, l0);
    split2(v.z, v.w, h1, l1);
    *(uint32_t*)(xh + i)     = h0;
    *(uint32_t*)(xh + i + 2) = h1;
    *(uint32_t*)(xl + i)     = l0;
    *(uint32_t*)(xl + i + 2) = l1;
}

// ---------------------------------------------------------------------------
// Transpose + split Wq/Wk: W[k][n] -> Wt[n][k] in bf16 hi/lo
// ---------------------------------------------------------------------------
__global__ __launch_bounds__(256) void convert_w(
    const float* __restrict__ wq, const float* __restrict__ wk,
    __nv_bfloat16* __restrict__ wth, __nv_bfloat16* __restrict__ wtl)
{
    __shared__ float t[32][33];
    const float* w = blockIdx.z ? wk : wq;
    __nv_bfloat16* oh = wth + (size_t)blockIdx.z * HH * HH;
    __nv_bfloat16* ol = wtl + (size_t)blockIdx.z * HH * HH;
    int n0 = blockIdx.x * 32, k0 = blockIdx.y * 32;
    int tx = threadIdx.x & 31, ty = threadIdx.x >> 5;
    #pragma unroll
    for (int j = 0; j < 4; j++)
        t[ty + j*8][tx] = w[(size_t)(k0 + ty + j*8) * HH + n0 + tx];
    __syncthreads();
    #pragma unroll
    for (int j = 0; j < 4; j++) {
        int n = n0 + ty + j*8, k = k0 + tx;
        float v = t[tx][ty + j*8];
        __nv_bfloat16 h = __float2bfloat16(v);
        oh[(size_t)n * HH + k] = h;
        ol[(size_t)n * HH + k] = __float2bfloat16(v - __bfloat162float(h));
    }
}

// ---------------------------------------------------------------------------
// Fused Q+K projection: mma.sync bf16, 3-pass compensated split.
// Epilogue writes bf16 hi/lo splits (Q pre-scaled by 1/8).
// ---------------------------------------------------------------------------
#define QK_STAGE 65536
#define QK_SMEM  (2 * QK_STAGE)

__global__ __launch_bounds__(256, 1) void qk_gemm(
    const __nv_bfloat16* __restrict__ xh, const __nv_bfloat16* __restrict__ xl,
    const __nv_bfloat16* __restrict__ wth, const __nv_bfloat16* __restrict__ wtl,
    const float* __restrict__ bq, const float* __restrict__ bk,
    __nv_bfloat16* __restrict__ qh, __nv_bfloat16* __restrict__ ql,
    __nv_bfloat16* __restrict__ kh, __nv_bfloat16* __restrict__ kl)
{
    extern __shared__ char smem[];
    const uint32_t sb = su32(smem);
    const int tid = threadIdx.x;
    const int lane = tid & 31;
    const int wid = tid >> 5;
    const int warp_m = wid & 3;
    const int warp_n = wid >> 2;

    const int ntile = blockIdx.x;
    const int which = ntile >> 3;
    const int n0 = (ntile & 7) * 128;
    const int m0 = blockIdx.y * 128;

    const __nv_bfloat16* wh = wth + (size_t)which * HH * HH;
    const __nv_bfloat16* wl = wtl + (size_t)which * HH * HH;
    const float* bias = which ? bk : bq;
    __nv_bfloat16* oh = which ? kh : qh;
    __nv_bfloat16* ol = which ? kl : ql;
    const float scale = which ? 1.0f : 0.125f;

    float c[2][8][4];
    #pragma unroll
    for (int tm = 0; tm < 2; tm++)
        #pragma unroll
        for (int j = 0; j < 8; j++)
            #pragma unroll
            for (int r = 0; r < 4; r++) c[tm][j][r] = 0.f;

    auto load_stage = [&](int stage, int k0) {
        const uint32_t sa = sb + stage * QK_STAGE;
        #pragma unroll
        for (int i = 0; i < 4; i++) {
            int s = tid + (i << 8);
            int r = s >> 3, ch = s & 7;
            uint32_t off = sw128((uint32_t)(r * 128 + ch * 16));
            const size_t ga = (size_t)(m0 + r) * HH + k0 + ch * 8;
            const size_t gb = (size_t)(n0 + r) * HH + k0 + ch * 8;
            CP16(sa + off,         xh + ga);
            CP16(sa + 16384 + off, xl + ga);
            CP16(sa + 32768 + off, wh + gb);
            CP16(sa + 49152 + off, wl + gb);
        }
        CP_COMMIT();
    };

    load_stage(0, 0);

    for (int cch = 0; cch < 16; cch++) {
        if (cch + 1 < 16) { load_stage((cch + 1) & 1, (cch + 1) * 64); CP_WAIT1(); }
        else              { CP_WAIT0(); }
        __syncthreads();

        const uint32_t sa = sb + (cch & 1) * QK_STAGE;
        #pragma unroll
        for (int kk = 0; kk < 4; kk++) {
            const int kc0 = kk * 2;
            uint32_t ah[2][4], al[2][4];
            {
                const int mat = lane >> 3, rin = lane & 7;
                #pragma unroll
                for (int tm = 0; tm < 2; tm++) {
                    int row = warp_m * 32 + tm * 16 + (mat & 1) * 8 + rin;
                    int ch  = kc0 + (mat >> 1);
                    uint32_t off = sw128((uint32_t)(row * 128 + ch * 16));
                    LDSM4(ah[tm][0], ah[tm][1], ah[tm][2], ah[tm][3], sa + off);
                    LDSM4(al[tm][0], al[tm][1], al[tm][2], al[tm][3],
                          sa + 16384 + off);
                }
            }
            uint32_t bh[8][2], bl[8][2];
            {
                const int mat = lane >> 3, rin = lane & 7;
                #pragma unroll
                for (int jp = 0; jp < 4; jp++) {
                    int grp = jp * 2 + (mat >> 1);
                    int ch  = kc0 + (mat & 1);
                    int row = warp_n * 64 + grp * 8 + rin;
                    uint32_t off = sw128((uint32_t)(row * 128 + ch * 16));
                    uint32_t r0, r1, r2, r3;
                    LDSM4(r0, r1, r2, r3, sa + 32768 + off);
                    bh[jp*2][0] = r0; bh[jp*2][1] = r1;
                    bh[jp*2+1][0] = r2; bh[jp*2+1][1] = r3;
                    LDSM4(r0, r1, r2, r3, sa + 49152 + off);
                    bl[jp*2][0] = r0; bl[jp*2][1] = r1;
                    bl[jp*2+1][0] = r2; bl[jp*2+1][1] = r3;
                }
            }
            #pragma unroll
            for (int tm = 0; tm < 2; tm++)
                #pragma unroll
                for (int j = 0; j < 8; j++) {
                    MMA16816(c[tm][j], ah[tm], bh[j]);
                    MMA16816(c[tm][j], ah[tm], bl[j]);
                    MMA16816(c[tm][j], al[tm], bh[j]);
                }
        }
        __syncthreads();
    }

    // epilogue: bias + scale + bf16 split store
    #pragma unroll
    for (int tm = 0; tm < 2; tm++) {
        #pragma unroll
        for (int j = 0; j < 8; j++) {
            int gn = n0 + warp_n * 64 + j * 8 + 2 * (lane & 3);
            float2 bv = *(const float2*)&bias[gn];
            int gm0 = m0 + warp_m * 32 + tm * 16 + (lane >> 2);
            float v0 = (c[tm][j][0] + bv.x) * scale;
            float v1 = (c[tm][j][1] + bv.y) * scale;
            float v2 = (c[tm][j][2] + bv.x) * scale;
            float v3 = (c[tm][j][3] + bv.y) * scale;
            uint32_t h01, l01, h23, l23;
            split2(v0, v1, h01, l01);
            split2(v2, v3, h23, l23);
            *(uint32_t*)(oh + (size_t)gm0 * HH + gn)       = h01;
            *(uint32_t*)(ol + (size_t)gm0 * HH + gn)       = l01;
            *(uint32_t*)(oh + (size_t)(gm0 + 8) * HH + gn) = h23;
            *(uint32_t*)(ol + (size_t)(gm0 + 8) * HH + gn) = l23;
        }
    }
}

// ---------------------------------------------------------------------------
// fp32 SGEMM with optional bias (V and O projections)
// ---------------------------------------------------------------------------
__global__ __launch_bounds__(256) void sgemm_bias(
    const float* __restrict__ A, const float* __restrict__ B,
    const float* __restrict__ bias, float* __restrict__ C,
    int M, int N, int K)
{
    __shared__ float As[16][128];
    __shared__ float Bs[16][128];

    const int tid = threadIdx.x;
    const int tx = tid & 15;
    const int ty = tid >> 4;
    const int m0 = blockIdx.y * 128;
    const int n0 = blockIdx.x * 128;

    float acc[8][8];
    #pragma unroll
    for (int i = 0; i < 8; i++)
        #pragma unroll
        for (int j = 0; j < 8; j++) acc[i][j] = 0.f;

    for (int k0 = 0; k0 < K; k0 += 16) {
        #pragma unroll
        for (int it = 0; it < 2; it++) {
            int idx = tid * 2 + it;
            int r = idx >> 2, c4 = idx & 3;
            float4 a = *(const float4*)&A[(size_t)(m0 + r) * K + k0 + c4 * 4];
            As[c4*4+0][r] = a.x; As[c4*4+1][r] = a.y;
            As[c4*4+2][r] = a.z; As[c4*4+3][r] = a.w;
        }
        #pragma unroll
        for (int it = 0; it < 2; it++) {
            int idx = tid * 2 + it;
            int r = idx >> 5, c4 = idx & 31;
            int col = n0 + c4 * 4;
            float4 bvv = make_float4(0.f, 0.f, 0.f, 0.f);
            if (col < N) bvv = *(const float4*)&B[(size_t)(k0 + r) * N + col];
            *(float4*)&Bs[r][c4*4] = bvv;
        }
        __syncthreads();
        #pragma unroll
        for (int kk = 0; kk < 16; kk++) {
            float a[8], b[8];
            *(float4*)&a[0] = *(const float4*)&As[kk][ty*4];
            *(float4*)&a[4] = *(const float4*)&As[kk][64 + ty*4];
            *(float4*)&b[0] = *(const float4*)&Bs[kk][tx*4];
            *(float4*)&b[4] = *(const float4*)&Bs[kk][64 + tx*4];
            #pragma unroll
            for (int i = 0; i < 8; i++)
                #pragma unroll
                for (int j = 0; j < 8; j++)
                    acc[i][j] += a[i] * b[j];
        }
        __syncthreads();
    }
    float bb[8];
    #pragma unroll
    for (int j = 0; j < 8; j++) {
        int col = n0 + ((j < 4) ? (tx*4 + j) : (64 + tx*4 + j - 4));
        bb[j] = (bias != nullptr && col < N) ? bias[col] : 0.f;
    }
    #pragma unroll
    for (int i = 0; i < 8; i++) {
        int row = m0 + ((i < 4) ? (ty*4 + i) : (64 + ty*4 + i - 4));
        #pragma unroll
        for (int g = 0; g < 2; g++) {
            int col = n0 + g*64 + tx*4;
            if (col < N) {
                float4 o;
                o.x = acc[i][g*4+0] + bb[g*4+0];
                o.y = acc[i][g*4+1] + bb[g*4+1];
                o.z = acc[i][g*4+2] + bb[g*4+2];
                o.w = acc[i][g*4+3] + bb[g*4+3];
                *(float4*)&C[(size_t)row * N + col] = o;
            }
        }
    }
}

// ---------------------------------------------------------------------------
// Tensor-core causal flash attention.
// CTA: (q-tile 128 rows, head, batch). 8 warps, each owns 16 q-rows (m16xn64).
// S = Qs @ Ks^T via 3-pass bf16 mma (q pre-scaled 1/8).
// P stays in registers (acc layout == A-operand layout), split hi/lo.
// O += P @ V via 3-pass bf16 mma; V consumed with ldmatrix.trans.
// SMEM (dynamic 64KB): 2 stages x [Kh 8K | Kl 8K | Vh 8K | Vl 8K];
// Q staged in bytes [0,32K) before the main loop.
// ---------------------------------------------------------------------------
#define AT_STAGE 32768
#define AT_SMEM  (2 * AT_STAGE)

__global__ __launch_bounds__(256) void attn_mma(
    const __nv_bfloat16* __restrict__ qh, const __nv_bfloat16* __restrict__ ql,
    const __nv_bfloat16* __restrict__ kh, const __nv_bfloat16* __restrict__ kl,
    const __nv_bfloat16* __restrict__ vh, const __nv_bfloat16* __restrict__ vl,
    float* __restrict__ attn_out)
{
    extern __shared__ char smem[];
    const uint32_t sb = su32(smem);
    const int tid = threadIdx.x;
    const int lane = tid & 31;
    const int w = tid >> 5;

    const int b  = blockIdx.z;
    const int h  = blockIdx.y;
    const int qi = blockIdx.x;
    const int q0 = qi * 128;

    // ---- stage Q tile (hi/lo) and load A fragments ----
    #pragma unroll
    for (int i = 0; i < 4; i++) {
        int idx = tid + (i << 8);
        int r = idx >> 3, ch = idx & 7;
        uint32_t off = sw128((uint32_t)(r * 128 + ch * 16));
        size_t g = (size_t)(b * TT + q0 + r) * HH + h * 64 + ch * 8;
        CP16(sb + off,         qh + g);
        CP16(sb + 16384 + off, ql + g);
    }
    CP_COMMIT();
    CP_WAIT0();
    __syncthreads();

    uint32_t Aqh[4][4], Aql[4][4];
    {
        const int tile = lane >> 3, rin = lane & 7;
        #pragma unroll
        for (int g = 0; g < 4; g++) {
            int row = w * 16 + (tile & 1) * 8 + rin;
            int ch  = 2 * g + (tile >> 1);
            uint32_t off = sw128((uint32_t)(row * 128 + ch * 16));
            LDSM4(Aqh[g][0], Aqh[g][1], Aqh[g][2], Aqh[g][3], sb + off);
            LDSM4(Aql[g][0], Aql[g][1], Aql[g][2], Aql[g][3], sb + 16384 + off);
        }
    }
    __syncthreads();

    // ---- softmax state / O accumulator ----
    float m0r = -1e30f, m1r = -1e30f, l0r = 0.f, l1r = 0.f;
    float o[8][4];
    #pragma unroll
    for (int j = 0; j < 8; j++)
        #pragma unroll
        for (int e = 0; e < 4; e++) o[j][e] = 0.f;

    const int ntiles = 2 * qi + 2;

    auto load_kv = [&](int stg, int kt) {
        const uint32_t sa = sb + stg * AT_STAGE;
        const size_t rowb = (size_t)(b * TT + kt * 64);
        #pragma unroll
        for (int i = 0; i < 2; i++) {
            int idx = tid + (i << 8);
            int r = idx >> 3, ch = idx & 7;
            uint32_t off = sw128((uint32_t)(r * 128 + ch * 16));
            size_t gk = (rowb + r) * HH + h * 64 + ch * 8;
            size_t gv = (rowb + r) * 64 + ch * 8;
            CP16(sa + off,         kh + gk);
            CP16(sa + 8192 + off,  kl + gk);
            CP16(sa + 16384 + off, vh + gv);
            CP16(sa + 24576 + off, vl + gv);
        }
        CP_COMMIT();
    };

    load_kv(0, 0);

    for (int kt = 0; kt < ntiles; kt++) {
        if (kt + 1 < ntiles) { load_kv((kt + 1) & 1, kt + 1); CP_WAIT1(); }
        else                 { CP_WAIT0(); }
        __syncthreads();

        // fully-masked warp-tile? (min k col > max q row of this warp)
        const bool skip = (kt * 64) > (q0 + w * 16 + 15);
        if (!skip) {
            const uint32_t sa = sb + (kt & 1) * AT_STAGE;
            const int tile = lane >> 3, rin = lane & 7;

            // ---- S = Q @ K^T ----
            float s[8][4];
            #pragma unroll
            for (int j = 0; j < 8; j++)
                #pragma unroll
                for (int e = 0; e < 4; e++) s[j][e] = 0.f;

            #pragma unroll
            for (int g = 0; g < 4; g++) {
                uint32_t bh[8][2], bl[8][2];
                #pragma unroll
                for (int p = 0; p < 4; p++) {
                    int row = 16 * p + (tile >> 1) * 8 + rin;
                    int ch  = 2 * g + (tile & 1);
                    uint32_t off = sw128((uint32_t)(row * 128 + ch * 16));
                    uint32_t r0, r1, r2, r3;
                    LDSM4(r0, r1, r2, r3, sa + off);
                    bh[2*p][0] = r0; bh[2*p][1] = r1;
                    bh[2*p+1][0] = r2; bh[2*p+1][1] = r3;
                    LDSM4(r0, r1, r2, r3, sa + 8192 + off);
                    bl[2*p][0] = r0; bl[2*p][1] = r1;
                    bl[2*p+1][0] = r2; bl[2*p+1][1] = r3;
                }
                #pragma unroll
                for (int j = 0; j < 8; j++) {
                    MMA16816(s[j], Aqh[g], bh[j]);
                    MMA16816(s[j], Aqh[g], bl[j]);
                    MMA16816(s[j], Aql[g], bh[j]);
                }
            }

            // ---- causal mask (only near diagonal) ----
            const int gr0 = q0 + w * 16 + (lane >> 2);
            if (kt * 64 + 63 > q0 + w * 16) {
                #pragma unroll
                for (int j = 0; j < 8; j++) {
                    int col = kt * 64 + j * 8 + 2 * (lane & 3);
                    if (col     > gr0)     s[j][0] = -1e30f;
                    if (col + 1 > gr0)     s[j][1] = -1e30f;
                    if (col     > gr0 + 8) s[j][2] = -1e30f;
                    if (col + 1 > gr0 + 8) s[j][3] = -1e30f;
                }
            }

            // ---- online softmax (rows fully within warp quads) ----
            float mx0 = -1e30f, mx1 = -1e30f;
            #pragma unroll
            for (int j = 0; j < 8; j++) {
                mx0 = fmaxf(mx0, fmaxf(s[j][0], s[j][1]));
                mx1 = fmaxf(mx1, fmaxf(s[j][2], s[j][3]));
            }
            mx0 = fmaxf(mx0, __shfl_xor_sync(0xffffffffu, mx0, 1));
            mx0 = fmaxf(mx0, __shfl_xor_sync(0xffffffffu, mx0, 2));
            mx1 = fmaxf(mx1, __shfl_xor_sync(0xffffffffu, mx1, 1));
            mx1 = fmaxf(mx1, __shfl_xor_sync(0xffffffffu, mx1, 2));

            float mn0 = fmaxf(m0r, mx0), mn1 = fmaxf(m1r, mx1);
            float c0 = __expf(m0r - mn0), c1 = __expf(m1r - mn1);
            float sum0 = 0.f, sum1 = 0.f;
            #pragma unroll
            for (int j = 0; j < 8; j++) {
                s[j][0] = __expf(s[j][0] - mn0);
                s[j][1] = __expf(s[j][1] - mn0);
                s[j][2] = __expf(s[j][2] - mn1);
                s[j][3] = __expf(s[j][3] - mn1);
                sum0 += s[j][0] + s[j][1];
                sum1 += s[j][2] + s[j][3];
            }
            sum0 += __shfl_xor_sync(0xffffffffu, sum0, 1);
            sum0 += __shfl_xor_sync(0xffffffffu, sum0, 2);
            sum1 += __shfl_xor_sync(0xffffffffu, sum1, 1);
            sum1 += __shfl_xor_sync(0xffffffffu, sum1, 2);
            m0r = mn0; m1r = mn1;
            l0r = l0r * c0 + sum0;
            l1r = l1r * c1 + sum1;

            // ---- pack P into A fragments (hi/lo) ----
            uint32_t Aph[4][4], Apl[4][4];
            #pragma unroll
            for (int g = 0; g < 4; g++) {
                split2(s[2*g][0],   s[2*g][1],   Aph[g][0], Apl[g][0]);
                split2(s[2*g][2],   s[2*g][3],   Aph[g][1], Apl[g][1]);
                split2(s[2*g+1][0], s[2*g+1][1], Aph[g][2], Apl[g][2]);
                split2(s[2*g+1][2], s[2*g+1][3], Aph[g][3], Apl[g][3]);
            }

            // ---- rescale O ----
            #pragma unroll
            for (int j = 0; j < 8; j++) {
                o[j][0] *= c0; o[j][1] *= c0;
                o[j][2] *= c1; o[j][3] *= c1;
            }

            // ---- O += P @ V (V^T via ldmatrix.trans) ----
            #pragma unroll
            for (int g = 0; g < 4; g++) {
                uint32_t bvh[8][2], bvl[8][2];
                #pragma unroll
                for (int p = 0; p < 4; p++) {
                    int row = 16 * g + (tile & 1) * 8 + rin;
                    int ch  = 2 * p + (tile >> 1);
                    uint32_t off = sw128((uint32_t)(row * 128 + ch * 16));
                    uint32_t r0, r1, r2, r3;
                    LDSM4T(r0, r1, r2, r3, sa + 16384 + off);
                    bvh[2*p][0] = r0; bvh[2*p][1] = r1;
                    bvh[2*p+1][0] = r2; bvh[2*p+1][1] = r3;
                    LDSM4T(r0, r1, r2, r3, sa + 24576 + off);
                    bvl[2*p][0] = r0; bvl[2*p][1] = r1;
                    bvl[2*p+1][0] = r2; bvl[2*p+1][1] = r3;
                }
                #pragma unroll
                for (int j = 0; j < 8; j++) {
                    MMA16816(o[j], Aph[g], bvh[j]);
                    MMA16816(o[j], Aph[g], bvl[j]);
                    MMA16816(o[j], Apl[g], bvh[j]);
                }
            }
        }
        __syncthreads();
    }

    // ---- normalize + write attn_vec [b,h,t,d] ----
    const float inv0 = 1.f / l0r, inv1 = 1.f / l1r;
    const int gr0 = q0 + w * 16 + (lane >> 2);
    float* base = attn_out + (((size_t)b * NHH + h) * TT) * DHH;
    #pragma unroll
    for (int j = 0; j < 8; j++) {
        int col = j * 8 + 2 * (lane & 3);
        float2 v0, v1;
        v0.x = o[j][0] * inv0; v0.y = o[j][1] * inv0;
        v1.x = o[j][2] * inv1; v1.y = o[j][3] * inv1;
        *(float2*)(base + (size_t)gr0 * DHH + col)       = v0;
        *(float2*)(base + (size_t)(gr0 + 8) * DHH + col) = v1;
    }
}

// ---------------------------------------------------------------------------
__global__ __launch_bounds__(256) void head_mean(
    const float* __restrict__ attn, float* __restrict__ mout)
{
    int idx = blockIdx.x * blockDim.x + threadIdx.x;
    int d4 = idx & 15;
    int bt = idx >> 4;
    int b  = bt / TT;
    int t  = bt % TT;
    float4 acc = make_float4(0.f, 0.f, 0.f, 0.f);
    #pragma unroll
    for (int h = 0; h < NHH; h++) {
        float4 vv = *(const float4*)&attn[(((size_t)b*NHH + h)*TT + t)*DHH + d4*4];
        acc.x += vv.x; acc.y += vv.y; acc.z += vv.z; acc.w += vv.w;
    }
    const float inv = 1.f / (float)NHH;
    float4 o = make_float4(acc.x*inv, acc.y*inv, acc.z*inv, acc.w*inv);
    *(float4*)&mout[(size_t)bt * DHH + d4*4] = o;
}

// ---------------------------------------------------------------------------
extern "C" void kernel_launch(void* const* d_in, const int* in_sizes, int n_in,
                              void* d_out, int out_size)
{
    const float* x  = (const float*)d_in[0];
    const float* Wq = (const float*)d_in[1];
    const float* bq = (const float*)d_in[2];
    const float* Wk = (const float*)d_in[3];
    const float* bk = (const float*)d_in[4];
    const float* Wv = (const float*)d_in[5];
    const float* bv = (const float*)d_in[6];
    const float* Wo = (const float*)d_in[7];

    float* out  = (float*)d_out;                      // [32,512,1024]
    float* attn = out + (size_t)MTOT * HH;            // [32,16,512,64]

    float *qbuf, *kbuf, *vbuf, *m;
    __nv_bfloat16 *xh, *xl, *wth, *wtl;
    cudaGetSymbolAddress((void**)&qbuf, g_q);
    cudaGetSymbolAddress((void**)&kbuf, g_k);
    cudaGetSymbolAddress((void**)&vbuf, g_v);
    cudaGetSymbolAddress((void**)&m, g_m);
    cudaGetSymbolAddress((void**)&xh, g_xh);
    cudaGetSymbolAddress((void**)&xl, g_xl);
    cudaGetSymbolAddress((void**)&wth, g_wth);
    cudaGetSymbolAddress((void**)&wtl, g_wtl);

    __nv_bfloat16* qh = (__nv_bfloat16*)qbuf;
    __nv_bfloat16* ql = qh + (size_t)MTOT * HH;
    __nv_bfloat16* kh = (__nv_bfloat16*)kbuf;
    __nv_bfloat16* kl = kh + (size_t)MTOT * HH;
    __nv_bfloat16* vh = (__nv_bfloat16*)vbuf;
    __nv_bfloat16* vl = vh + (size_t)MTOT * DHH;

    cudaFuncSetAttribute(qk_gemm, cudaFuncAttributeMaxDynamicSharedMemorySize,
                         QK_SMEM);
    cudaFuncSetAttribute(attn_mma, cudaFuncAttributeMaxDynamicSharedMemorySize,
                         AT_SMEM);

    dim3 blk(256);

    // bf16 splits of x and W
    convert_x<<<dim3(((size_t)MTOT*HH/4)/256), blk>>>(x, xh, xl);
    convert_w<<<dim3(32, 32, 2), blk>>>(Wq, Wk, wth, wtl);

    // V projection (fp32 into g_m temp), then split to bf16
    sgemm_bias<<<dim3(1, MTOT/128), blk>>>(x, Wv, bv, m, MTOT, DHH, HH);
    convert_x<<<dim3(((size_t)MTOT*DHH/4)/256), blk>>>(m, vh, vl);

    // Q+K projections (mma bf16 x3) -> bf16 splits, Q pre-scaled by 1/8
    qk_gemm<<<dim3(16, MTOT/128), blk, QK_SMEM>>>(xh, xl, wth, wtl,
                                                  bq, bk, qh, ql, kh, kl);

    // Tensor-core causal attention -> attn_vec (fp32)
    attn_mma<<<dim3(TT/128, NHH, BSZ), blk, AT_SMEM>>>(qh, ql, kh, kl,
                                                       vh, vl, attn);

    // Head mean + out projection (g_m reused)
    head_mean<<<dim3((MTOT * (DHH/4)) / 256), blk>>>(attn, m);
    sgemm_bias<<<dim3(HH/128, MTOT/128), blk>>>(m, Wo, nullptr, out, MTOT, HH, DHH);
}

// round 5
// speedup vs baseline: 3.0177x; 1.1333x over previous
#include <cuda_runtime.h>
#include <cuda_bf16.h>
#include <math.h>
#include <stdint.h>

#define BSZ 32
#define TT  512
#define HH  1024
#define DHH 64
#define NHH 16
#define MTOT (BSZ*TT)   // 16384

// ---------------------------------------------------------------------------
// Scratch (device globals: allocation-free contract)
// ---------------------------------------------------------------------------
__device__ float g_q[(size_t)MTOT * HH];             // 64 MB -> qh|ql splits
__device__ float g_k[(size_t)MTOT * HH];             // 64 MB -> kh|kl
__device__ float g_v[(size_t)MTOT * DHH];            //  4 MB -> vh|vl
__device__ float g_m[(size_t)MTOT * DHH];            //  4 MB -> mh|ml splits
__device__ __nv_bfloat16 g_xh[(size_t)MTOT * HH];    // 32 MB
__device__ __nv_bfloat16 g_xl[(size_t)MTOT * HH];    // 32 MB
// Wq^T (1024 rows) | Wk^T (1024 rows) | Wv^T (64 rows), all stride HH
__device__ __nv_bfloat16 g_wth[(size_t)2 * HH * HH + 64 * HH];
__device__ __nv_bfloat16 g_wtl[(size_t)2 * HH * HH + 64 * HH];
// Wo^T: 1024 rows x 64 cols
__device__ __nv_bfloat16 g_wtoh[(size_t)HH * 64];
__device__ __nv_bfloat16 g_wtol[(size_t)HH * 64];

// ---------------------------------------------------------------------------
// Baseline-ISA PTX helpers
// ---------------------------------------------------------------------------
__device__ __forceinline__ uint32_t su32(const void* p) {
    uint32_t a;
    asm("{ .reg .u64 t; cvta.to.shared.u64 t, %1; cvt.u32.u64 %0, t; }"
        : "=r"(a) : "l"(p));
    return a;
}
#define CP16(dst, src) \
    asm volatile("cp.async.cg.shared.global [%0], [%1], 16;" \
                 :: "r"(dst), "l"(src))
#define CP_COMMIT() asm volatile("cp.async.commit_group;" ::: "memory")
#define CP_WAIT1()  asm volatile("cp.async.wait_group 1;" ::: "memory")
#define CP_WAIT0()  asm volatile("cp.async.wait_group 0;" ::: "memory")
#define LDSM4(r0, r1, r2, r3, addr) \
    asm volatile("ldmatrix.sync.aligned.m8n8.x4.shared.b16 {%0,%1,%2,%3}, [%4];" \
                 : "=r"(r0), "=r"(r1), "=r"(r2), "=r"(r3) : "r"(addr))
#define LDSM4T(r0, r1, r2, r3, addr) \
    asm volatile("ldmatrix.sync.aligned.m8n8.x4.trans.shared.b16 {%0,%1,%2,%3}, [%4];" \
                 : "=r"(r0), "=r"(r1), "=r"(r2), "=r"(r3) : "r"(addr))
#define MMA16816(d, a, b) \
    asm volatile("mma.sync.aligned.m16n8k16.row.col.f32.bf16.bf16.f32 " \
                 "{%0,%1,%2,%3}, {%4,%5,%6,%7}, {%8,%9}, {%0,%1,%2,%3};" \
                 : "+f"((d)[0]), "+f"((d)[1]), "+f"((d)[2]), "+f"((d)[3]) \
                 : "r"((a)[0]), "r"((a)[1]), "r"((a)[2]), "r"((a)[3]), \
                   "r"((b)[0]), "r"((b)[1]))

__device__ __forceinline__ uint32_t sw128(uint32_t off) {
    return off ^ ((off >> 3) & 0x70u);
}
__device__ __forceinline__ void split2(float a, float b,
                                       uint32_t& hi, uint32_t& lo) {
    __nv_bfloat162 h = __floats2bfloat162_rn(a, b);
    float ra = a - __bfloat162float(h.x);
    float rb = b - __bfloat162float(h.y);
    __nv_bfloat162 l = __floats2bfloat162_rn(ra, rb);
    hi = *(uint32_t*)&h;
    lo = *(uint32_t*)&l;
}

// ---------------------------------------------------------------------------
// Split fp32 -> bf16 hi + bf16 lo
// ---------------------------------------------------------------------------
__global__ __launch_bounds__(256) void convert_x(
    const float* __restrict__ x, __nv_bfloat16* __restrict__ xh,
    __nv_bfloat16* __restrict__ xl)
{
    size_t i = ((size_t)blockIdx.x * blockDim.x + threadIdx.x) * 4;
    float4 v = *(const float4*)(x + i);
    uint32_t h0, l0, h1, l1;
    split2(v.x, v.y, h0, l0);
    split2(v.z, v.w, h1, l1);
    *(uint32_t*)(xh + i)     = h0;
    *(uint32_t*)(xh + i + 2) = h1;
    *(uint32_t*)(xl + i)     = l0;
    *(uint32_t*)(xl + i + 2) = l1;
}

// ---------------------------------------------------------------------------
// Generic transpose + split: src[R][C] fp32 -> dst[C][R] bf16 hi/lo
// grid (C/32, R/32), block 256
// ---------------------------------------------------------------------------
__global__ __launch_bounds__(256) void tsplit(
    const float* __restrict__ src, __nv_bfloat16* __restrict__ dh,
    __nv_bfloat16* __restrict__ dl, int R, int C)
{
    __shared__ float t[32][33];
    int c0 = blockIdx.x * 32, r0 = blockIdx.y * 32;
    int tx = threadIdx.x & 31, ty = threadIdx.x >> 5;
    #pragma unroll
    for (int j = 0; j < 4; j++)
        t[ty + j*8][tx] = src[(size_t)(r0 + ty + j*8) * C + c0 + tx];
    __syncthreads();
    #pragma unroll
    for (int j = 0; j < 4; j++) {
        int ro = c0 + ty + j*8;     // output row (0..C)
        int co = r0 + tx;           // output col (0..R)
        float v = t[tx][ty + j*8];
        __nv_bfloat16 h = __float2bfloat16(v);
        dh[(size_t)ro * R + co] = h;
        dl[(size_t)ro * R + co] = __float2bfloat16(v - __bfloat162float(h));
    }
}

// ---------------------------------------------------------------------------
// Fused Q+K+V projection: mma.sync bf16, 3-pass compensated split.
// grid.x = 17 tiles: 0-7 Q cols, 8-15 K cols, 16 V (N=64). grid.y = m-tile.
// 3-stage cp.async pipeline (BK=64, 64 KB/stage), 1 syncthreads per chunk.
// Epilogue writes bf16 hi/lo splits; Q pre-scaled by 1/8.
// ---------------------------------------------------------------------------
#define QK_STAGE 65536
#define QK_SMEM  (3 * QK_STAGE)

__global__ __launch_bounds__(256, 1) void qkv_gemm(
    const __nv_bfloat16* __restrict__ xh, const __nv_bfloat16* __restrict__ xl,
    const __nv_bfloat16* __restrict__ wth, const __nv_bfloat16* __restrict__ wtl,
    const float* __restrict__ bq, const float* __restrict__ bk,
    const float* __restrict__ bv,
    __nv_bfloat16* __restrict__ qh, __nv_bfloat16* __restrict__ ql,
    __nv_bfloat16* __restrict__ kh, __nv_bfloat16* __restrict__ kl,
    __nv_bfloat16* __restrict__ vh, __nv_bfloat16* __restrict__ vl)
{
    extern __shared__ char smem[];
    const uint32_t sb = su32(smem);
    const int tid = threadIdx.x;
    const int lane = tid & 31;
    const int wid = tid >> 5;
    const int warp_m = wid & 3;
    const int warp_n = wid >> 2;

    const int ntile = blockIdx.x;
    const int which = ntile >> 3;        // 0=Q, 1=K, 2=V
    const int n0 = (ntile & 7) * 128;    // 0 for V
    const int m0 = blockIdx.y * 128;

    const __nv_bfloat16* wbh = wth + (size_t)which * HH * HH;
    const __nv_bfloat16* wbl = wtl + (size_t)which * HH * HH;

    float c[2][8][4];
    #pragma unroll
    for (int tm = 0; tm < 2; tm++)
        #pragma unroll
        for (int j = 0; j < 8; j++)
            #pragma unroll
            for (int r = 0; r < 4; r++) c[tm][j][r] = 0.f;

    auto load_stage = [&](int stage, int k0) {
        const uint32_t sa = sb + stage * QK_STAGE;
        #pragma unroll
        for (int i = 0; i < 4; i++) {
            int s = tid + (i << 8);
            int r = s >> 3, ch = s & 7;
            uint32_t off = sw128((uint32_t)(r * 128 + ch * 16));
            const size_t ga = (size_t)(m0 + r) * HH + k0 + ch * 8;
            const int br = (which == 2) ? (r & 63) : r;  // clamp V rows
            const size_t gb = (size_t)(n0 + br) * HH + k0 + ch * 8;
            CP16(sa + off,         xh + ga);
            CP16(sa + 16384 + off, xl + ga);
            CP16(sa + 32768 + off, wbh + gb);
            CP16(sa + 49152 + off, wbl + gb);
        }
        CP_COMMIT();
    };

    load_stage(0, 0);
    load_stage(1, 64);

    for (int cch = 0; cch < 16; cch++) {
        if (cch + 2 < 16) CP_WAIT1(); else CP_WAIT0();
        __syncthreads();
        if (cch + 2 < 16) load_stage((cch + 2) % 3, (cch + 2) * 64);

        const uint32_t sa = sb + (cch % 3) * QK_STAGE;
        #pragma unroll
        for (int kk = 0; kk < 4; kk++) {
            const int kc0 = kk * 2;
            uint32_t ah[2][4], al[2][4];
            {
                const int mat = lane >> 3, rin = lane & 7;
                #pragma unroll
                for (int tm = 0; tm < 2; tm++) {
                    int row = warp_m * 32 + tm * 16 + (mat & 1) * 8 + rin;
                    int ch  = kc0 + (mat >> 1);
                    uint32_t off = sw128((uint32_t)(row * 128 + ch * 16));
                    LDSM4(ah[tm][0], ah[tm][1], ah[tm][2], ah[tm][3], sa + off);
                    LDSM4(al[tm][0], al[tm][1], al[tm][2], al[tm][3],
                          sa + 16384 + off);
                }
            }
            uint32_t bh[8][2], bl[8][2];
            {
                const int mat = lane >> 3, rin = lane & 7;
                #pragma unroll
                for (int jp = 0; jp < 4; jp++) {
                    int grp = jp * 2 + (mat >> 1);
                    int ch  = kc0 + (mat & 1);
                    int row = warp_n * 64 + grp * 8 + rin;
                    uint32_t off = sw128((uint32_t)(row * 128 + ch * 16));
                    uint32_t r0, r1, r2, r3;
                    LDSM4(r0, r1, r2, r3, sa + 32768 + off);
                    bh[jp*2][0] = r0; bh[jp*2][1] = r1;
                    bh[jp*2+1][0] = r2; bh[jp*2+1][1] = r3;
                    LDSM4(r0, r1, r2, r3, sa + 49152 + off);
                    bl[jp*2][0] = r0; bl[jp*2][1] = r1;
                    bl[jp*2+1][0] = r2; bl[jp*2+1][1] = r3;
                }
            }
            #pragma unroll
            for (int tm = 0; tm < 2; tm++)
                #pragma unroll
                for (int j = 0; j < 8; j++) {
                    MMA16816(c[tm][j], ah[tm], bh[j]);
                    MMA16816(c[tm][j], ah[tm], bl[j]);
                    MMA16816(c[tm][j], al[tm], bh[j]);
                }
        }
        __syncthreads();
    }

    // epilogue: bias + scale + bf16 split store
    const float scale = (which == 0) ? 0.125f : 1.0f;
    const float* bias = (which == 0) ? bq : (which == 1) ? bk : bv;
    __nv_bfloat16* oh = (which == 0) ? qh : (which == 1) ? kh : vh;
    __nv_bfloat16* ol = (which == 0) ? ql : (which == 1) ? kl : vl;
    const size_t ostr = (which == 2) ? 64 : HH;

    #pragma unroll
    for (int tm = 0; tm < 2; tm++) {
        #pragma unroll
        for (int j = 0; j < 8; j++) {
            int gnl = warp_n * 64 + j * 8 + 2 * (lane & 3);
            if (which == 2 && gnl >= 64) continue;   // V: only 64 cols
            float2 bv2 = *(const float2*)&bias[n0 + gnl];
            int gm0 = m0 + warp_m * 32 + tm * 16 + (lane >> 2);
            float v0 = (c[tm][j][0] + bv2.x) * scale;
            float v1 = (c[tm][j][1] + bv2.y) * scale;
            float v2 = (c[tm][j][2] + bv2.x) * scale;
            float v3 = (c[tm][j][3] + bv2.y) * scale;
            uint32_t h01, l01, h23, l23;
            split2(v0, v1, h01, l01);
            split2(v2, v3, h23, l23);
            size_t a0 = (size_t)gm0 * ostr + n0 + gnl;
            size_t a1 = (size_t)(gm0 + 8) * ostr + n0 + gnl;
            *(uint32_t*)(oh + a0) = h01;
            *(uint32_t*)(ol + a0) = l01;
            *(uint32_t*)(oh + a1) = h23;
            *(uint32_t*)(ol + a1) = l23;
        }
    }
}

// ---------------------------------------------------------------------------
// O projection: out[M,1024] = m[M,64] @ Wo[64,1024], bf16 3-pass mma, K=64.
// Single smem stage (64 KB). grid (8, 128).
// ---------------------------------------------------------------------------
#define OG_SMEM 65536

__global__ __launch_bounds__(256) void out_gemm(
    const __nv_bfloat16* __restrict__ mh, const __nv_bfloat16* __restrict__ ml,
    const __nv_bfloat16* __restrict__ wtoh, const __nv_bfloat16* __restrict__ wtol,
    float* __restrict__ out)
{
    extern __shared__ char smem[];
    const uint32_t sb = su32(smem);
    const int tid = threadIdx.x;
    const int lane = tid & 31;
    const int wid = tid >> 5;
    const int warp_m = wid & 3;
    const int warp_n = wid >> 2;
    const int n0 = blockIdx.x * 128;
    const int m0 = blockIdx.y * 128;

    // load A (m splits) and B (Wo^T splits): 128 rows x 128B each, 4 arrays
    #pragma unroll
    for (int i = 0; i < 4; i++) {
        int s = tid + (i << 8);
        int r = s >> 3, ch = s & 7;
        uint32_t off = sw128((uint32_t)(r * 128 + ch * 16));
        const size_t ga = (size_t)(m0 + r) * 64 + ch * 8;
        const size_t gb = (size_t)(n0 + r) * 64 + ch * 8;
        CP16(sb + off,         mh + ga);
        CP16(sb + 16384 + off, ml + ga);
        CP16(sb + 32768 + off, wtoh + gb);
        CP16(sb + 49152 + off, wtol + gb);
    }
    CP_COMMIT();
    CP_WAIT0();
    __syncthreads();

    float c[2][8][4];
    #pragma unroll
    for (int tm = 0; tm < 2; tm++)
        #pragma unroll
        for (int j = 0; j < 8; j++)
            #pragma unroll
            for (int r = 0; r < 4; r++) c[tm][j][r] = 0.f;

    #pragma unroll
    for (int kk = 0; kk < 4; kk++) {
        const int kc0 = kk * 2;
        uint32_t ah[2][4], al[2][4];
        {
            const int mat = lane >> 3, rin = lane & 7;
            #pragma unroll
            for (int tm = 0; tm < 2; tm++) {
                int row = warp_m * 32 + tm * 16 + (mat & 1) * 8 + rin;
                int ch  = kc0 + (mat >> 1);
                uint32_t off = sw128((uint32_t)(row * 128 + ch * 16));
                LDSM4(ah[tm][0], ah[tm][1], ah[tm][2], ah[tm][3], sb + off);
                LDSM4(al[tm][0], al[tm][1], al[tm][2], al[tm][3],
                      sb + 16384 + off);
            }
        }
        uint32_t bh[8][2], bl[8][2];
        {
            const int mat = lane >> 3, rin = lane & 7;
            #pragma unroll
            for (int jp = 0; jp < 4; jp++) {
                int grp = jp * 2 + (mat >> 1);
                int ch  = kc0 + (mat & 1);
                int row = warp_n * 64 + grp * 8 + rin;
                uint32_t off = sw128((uint32_t)(row * 128 + ch * 16));
                uint32_t r0, r1, r2, r3;
                LDSM4(r0, r1, r2, r3, sb + 32768 + off);
                bh[jp*2][0] = r0; bh[jp*2][1] = r1;
                bh[jp*2+1][0] = r2; bh[jp*2+1][1] = r3;
                LDSM4(r0, r1, r2, r3, sb + 49152 + off);
                bl[jp*2][0] = r0; bl[jp*2][1] = r1;
                bl[jp*2+1][0] = r2; bl[jp*2+1][1] = r3;
            }
        }
        #pragma unroll
        for (int tm = 0; tm < 2; tm++)
            #pragma unroll
            for (int j = 0; j < 8; j++) {
                MMA16816(c[tm][j], ah[tm], bh[j]);
                MMA16816(c[tm][j], ah[tm], bl[j]);
                MMA16816(c[tm][j], al[tm], bh[j]);
            }
    }

    #pragma unroll
    for (int tm = 0; tm < 2; tm++) {
        #pragma unroll
        for (int j = 0; j < 8; j++) {
            int gn = n0 + warp_n * 64 + j * 8 + 2 * (lane & 3);
            int gm0 = m0 + warp_m * 32 + tm * 16 + (lane >> 2);
            float2 o0, o1;
            o0.x = c[tm][j][0]; o0.y = c[tm][j][1];
            o1.x = c[tm][j][2]; o1.y = c[tm][j][3];
            *(float2*)&out[(size_t)gm0 * HH + gn]       = o0;
            *(float2*)&out[(size_t)(gm0 + 8) * HH + gn] = o1;
        }
    }
}

// ---------------------------------------------------------------------------
// Tensor-core causal flash attention (unchanged from round 4).
// ---------------------------------------------------------------------------
#define AT_STAGE 32768
#define AT_SMEM  (2 * AT_STAGE)

__global__ __launch_bounds__(256) void attn_mma(
    const __nv_bfloat16* __restrict__ qh, const __nv_bfloat16* __restrict__ ql,
    const __nv_bfloat16* __restrict__ kh, const __nv_bfloat16* __restrict__ kl,
    const __nv_bfloat16* __restrict__ vh, const __nv_bfloat16* __restrict__ vl,
    float* __restrict__ attn_out)
{
    extern __shared__ char smem[];
    const uint32_t sb = su32(smem);
    const int tid = threadIdx.x;
    const int lane = tid & 31;
    const int w = tid >> 5;

    const int b  = blockIdx.z;
    const int h  = blockIdx.y;
    const int qi = blockIdx.x;
    const int q0 = qi * 128;

    #pragma unroll
    for (int i = 0; i < 4; i++) {
        int idx = tid + (i << 8);
        int r = idx >> 3, ch = idx & 7;
        uint32_t off = sw128((uint32_t)(r * 128 + ch * 16));
        size_t g = (size_t)(b * TT + q0 + r) * HH + h * 64 + ch * 8;
        CP16(sb + off,         qh + g);
        CP16(sb + 16384 + off, ql + g);
    }
    CP_COMMIT();
    CP_WAIT0();
    __syncthreads();

    uint32_t Aqh[4][4], Aql[4][4];
    {
        const int tile = lane >> 3, rin = lane & 7;
        #pragma unroll
        for (int g = 0; g < 4; g++) {
            int row = w * 16 + (tile & 1) * 8 + rin;
            int ch  = 2 * g + (tile >> 1);
            uint32_t off = sw128((uint32_t)(row * 128 + ch * 16));
            LDSM4(Aqh[g][0], Aqh[g][1], Aqh[g][2], Aqh[g][3], sb + off);
            LDSM4(Aql[g][0], Aql[g][1], Aql[g][2], Aql[g][3], sb + 16384 + off);
        }
    }
    __syncthreads();

    float m0r = -1e30f, m1r = -1e30f, l0r = 0.f, l1r = 0.f;
    float o[8][4];
    #pragma unroll
    for (int j = 0; j < 8; j++)
        #pragma unroll
        for (int e = 0; e < 4; e++) o[j][e] = 0.f;

    const int ntiles = 2 * qi + 2;

    auto load_kv = [&](int stg, int kt) {
        const uint32_t sa = sb + stg * AT_STAGE;
        const size_t rowb = (size_t)(b * TT + kt * 64);
        #pragma unroll
        for (int i = 0; i < 2; i++) {
            int idx = tid + (i << 8);
            int r = idx >> 3, ch = idx & 7;
            uint32_t off = sw128((uint32_t)(r * 128 + ch * 16));
            size_t gk = (rowb + r) * HH + h * 64 + ch * 8;
            size_t gv = (rowb + r) * 64 + ch * 8;
            CP16(sa + off,         kh + gk);
            CP16(sa + 8192 + off,  kl + gk);
            CP16(sa + 16384 + off, vh + gv);
            CP16(sa + 24576 + off, vl + gv);
        }
        CP_COMMIT();
    };

    load_kv(0, 0);

    for (int kt = 0; kt < ntiles; kt++) {
        if (kt + 1 < ntiles) { load_kv((kt + 1) & 1, kt + 1); CP_WAIT1(); }
        else                 { CP_WAIT0(); }
        __syncthreads();

        const bool skip = (kt * 64) > (q0 + w * 16 + 15);
        if (!skip) {
            const uint32_t sa = sb + (kt & 1) * AT_STAGE;
            const int tile = lane >> 3, rin = lane & 7;

            float s[8][4];
            #pragma unroll
            for (int j = 0; j < 8; j++)
                #pragma unroll
                for (int e = 0; e < 4; e++) s[j][e] = 0.f;

            #pragma unroll
            for (int g = 0; g < 4; g++) {
                uint32_t bh[8][2], bl[8][2];
                #pragma unroll
                for (int p = 0; p < 4; p++) {
                    int row = 16 * p + (tile >> 1) * 8 + rin;
                    int ch  = 2 * g + (tile & 1);
                    uint32_t off = sw128((uint32_t)(row * 128 + ch * 16));
                    uint32_t r0, r1, r2, r3;
                    LDSM4(r0, r1, r2, r3, sa + off);
                    bh[2*p][0] = r0; bh[2*p][1] = r1;
                    bh[2*p+1][0] = r2; bh[2*p+1][1] = r3;
                    LDSM4(r0, r1, r2, r3, sa + 8192 + off);
                    bl[2*p][0] = r0; bl[2*p][1] = r1;
                    bl[2*p+1][0] = r2; bl[2*p+1][1] = r3;
                }
                #pragma unroll
                for (int j = 0; j < 8; j++) {
                    MMA16816(s[j], Aqh[g], bh[j]);
                    MMA16816(s[j], Aqh[g], bl[j]);
                    MMA16816(s[j], Aql[g], bh[j]);
                }
            }

            const int gr0 = q0 + w * 16 + (lane >> 2);
            if (kt * 64 + 63 > q0 + w * 16) {
                #pragma unroll
                for (int j = 0; j < 8; j++) {
                    int col = kt * 64 + j * 8 + 2 * (lane & 3);
                    if (col     > gr0)     s[j][0] = -1e30f;
                    if (col + 1 > gr0)     s[j][1] = -1e30f;
                    if (col     > gr0 + 8) s[j][2] = -1e30f;
                    if (col + 1 > gr0 + 8) s[j][3] = -1e30f;
                }
            }

            float mx0 = -1e30f, mx1 = -1e30f;
            #pragma unroll
            for (int j = 0; j < 8; j++) {
                mx0 = fmaxf(mx0, fmaxf(s[j][0], s[j][1]));
                mx1 = fmaxf(mx1, fmaxf(s[j][2], s[j][3]));
            }
            mx0 = fmaxf(mx0, __shfl_xor_sync(0xffffffffu, mx0, 1));
            mx0 = fmaxf(mx0, __shfl_xor_sync(0xffffffffu, mx0, 2));
            mx1 = fmaxf(mx1, __shfl_xor_sync(0xffffffffu, mx1, 1));
            mx1 = fmaxf(mx1, __shfl_xor_sync(0xffffffffu, mx1, 2));

            float mn0 = fmaxf(m0r, mx0), mn1 = fmaxf(m1r, mx1);
            float c0 = __expf(m0r - mn0), c1 = __expf(m1r - mn1);
            float sum0 = 0.f, sum1 = 0.f;
            #pragma unroll
            for (int j = 0; j < 8; j++) {
                s[j][0] = __expf(s[j][0] - mn0);
                s[j][1] = __expf(s[j][1] - mn0);
                s[j][2] = __expf(s[j][2] - mn1);
                s[j][3] = __expf(s[j][3] - mn1);
                sum0 += s[j][0] + s[j][1];
                sum1 += s[j][2] + s[j][3];
            }
            sum0 += __shfl_xor_sync(0xffffffffu, sum0, 1);
            sum0 += __shfl_xor_sync(0xffffffffu, sum0, 2);
            sum1 += __shfl_xor_sync(0xffffffffu, sum1, 1);
            sum1 += __shfl_xor_sync(0xffffffffu, sum1, 2);
            m0r = mn0; m1r = mn1;
            l0r = l0r * c0 + sum0;
            l1r = l1r * c1 + sum1;

            uint32_t Aph[4][4], Apl[4][4];
            #pragma unroll
            for (int g = 0; g < 4; g++) {
                split2(s[2*g][0],   s[2*g][1],   Aph[g][0], Apl[g][0]);
                split2(s[2*g][2],   s[2*g][3],   Aph[g][1], Apl[g][1]);
                split2(s[2*g+1][0], s[2*g+1][1], Aph[g][2], Apl[g][2]);
                split2(s[2*g+1][2], s[2*g+1][3], Aph[g][3], Apl[g][3]);
            }

            #pragma unroll
            for (int j = 0; j < 8; j++) {
                o[j][0] *= c0; o[j][1] *= c0;
                o[j][2] *= c1; o[j][3] *= c1;
            }

            #pragma unroll
            for (int g = 0; g < 4; g++) {
                uint32_t bvh[8][2], bvl[8][2];
                #pragma unroll
                for (int p = 0; p < 4; p++) {
                    int row = 16 * g + (tile & 1) * 8 + rin;
                    int ch  = 2 * p + (tile >> 1);
                    uint32_t off = sw128((uint32_t)(row * 128 + ch * 16));
                    uint32_t r0, r1, r2, r3;
                    LDSM4T(r0, r1, r2, r3, sa + 16384 + off);
                    bvh[2*p][0] = r0; bvh[2*p][1] = r1;
                    bvh[2*p+1][0] = r2; bvh[2*p+1][1] = r3;
                    LDSM4T(r0, r1, r2, r3, sa + 24576 + off);
                    bvl[2*p][0] = r0; bvl[2*p][1] = r1;
                    bvl[2*p+1][0] = r2; bvl[2*p+1][1] = r3;
                }
                #pragma unroll
                for (int j = 0; j < 8; j++) {
                    MMA16816(o[j], Aph[g], bvh[j]);
                    MMA16816(o[j], Aph[g], bvl[j]);
                    MMA16816(o[j], Apl[g], bvh[j]);
                }
            }
        }
        __syncthreads();
    }

    const float inv0 = 1.f / l0r, inv1 = 1.f / l1r;
    const int gr0 = q0 + w * 16 + (lane >> 2);
    float* base = attn_out + (((size_t)b * NHH + h) * TT) * DHH;
    #pragma unroll
    for (int j = 0; j < 8; j++) {
        int col = j * 8 + 2 * (lane & 3);
        float2 v0, v1;
        v0.x = o[j][0] * inv0; v0.y = o[j][1] * inv0;
        v1.x = o[j][2] * inv1; v1.y = o[j][3] * inv1;
        *(float2*)(base + (size_t)gr0 * DHH + col)       = v0;
        *(float2*)(base + (size_t)(gr0 + 8) * DHH + col) = v1;
    }
}

// ---------------------------------------------------------------------------
// Head-mean pooling fused with bf16 hi/lo split output
// ---------------------------------------------------------------------------
__global__ __launch_bounds__(256) void head_mean_split(
    const float* __restrict__ attn, __nv_bfloat16* __restrict__ mh,
    __nv_bfloat16* __restrict__ ml)
{
    int idx = blockIdx.x * blockDim.x + threadIdx.x;
    int d4 = idx & 15;
    int bt = idx >> 4;
    int b  = bt / TT;
    int t  = bt % TT;
    float4 acc = make_float4(0.f, 0.f, 0.f, 0.f);
    #pragma unroll
    for (int h = 0; h < NHH; h++) {
        float4 vv = *(const float4*)&attn[(((size_t)b*NHH + h)*TT + t)*DHH + d4*4];
        acc.x += vv.x; acc.y += vv.y; acc.z += vv.z; acc.w += vv.w;
    }
    const float inv = 1.f / (float)NHH;
    uint32_t h01, l01, h23, l23;
    split2(acc.x * inv, acc.y * inv, h01, l01);
    split2(acc.z * inv, acc.w * inv, h23, l23);
    size_t o = (size_t)bt * DHH + d4 * 4;
    *(uint32_t*)(mh + o)     = h01;
    *(uint32_t*)(mh + o + 2) = h23;
    *(uint32_t*)(ml + o)     = l01;
    *(uint32_t*)(ml + o + 2) = l23;
}

// ---------------------------------------------------------------------------
extern "C" void kernel_launch(void* const* d_in, const int* in_sizes, int n_in,
                              void* d_out, int out_size)
{
    const float* x  = (const float*)d_in[0];
    const float* Wq = (const float*)d_in[1];
    const float* bq = (const float*)d_in[2];
    const float* Wk = (const float*)d_in[3];
    const float* bk = (const float*)d_in[4];
    const float* Wv = (const float*)d_in[5];
    const float* bv = (const float*)d_in[6];
    const float* Wo = (const float*)d_in[7];

    float* out  = (float*)d_out;                      // [32,512,1024]
    float* attn = out + (size_t)MTOT * HH;            // [32,16,512,64]

    float *qbuf, *kbuf, *vbuf, *mbuf;
    __nv_bfloat16 *xh, *xl, *wth, *wtl, *wtoh, *wtol;
    cudaGetSymbolAddress((void**)&qbuf, g_q);
    cudaGetSymbolAddress((void**)&kbuf, g_k);
    cudaGetSymbolAddress((void**)&vbuf, g_v);
    cudaGetSymbolAddress((void**)&mbuf, g_m);
    cudaGetSymbolAddress((void**)&xh, g_xh);
    cudaGetSymbolAddress((void**)&xl, g_xl);
    cudaGetSymbolAddress((void**)&wth, g_wth);
    cudaGetSymbolAddress((void**)&wtl, g_wtl);
    cudaGetSymbolAddress((void**)&wtoh, g_wtoh);
    cudaGetSymbolAddress((void**)&wtol, g_wtol);

    __nv_bfloat16* qh = (__nv_bfloat16*)qbuf;
    __nv_bfloat16* ql = qh + (size_t)MTOT * HH;
    __nv_bfloat16* kh = (__nv_bfloat16*)kbuf;
    __nv_bfloat16* kl = kh + (size_t)MTOT * HH;
    __nv_bfloat16* vh = (__nv_bfloat16*)vbuf;
    __nv_bfloat16* vl = vh + (size_t)MTOT * DHH;
    __nv_bfloat16* mh = (__nv_bfloat16*)mbuf;
    __nv_bfloat16* ml = mh + (size_t)MTOT * DHH;

    cudaFuncSetAttribute(qkv_gemm, cudaFuncAttributeMaxDynamicSharedMemorySize,
                         QK_SMEM);
    cudaFuncSetAttribute(attn_mma, cudaFuncAttributeMaxDynamicSharedMemorySize,
                         AT_SMEM);
    cudaFuncSetAttribute(out_gemm, cudaFuncAttributeMaxDynamicSharedMemorySize,
                         OG_SMEM);

    dim3 blk(256);

    // bf16 splits of x and all weights
    convert_x<<<dim3(((size_t)MTOT*HH/4)/256), blk>>>(x, xh, xl);
    tsplit<<<dim3(32, 32), blk>>>(Wq, wth, wtl, HH, HH);
    tsplit<<<dim3(32, 32), blk>>>(Wk, wth + (size_t)HH*HH, wtl + (size_t)HH*HH,
                                  HH, HH);
    tsplit<<<dim3(2, 32),  blk>>>(Wv, wth + (size_t)2*HH*HH,
                                  wtl + (size_t)2*HH*HH, HH, 64);
    tsplit<<<dim3(32, 2),  blk>>>(Wo, wtoh, wtol, 64, HH);

    // Q+K+V projections (tensor, 3-pass) -> bf16 splits (Q pre-scaled 1/8)
    qkv_gemm<<<dim3(17, MTOT/128), blk, QK_SMEM>>>(xh, xl, wth, wtl,
                                                   bq, bk, bv,
                                                   qh, ql, kh, kl, vh, vl);

    // Tensor-core causal attention -> attn_vec (fp32)
    attn_mma<<<dim3(TT/128, NHH, BSZ), blk, AT_SMEM>>>(qh, ql, kh, kl,
                                                       vh, vl, attn);

    // Head mean (+split) and O projection (tensor, 3-pass)
    head_mean_split<<<dim3((MTOT * (DHH/4)) / 256), blk>>>(attn, mh, ml);
    out_gemm<<<dim3(8, MTOT/128), blk, OG_SMEM>>>(mh, ml, wtoh, wtol, out);
}

// round 6
// speedup vs baseline: 3.0819x; 1.0213x over previous
#include <cuda_runtime.h>
#include <cuda_bf16.h>
#include <math.h>
#include <stdint.h>

#define BSZ 32
#define TT  512
#define HH  1024
#define DHH 64
#define NHH 16
#define MTOT (BSZ*TT)   // 16384

// ---------------------------------------------------------------------------
// Scratch (device globals: allocation-free contract)
// ---------------------------------------------------------------------------
__device__ float g_q[(size_t)MTOT * HH];             // 64 MB -> qh|ql splits
__device__ float g_k[(size_t)MTOT * HH];             // 64 MB -> kh|kl
__device__ float g_v[(size_t)MTOT * DHH];            //  4 MB -> vh|vl
__device__ float g_m[(size_t)MTOT * DHH];            //  4 MB -> mh|ml splits
__device__ __nv_bfloat16 g_xh[(size_t)MTOT * HH];    // 32 MB
__device__ __nv_bfloat16 g_xl[(size_t)MTOT * HH];    // 32 MB
// Wq^T (1024 rows) | Wk^T (1024 rows) | Wv^T (64 rows), all stride HH
__device__ __nv_bfloat16 g_wth[(size_t)2 * HH * HH + 64 * HH];
__device__ __nv_bfloat16 g_wtl[(size_t)2 * HH * HH + 64 * HH];
// Wo^T: 1024 rows x 64 cols
__device__ __nv_bfloat16 g_wtoh[(size_t)HH * 64];
__device__ __nv_bfloat16 g_wtol[(size_t)HH * 64];

// ---------------------------------------------------------------------------
// Baseline-ISA PTX helpers
// ---------------------------------------------------------------------------
__device__ __forceinline__ uint32_t su32(const void* p) {
    uint32_t a;
    asm("{ .reg .u64 t; cvta.to.shared.u64 t, %1; cvt.u32.u64 %0, t; }"
        : "=r"(a) : "l"(p));
    return a;
}
#define CP16(dst, src) \
    asm volatile("cp.async.cg.shared.global [%0], [%1], 16;" \
                 :: "r"(dst), "l"(src))
#define CP_COMMIT() asm volatile("cp.async.commit_group;" ::: "memory")
#define CP_WAIT1()  asm volatile("cp.async.wait_group 1;" ::: "memory")
#define CP_WAIT0()  asm volatile("cp.async.wait_group 0;" ::: "memory")
#define LDSM4(r0, r1, r2, r3, addr) \
    asm volatile("ldmatrix.sync.aligned.m8n8.x4.shared.b16 {%0,%1,%2,%3}, [%4];" \
                 : "=r"(r0), "=r"(r1), "=r"(r2), "=r"(r3) : "r"(addr))
#define LDSM4T(r0, r1, r2, r3, addr) \
    asm volatile("ldmatrix.sync.aligned.m8n8.x4.trans.shared.b16 {%0,%1,%2,%3}, [%4];" \
                 : "=r"(r0), "=r"(r1), "=r"(r2), "=r"(r3) : "r"(addr))
#define MMA16816(d, a, b) \
    asm volatile("mma.sync.aligned.m16n8k16.row.col.f32.bf16.bf16.f32 " \
                 "{%0,%1,%2,%3}, {%4,%5,%6,%7}, {%8,%9}, {%0,%1,%2,%3};" \
                 : "+f"((d)[0]), "+f"((d)[1]), "+f"((d)[2]), "+f"((d)[3]) \
                 : "r"((a)[0]), "r"((a)[1]), "r"((a)[2]), "r"((a)[3]), \
                   "r"((b)[0]), "r"((b)[1]))

__device__ __forceinline__ uint32_t sw128(uint32_t off) {
    return off ^ ((off >> 3) & 0x70u);
}
__device__ __forceinline__ void split2(float a, float b,
                                       uint32_t& hi, uint32_t& lo) {
    __nv_bfloat162 h = __floats2bfloat162_rn(a, b);
    float ra = a - __bfloat162float(h.x);
    float rb = b - __bfloat162float(h.y);
    __nv_bfloat162 l = __floats2bfloat162_rn(ra, rb);
    hi = *(uint32_t*)&h;
    lo = *(uint32_t*)&l;
}

// ---------------------------------------------------------------------------
// Split fp32 -> bf16 hi + bf16 lo
// ---------------------------------------------------------------------------
__global__ __launch_bounds__(256) void convert_x(
    const float* __restrict__ x, __nv_bfloat16* __restrict__ xh,
    __nv_bfloat16* __restrict__ xl)
{
    size_t i = ((size_t)blockIdx.x * blockDim.x + threadIdx.x) * 4;
    float4 v = *(const float4*)(x + i);
    uint32_t h0, l0, h1, l1;
    split2(v.x, v.y, h0, l0);
    split2(v.z, v.w, h1, l1);
    *(uint32_t*)(xh + i)     = h0;
    *(uint32_t*)(xh + i + 2) = h1;
    *(uint32_t*)(xl + i)     = l0;
    *(uint32_t*)(xl + i + 2) = l1;
}

// ---------------------------------------------------------------------------
// Generic transpose + split: src[R][C] fp32 -> dst[C][R] bf16 hi/lo
// ---------------------------------------------------------------------------
__global__ __launch_bounds__(256) void tsplit(
    const float* __restrict__ src, __nv_bfloat16* __restrict__ dh,
    __nv_bfloat16* __restrict__ dl, int R, int C)
{
    __shared__ float t[32][33];
    int c0 = blockIdx.x * 32, r0 = blockIdx.y * 32;
    int tx = threadIdx.x & 31, ty = threadIdx.x >> 5;
    #pragma unroll
    for (int j = 0; j < 4; j++)
        t[ty + j*8][tx] = src[(size_t)(r0 + ty + j*8) * C + c0 + tx];
    __syncthreads();
    #pragma unroll
    for (int j = 0; j < 4; j++) {
        int ro = c0 + ty + j*8;
        int co = r0 + tx;
        float v = t[tx][ty + j*8];
        __nv_bfloat16 h = __float2bfloat16(v);
        dh[(size_t)ro * R + co] = h;
        dl[(size_t)ro * R + co] = __float2bfloat16(v - __bfloat162float(h));
    }
}

// ---------------------------------------------------------------------------
// Fused Q+K+V projection: mma.sync bf16, 3-pass compensated split.
// 3-stage cp.async pipeline, ONE __syncthreads per k-chunk.
// ---------------------------------------------------------------------------
#define QK_STAGE 65536
#define QK_SMEM  (3 * QK_STAGE)

__global__ __launch_bounds__(256, 1) void qkv_gemm(
    const __nv_bfloat16* __restrict__ xh, const __nv_bfloat16* __restrict__ xl,
    const __nv_bfloat16* __restrict__ wth, const __nv_bfloat16* __restrict__ wtl,
    const float* __restrict__ bq, const float* __restrict__ bk,
    const float* __restrict__ bv,
    __nv_bfloat16* __restrict__ qh, __nv_bfloat16* __restrict__ ql,
    __nv_bfloat16* __restrict__ kh, __nv_bfloat16* __restrict__ kl,
    __nv_bfloat16* __restrict__ vh, __nv_bfloat16* __restrict__ vl)
{
    extern __shared__ char smem[];
    const uint32_t sb = su32(smem);
    const int tid = threadIdx.x;
    const int lane = tid & 31;
    const int wid = tid >> 5;
    const int warp_m = wid & 3;
    const int warp_n = wid >> 2;

    const int ntile = blockIdx.x;
    const int which = ntile >> 3;        // 0=Q, 1=K, 2=V
    const int n0 = (ntile & 7) * 128;
    const int m0 = blockIdx.y * 128;

    const __nv_bfloat16* wbh = wth + (size_t)which * HH * HH;
    const __nv_bfloat16* wbl = wtl + (size_t)which * HH * HH;

    float c[2][8][4];
    #pragma unroll
    for (int tm = 0; tm < 2; tm++)
        #pragma unroll
        for (int j = 0; j < 8; j++)
            #pragma unroll
            for (int r = 0; r < 4; r++) c[tm][j][r] = 0.f;

    auto load_stage = [&](int stage, int k0) {
        const uint32_t sa = sb + stage * QK_STAGE;
        #pragma unroll
        for (int i = 0; i < 4; i++) {
            int s = tid + (i << 8);
            int r = s >> 3, ch = s & 7;
            uint32_t off = sw128((uint32_t)(r * 128 + ch * 16));
            const size_t ga = (size_t)(m0 + r) * HH + k0 + ch * 8;
            const int br = (which == 2) ? (r & 63) : r;
            const size_t gb = (size_t)(n0 + br) * HH + k0 + ch * 8;
            CP16(sa + off,         xh + ga);
            CP16(sa + 16384 + off, xl + ga);
            CP16(sa + 32768 + off, wbh + gb);
            CP16(sa + 49152 + off, wbl + gb);
        }
        CP_COMMIT();
    };

    load_stage(0, 0);
    load_stage(1, 64);

    for (int cch = 0; cch < 16; cch++) {
        if (cch + 2 < 16) CP_WAIT1(); else CP_WAIT0();
        __syncthreads();
        if (cch + 2 < 16) load_stage((cch + 2) % 3, (cch + 2) * 64);

        const uint32_t sa = sb + (cch % 3) * QK_STAGE;
        #pragma unroll
        for (int kk = 0; kk < 4; kk++) {
            const int kc0 = kk * 2;
            uint32_t ah[2][4], al[2][4];
            {
                const int mat = lane >> 3, rin = lane & 7;
                #pragma unroll
                for (int tm = 0; tm < 2; tm++) {
                    int row = warp_m * 32 + tm * 16 + (mat & 1) * 8 + rin;
                    int ch  = kc0 + (mat >> 1);
                    uint32_t off = sw128((uint32_t)(row * 128 + ch * 16));
                    LDSM4(ah[tm][0], ah[tm][1], ah[tm][2], ah[tm][3], sa + off);
                    LDSM4(al[tm][0], al[tm][1], al[tm][2], al[tm][3],
                          sa + 16384 + off);
                }
            }
            uint32_t bh[8][2], bl[8][2];
            {
                const int mat = lane >> 3, rin = lane & 7;
                #pragma unroll
                for (int jp = 0; jp < 4; jp++) {
                    int grp = jp * 2 + (mat >> 1);
                    int ch  = kc0 + (mat & 1);
                    int row = warp_n * 64 + grp * 8 + rin;
                    uint32_t off = sw128((uint32_t)(row * 128 + ch * 16));
                    uint32_t r0, r1, r2, r3;
                    LDSM4(r0, r1, r2, r3, sa + 32768 + off);
                    bh[jp*2][0] = r0; bh[jp*2][1] = r1;
                    bh[jp*2+1][0] = r2; bh[jp*2+1][1] = r3;
                    LDSM4(r0, r1, r2, r3, sa + 49152 + off);
                    bl[jp*2][0] = r0; bl[jp*2][1] = r1;
                    bl[jp*2+1][0] = r2; bl[jp*2+1][1] = r3;
                }
            }
            #pragma unroll
            for (int tm = 0; tm < 2; tm++)
                #pragma unroll
                for (int j = 0; j < 8; j++) {
                    MMA16816(c[tm][j], ah[tm], bh[j]);
                    MMA16816(c[tm][j], ah[tm], bl[j]);
                    MMA16816(c[tm][j], al[tm], bh[j]);
                }
        }
        // no trailing sync: top-of-chunk sync protects stage reuse (3 stages)
    }

    // epilogue: bias + scale + bf16 split store
    const float scale = (which == 0) ? 0.125f : 1.0f;
    const float* bias = (which == 0) ? bq : (which == 1) ? bk : bv;
    __nv_bfloat16* oh = (which == 0) ? qh : (which == 1) ? kh : vh;
    __nv_bfloat16* ol = (which == 0) ? ql : (which == 1) ? kl : vl;
    const size_t ostr = (which == 2) ? 64 : HH;

    #pragma unroll
    for (int tm = 0; tm < 2; tm++) {
        #pragma unroll
        for (int j = 0; j < 8; j++) {
            int gnl = warp_n * 64 + j * 8 + 2 * (lane & 3);
            if (which == 2 && gnl >= 64) continue;
            float2 bv2 = *(const float2*)&bias[n0 + gnl];
            int gm0 = m0 + warp_m * 32 + tm * 16 + (lane >> 2);
            float v0 = (c[tm][j][0] + bv2.x) * scale;
            float v1 = (c[tm][j][1] + bv2.y) * scale;
            float v2 = (c[tm][j][2] + bv2.x) * scale;
            float v3 = (c[tm][j][3] + bv2.y) * scale;
            uint32_t h01, l01, h23, l23;
            split2(v0, v1, h01, l01);
            split2(v2, v3, h23, l23);
            size_t a0 = (size_t)gm0 * ostr + n0 + gnl;
            size_t a1 = (size_t)(gm0 + 8) * ostr + n0 + gnl;
            *(uint32_t*)(oh + a0) = h01;
            *(uint32_t*)(ol + a0) = l01;
            *(uint32_t*)(oh + a1) = h23;
            *(uint32_t*)(ol + a1) = l23;
        }
    }
}

// ---------------------------------------------------------------------------
// O projection: out[M,1024] = m[M,64] @ Wo[64,1024], bf16 3-pass mma, K=64.
// ---------------------------------------------------------------------------
#define OG_SMEM 65536

__global__ __launch_bounds__(256) void out_gemm(
    const __nv_bfloat16* __restrict__ mh, const __nv_bfloat16* __restrict__ ml,
    const __nv_bfloat16* __restrict__ wtoh, const __nv_bfloat16* __restrict__ wtol,
    float* __restrict__ out)
{
    extern __shared__ char smem[];
    const uint32_t sb = su32(smem);
    const int tid = threadIdx.x;
    const int lane = tid & 31;
    const int wid = tid >> 5;
    const int warp_m = wid & 3;
    const int warp_n = wid >> 2;
    const int n0 = blockIdx.x * 128;
    const int m0 = blockIdx.y * 128;

    #pragma unroll
    for (int i = 0; i < 4; i++) {
        int s = tid + (i << 8);
        int r = s >> 3, ch = s & 7;
        uint32_t off = sw128((uint32_t)(r * 128 + ch * 16));
        const size_t ga = (size_t)(m0 + r) * 64 + ch * 8;
        const size_t gb = (size_t)(n0 + r) * 64 + ch * 8;
        CP16(sb + off,         mh + ga);
        CP16(sb + 16384 + off, ml + ga);
        CP16(sb + 32768 + off, wtoh + gb);
        CP16(sb + 49152 + off, wtol + gb);
    }
    CP_COMMIT();
    CP_WAIT0();
    __syncthreads();

    float c[2][8][4];
    #pragma unroll
    for (int tm = 0; tm < 2; tm++)
        #pragma unroll
        for (int j = 0; j < 8; j++)
            #pragma unroll
            for (int r = 0; r < 4; r++) c[tm][j][r] = 0.f;

    #pragma unroll
    for (int kk = 0; kk < 4; kk++) {
        const int kc0 = kk * 2;
        uint32_t ah[2][4], al[2][4];
        {
            const int mat = lane >> 3, rin = lane & 7;
            #pragma unroll
            for (int tm = 0; tm < 2; tm++) {
                int row = warp_m * 32 + tm * 16 + (mat & 1) * 8 + rin;
                int ch  = kc0 + (mat >> 1);
                uint32_t off = sw128((uint32_t)(row * 128 + ch * 16));
                LDSM4(ah[tm][0], ah[tm][1], ah[tm][2], ah[tm][3], sb + off);
                LDSM4(al[tm][0], al[tm][1], al[tm][2], al[tm][3],
                      sb + 16384 + off);
            }
        }
        uint32_t bh[8][2], bl[8][2];
        {
            const int mat = lane >> 3, rin = lane & 7;
            #pragma unroll
            for (int jp = 0; jp < 4; jp++) {
                int grp = jp * 2 + (mat >> 1);
                int ch  = kc0 + (mat & 1);
                int row = warp_n * 64 + grp * 8 + rin;
                uint32_t off = sw128((uint32_t)(row * 128 + ch * 16));
                uint32_t r0, r1, r2, r3;
                LDSM4(r0, r1, r2, r3, sb + 32768 + off);
                bh[jp*2][0] = r0; bh[jp*2][1] = r1;
                bh[jp*2+1][0] = r2; bh[jp*2+1][1] = r3;
                LDSM4(r0, r1, r2, r3, sb + 49152 + off);
                bl[jp*2][0] = r0; bl[jp*2][1] = r1;
                bl[jp*2+1][0] = r2; bl[jp*2+1][1] = r3;
            }
        }
        #pragma unroll
        for (int tm = 0; tm < 2; tm++)
            #pragma unroll
            for (int j = 0; j < 8; j++) {
                MMA16816(c[tm][j], ah[tm], bh[j]);
                MMA16816(c[tm][j], ah[tm], bl[j]);
                MMA16816(c[tm][j], al[tm], bh[j]);
            }
    }

    #pragma unroll
    for (int tm = 0; tm < 2; tm++) {
        #pragma unroll
        for (int j = 0; j < 8; j++) {
            int gn = n0 + warp_n * 64 + j * 8 + 2 * (lane & 3);
            int gm0 = m0 + warp_m * 32 + tm * 16 + (lane >> 2);
            float2 o0, o1;
            o0.x = c[tm][j][0]; o0.y = c[tm][j][1];
            o1.x = c[tm][j][2]; o1.y = c[tm][j][3];
            *(float2*)&out[(size_t)gm0 * HH + gn]       = o0;
            *(float2*)&out[(size_t)(gm0 + 8) * HH + gn] = o1;
        }
    }
}

// ---------------------------------------------------------------------------
// Tensor-core causal flash attention — paired k-tiles (128 rows per sync).
// SMEM: 2 stages x [2 subtiles x (Kh|Kl|Vh|Vl, 8KB each)] + 32KB Q staging.
// ---------------------------------------------------------------------------
#define AT_SUB   32768
#define AT_STAGE (2 * AT_SUB)
#define AT_SMEM  (2 * AT_STAGE + 32768)   // 163840

__global__ __launch_bounds__(256) void attn_mma(
    const __nv_bfloat16* __restrict__ qh, const __nv_bfloat16* __restrict__ ql,
    const __nv_bfloat16* __restrict__ kh, const __nv_bfloat16* __restrict__ kl,
    const __nv_bfloat16* __restrict__ vh, const __nv_bfloat16* __restrict__ vl,
    float* __restrict__ attn_out)
{
    extern __shared__ char smem[];
    const uint32_t sb = su32(smem);
    const uint32_t qb = sb + 2 * AT_STAGE;
    const int tid = threadIdx.x;
    const int lane = tid & 31;
    const int w = tid >> 5;

    const int b  = blockIdx.z;
    const int h  = blockIdx.y;
    const int qi = blockIdx.x;
    const int q0 = qi * 128;

    // stage Q tile (hi/lo)
    #pragma unroll
    for (int i = 0; i < 4; i++) {
        int idx = tid + (i << 8);
        int r = idx >> 3, ch = idx & 7;
        uint32_t off = sw128((uint32_t)(r * 128 + ch * 16));
        size_t g = (size_t)(b * TT + q0 + r) * HH + h * 64 + ch * 8;
        CP16(qb + off,         qh + g);
        CP16(qb + 16384 + off, ql + g);
    }
    CP_COMMIT();

    // pair loader: 128 K rows + 128 V rows (hi/lo) into one stage
    auto load_pair = [&](int stg, int p) {
        const uint32_t sa = sb + stg * AT_STAGE;
        const size_t rowb = (size_t)(b * TT + p * 128);
        #pragma unroll
        for (int i = 0; i < 4; i++) {
            int idx = tid + (i << 8);
            int r = idx >> 3, ch = idx & 7;   // r in 0..127
            uint32_t sub = (uint32_t)(r >> 6) * AT_SUB;
            uint32_t off = sub + sw128((uint32_t)((r & 63) * 128 + ch * 16));
            size_t gk = (rowb + r) * HH + h * 64 + ch * 8;
            size_t gv = (rowb + r) * 64 + ch * 8;
            CP16(sa + off,         kh + gk);
            CP16(sa + 8192 + off,  kl + gk);
            CP16(sa + 16384 + off, vh + gv);
            CP16(sa + 24576 + off, vl + gv);
        }
        CP_COMMIT();
    };

    load_pair(0, 0);

    // Q complete (pair0 may still be pending)
    CP_WAIT1();
    __syncthreads();

    uint32_t Aqh[4][4], Aql[4][4];
    {
        const int tile = lane >> 3, rin = lane & 7;
        #pragma unroll
        for (int g = 0; g < 4; g++) {
            int row = w * 16 + (tile & 1) * 8 + rin;
            int ch  = 2 * g + (tile >> 1);
            uint32_t off = sw128((uint32_t)(row * 128 + ch * 16));
            LDSM4(Aqh[g][0], Aqh[g][1], Aqh[g][2], Aqh[g][3], qb + off);
            LDSM4(Aql[g][0], Aql[g][1], Aql[g][2], Aql[g][3], qb + 16384 + off);
        }
    }

    float m0r = -1e30f, m1r = -1e30f, l0r = 0.f, l1r = 0.f;
    float o[8][4];
    #pragma unroll
    for (int j = 0; j < 8; j++)
        #pragma unroll
        for (int e = 0; e < 4; e++) o[j][e] = 0.f;

    const int npairs = qi + 1;    // ntiles = 2*qi+2, always even

    for (int p = 0; p < npairs; p++) {
        CP_WAIT0();
        __syncthreads();
        if (p + 1 < npairs) load_pair((p + 1) & 1, p + 1);

        #pragma unroll
        for (int sub = 0; sub < 2; sub++) {
            const int kt = 2 * p + sub;
            const bool skip = (kt * 64) > (q0 + w * 16 + 15);
            if (skip) continue;

            const uint32_t sa = sb + (p & 1) * AT_STAGE + sub * AT_SUB;
            const int tile = lane >> 3, rin = lane & 7;

            float s[8][4];
            #pragma unroll
            for (int j = 0; j < 8; j++)
                #pragma unroll
                for (int e = 0; e < 4; e++) s[j][e] = 0.f;

            #pragma unroll
            for (int g = 0; g < 4; g++) {
                uint32_t bh[8][2], bl[8][2];
                #pragma unroll
                for (int pp = 0; pp < 4; pp++) {
                    int row = 16 * pp + (tile >> 1) * 8 + rin;
                    int ch  = 2 * g + (tile & 1);
                    uint32_t off = sw128((uint32_t)(row * 128 + ch * 16));
                    uint32_t r0, r1, r2, r3;
                    LDSM4(r0, r1, r2, r3, sa + off);
                    bh[2*pp][0] = r0; bh[2*pp][1] = r1;
                    bh[2*pp+1][0] = r2; bh[2*pp+1][1] = r3;
                    LDSM4(r0, r1, r2, r3, sa + 8192 + off);
                    bl[2*pp][0] = r0; bl[2*pp][1] = r1;
                    bl[2*pp+1][0] = r2; bl[2*pp+1][1] = r3;
                }
                #pragma unroll
                for (int j = 0; j < 8; j++) {
                    MMA16816(s[j], Aqh[g], bh[j]);
                    MMA16816(s[j], Aqh[g], bl[j]);
                    MMA16816(s[j], Aql[g], bh[j]);
                }
            }

            const int gr0 = q0 + w * 16 + (lane >> 2);
            if (kt * 64 + 63 > q0 + w * 16) {
                #pragma unroll
                for (int j = 0; j < 8; j++) {
                    int col = kt * 64 + j * 8 + 2 * (lane & 3);
                    if (col     > gr0)     s[j][0] = -1e30f;
                    if (col + 1 > gr0)     s[j][1] = -1e30f;
                    if (col     > gr0 + 8) s[j][2] = -1e30f;
                    if (col + 1 > gr0 + 8) s[j][3] = -1e30f;
                }
            }

            float mx0 = -1e30f, mx1 = -1e30f;
            #pragma unroll
            for (int j = 0; j < 8; j++) {
                mx0 = fmaxf(mx0, fmaxf(s[j][0], s[j][1]));
                mx1 = fmaxf(mx1, fmaxf(s[j][2], s[j][3]));
            }
            mx0 = fmaxf(mx0, __shfl_xor_sync(0xffffffffu, mx0, 1));
            mx0 = fmaxf(mx0, __shfl_xor_sync(0xffffffffu, mx0, 2));
            mx1 = fmaxf(mx1, __shfl_xor_sync(0xffffffffu, mx1, 1));
            mx1 = fmaxf(mx1, __shfl_xor_sync(0xffffffffu, mx1, 2));

            float mn0 = fmaxf(m0r, mx0), mn1 = fmaxf(m1r, mx1);
            float c0 = __expf(m0r - mn0), c1 = __expf(m1r - mn1);
            float sum0 = 0.f, sum1 = 0.f;
            #pragma unroll
            for (int j = 0; j < 8; j++) {
                s[j][0] = __expf(s[j][0] - mn0);
                s[j][1] = __expf(s[j][1] - mn0);
                s[j][2] = __expf(s[j][2] - mn1);
                s[j][3] = __expf(s[j][3] - mn1);
                sum0 += s[j][0] + s[j][1];
                sum1 += s[j][2] + s[j][3];
            }
            sum0 += __shfl_xor_sync(0xffffffffu, sum0, 1);
            sum0 += __shfl_xor_sync(0xffffffffu, sum0, 2);
            sum1 += __shfl_xor_sync(0xffffffffu, sum1, 1);
            sum1 += __shfl_xor_sync(0xffffffffu, sum1, 2);
            m0r = mn0; m1r = mn1;
            l0r = l0r * c0 + sum0;
            l1r = l1r * c1 + sum1;

            uint32_t Aph[4][4], Apl[4][4];
            #pragma unroll
            for (int g = 0; g < 4; g++) {
                split2(s[2*g][0],   s[2*g][1],   Aph[g][0], Apl[g][0]);
                split2(s[2*g][2],   s[2*g][3],   Aph[g][1], Apl[g][1]);
                split2(s[2*g+1][0], s[2*g+1][1], Aph[g][2], Apl[g][2]);
                split2(s[2*g+1][2], s[2*g+1][3], Aph[g][3], Apl[g][3]);
            }

            #pragma unroll
            for (int j = 0; j < 8; j++) {
                o[j][0] *= c0; o[j][1] *= c0;
                o[j][2] *= c1; o[j][3] *= c1;
            }

            #pragma unroll
            for (int g = 0; g < 4; g++) {
                uint32_t bvh[8][2], bvl[8][2];
                #pragma unroll
                for (int pp = 0; pp < 4; pp++) {
                    int row = 16 * g + (tile & 1) * 8 + rin;
                    int ch  = 2 * pp + (tile >> 1);
                    uint32_t off = sw128((uint32_t)(row * 128 + ch * 16));
                    uint32_t r0, r1, r2, r3;
                    LDSM4T(r0, r1, r2, r3, sa + 16384 + off);
                    bvh[2*pp][0] = r0; bvh[2*pp][1] = r1;
                    bvh[2*pp+1][0] = r2; bvh[2*pp+1][1] = r3;
                    LDSM4T(r0, r1, r2, r3, sa + 24576 + off);
                    bvl[2*pp][0] = r0; bvl[2*pp][1] = r1;
                    bvl[2*pp+1][0] = r2; bvl[2*pp+1][1] = r3;
                }
                #pragma unroll
                for (int j = 0; j < 8; j++) {
                    MMA16816(o[j], Aph[g], bvh[j]);
                    MMA16816(o[j], Aph[g], bvl[j]);
                    MMA16816(o[j], Apl[g], bvh[j]);
                }
            }
        }
        // no trailing sync: next pair's top sync protects stage reuse
    }

    const float inv0 = 1.f / l0r, inv1 = 1.f / l1r;
    const int gr0 = q0 + w * 16 + (lane >> 2);
    float* base = attn_out + (((size_t)b * NHH + h) * TT) * DHH;
    #pragma unroll
    for (int j = 0; j < 8; j++) {
        int col = j * 8 + 2 * (lane & 3);
        float2 v0, v1;
        v0.x = o[j][0] * inv0; v0.y = o[j][1] * inv0;
        v1.x = o[j][2] * inv1; v1.y = o[j][3] * inv1;
        *(float2*)(base + (size_t)gr0 * DHH + col)       = v0;
        *(float2*)(base + (size_t)(gr0 + 8) * DHH + col) = v1;
    }
}

// ---------------------------------------------------------------------------
// Head-mean pooling fused with bf16 hi/lo split output
// ---------------------------------------------------------------------------
__global__ __launch_bounds__(256) void head_mean_split(
    const float* __restrict__ attn, __nv_bfloat16* __restrict__ mh,
    __nv_bfloat16* __restrict__ ml)
{
    int idx = blockIdx.x * blockDim.x + threadIdx.x;
    int d4 = idx & 15;
    int bt = idx >> 4;
    int b  = bt / TT;
    int t  = bt % TT;
    float4 acc = make_float4(0.f, 0.f, 0.f, 0.f);
    #pragma unroll
    for (int h = 0; h < NHH; h++) {
        float4 vv = *(const float4*)&attn[(((size_t)b*NHH + h)*TT + t)*DHH + d4*4];
        acc.x += vv.x; acc.y += vv.y; acc.z += vv.z; acc.w += vv.w;
    }
    const float inv = 1.f / (float)NHH;
    uint32_t h01, l01, h23, l23;
    split2(acc.x * inv, acc.y * inv, h01, l01);
    split2(acc.z * inv, acc.w * inv, h23, l23);
    size_t o = (size_t)bt * DHH + d4 * 4;
    *(uint32_t*)(mh + o)     = h01;
    *(uint32_t*)(mh + o + 2) = h23;
    *(uint32_t*)(ml + o)     = l01;
    *(uint32_t*)(ml + o + 2) = l23;
}

// ---------------------------------------------------------------------------
extern "C" void kernel_launch(void* const* d_in, const int* in_sizes, int n_in,
                              void* d_out, int out_size)
{
    const float* x  = (const float*)d_in[0];
    const float* Wq = (const float*)d_in[1];
    const float* bq = (const float*)d_in[2];
    const float* Wk = (const float*)d_in[3];
    const float* bk = (const float*)d_in[4];
    const float* Wv = (const float*)d_in[5];
    const float* bv = (const float*)d_in[6];
    const float* Wo = (const float*)d_in[7];

    float* out  = (float*)d_out;                      // [32,512,1024]
    float* attn = out + (size_t)MTOT * HH;            // [32,16,512,64]

    float *qbuf, *kbuf, *vbuf, *mbuf;
    __nv_bfloat16 *xh, *xl, *wth, *wtl, *wtoh, *wtol;
    cudaGetSymbolAddress((void**)&qbuf, g_q);
    cudaGetSymbolAddress((void**)&kbuf, g_k);
    cudaGetSymbolAddress((void**)&vbuf, g_v);
    cudaGetSymbolAddress((void**)&mbuf, g_m);
    cudaGetSymbolAddress((void**)&xh, g_xh);
    cudaGetSymbolAddress((void**)&xl, g_xl);
    cudaGetSymbolAddress((void**)&wth, g_wth);
    cudaGetSymbolAddress((void**)&wtl, g_wtl);
    cudaGetSymbolAddress((void**)&wtoh, g_wtoh);
    cudaGetSymbolAddress((void**)&wtol, g_wtol);

    __nv_bfloat16* qh = (__nv_bfloat16*)qbuf;
    __nv_bfloat16* ql = qh + (size_t)MTOT * HH;
    __nv_bfloat16* kh = (__nv_bfloat16*)kbuf;
    __nv_bfloat16* kl = kh + (size_t)MTOT * HH;
    __nv_bfloat16* vh = (__nv_bfloat16*)vbuf;
    __nv_bfloat16* vl = vh + (size_t)MTOT * DHH;
    __nv_bfloat16* mh = (__nv_bfloat16*)mbuf;
    __nv_bfloat16* ml = mh + (size_t)MTOT * DHH;

    cudaFuncSetAttribute(qkv_gemm, cudaFuncAttributeMaxDynamicSharedMemorySize,
                         QK_SMEM);
    cudaFuncSetAttribute(attn_mma, cudaFuncAttributeMaxDynamicSharedMemorySize,
                         AT_SMEM);
    cudaFuncSetAttribute(out_gemm, cudaFuncAttributeMaxDynamicSharedMemorySize,
                         OG_SMEM);

    dim3 blk(256);

    // bf16 splits of x and all weights
    convert_x<<<dim3(((size_t)MTOT*HH/4)/256), blk>>>(x, xh, xl);
    tsplit<<<dim3(32, 32), blk>>>(Wq, wth, wtl, HH, HH);
    tsplit<<<dim3(32, 32), blk>>>(Wk, wth + (size_t)HH*HH, wtl + (size_t)HH*HH,
                                  HH, HH);
    tsplit<<<dim3(2, 32),  blk>>>(Wv, wth + (size_t)2*HH*HH,
                                  wtl + (size_t)2*HH*HH, HH, 64);
    tsplit<<<dim3(32, 2),  blk>>>(Wo, wtoh, wtol, 64, HH);

    // Q+K+V projections (tensor, 3-pass) -> bf16 splits (Q pre-scaled 1/8)
    qkv_gemm<<<dim3(17, MTOT/128), blk, QK_SMEM>>>(xh, xl, wth, wtl,
                                                   bq, bk, bv,
                                                   qh, ql, kh, kl, vh, vl);

    // Tensor-core causal attention -> attn_vec (fp32)
    attn_mma<<<dim3(TT/128, NHH, BSZ), blk, AT_SMEM>>>(qh, ql, kh, kl,
                                                       vh, vl, attn);

    // Head mean (+split) and O projection (tensor, 3-pass)
    head_mean_split<<<dim3((MTOT * (DHH/4)) / 256), blk>>>(attn, mh, ml);
    out_gemm<<<dim3(8, MTOT/128), blk, OG_SMEM>>>(mh, ml, wtoh, wtol, out);
}

// round 7
// speedup vs baseline: 3.3779x; 1.0960x over previous
#include <cuda_runtime.h>
#include <cuda_bf16.h>
#include <cuda_fp16.h>
#include <math.h>
#include <stdint.h>

#define BSZ 32
#define TT  512
#define HH  1024
#define DHH 64
#define NHH 16
#define MTOT (BSZ*TT)   // 16384

// ---------------------------------------------------------------------------
// Scratch (device globals: allocation-free contract)
// ---------------------------------------------------------------------------
__device__ float g_q[(size_t)MTOT * HH];             // 64 MB -> qh|ql splits
__device__ float g_k[(size_t)MTOT * HH];             // 64 MB -> kh|kl
__device__ float g_v[(size_t)MTOT * DHH];            //  4 MB -> vf (fp16)
__device__ float g_m[(size_t)MTOT * DHH];            //  4 MB -> mh|ml splits
__device__ __nv_bfloat16 g_xh[(size_t)MTOT * HH];    // 32 MB
__device__ __nv_bfloat16 g_xl[(size_t)MTOT * HH];    // 32 MB
// Wq^T (1024 rows) | Wk^T (1024 rows) | Wv^T (64 rows), all stride HH
__device__ __nv_bfloat16 g_wth[(size_t)2 * HH * HH + 64 * HH];
__device__ __nv_bfloat16 g_wtl[(size_t)2 * HH * HH + 64 * HH];
// Wo^T: 1024 rows x 64 cols
__device__ __nv_bfloat16 g_wtoh[(size_t)HH * 64];
__device__ __nv_bfloat16 g_wtol[(size_t)HH * 64];

// ---------------------------------------------------------------------------
// Baseline-ISA PTX helpers
// ---------------------------------------------------------------------------
__device__ __forceinline__ uint32_t su32(const void* p) {
    uint32_t a;
    asm("{ .reg .u64 t; cvta.to.shared.u64 t, %1; cvt.u32.u64 %0, t; }"
        : "=r"(a) : "l"(p));
    return a;
}
#define CP16(dst, src) \
    asm volatile("cp.async.cg.shared.global [%0], [%1], 16;" \
                 :: "r"(dst), "l"(src))
#define CP_COMMIT() asm volatile("cp.async.commit_group;" ::: "memory")
#define CP_WAIT1()  asm volatile("cp.async.wait_group 1;" ::: "memory")
#define CP_WAIT0()  asm volatile("cp.async.wait_group 0;" ::: "memory")
#define LDSM4(r0, r1, r2, r3, addr) \
    asm volatile("ldmatrix.sync.aligned.m8n8.x4.shared.b16 {%0,%1,%2,%3}, [%4];" \
                 : "=r"(r0), "=r"(r1), "=r"(r2), "=r"(r3) : "r"(addr))
#define LDSM4T(r0, r1, r2, r3, addr) \
    asm volatile("ldmatrix.sync.aligned.m8n8.x4.trans.shared.b16 {%0,%1,%2,%3}, [%4];" \
                 : "=r"(r0), "=r"(r1), "=r"(r2), "=r"(r3) : "r"(addr))
#define MMA16816(d, a, b) \
    asm volatile("mma.sync.aligned.m16n8k16.row.col.f32.bf16.bf16.f32 " \
                 "{%0,%1,%2,%3}, {%4,%5,%6,%7}, {%8,%9}, {%0,%1,%2,%3};" \
                 : "+f"((d)[0]), "+f"((d)[1]), "+f"((d)[2]), "+f"((d)[3]) \
                 : "r"((a)[0]), "r"((a)[1]), "r"((a)[2]), "r"((a)[3]), \
                   "r"((b)[0]), "r"((b)[1]))
#define MMAF16(d, a, b) \
    asm volatile("mma.sync.aligned.m16n8k16.row.col.f32.f16.f16.f32 " \
                 "{%0,%1,%2,%3}, {%4,%5,%6,%7}, {%8,%9}, {%0,%1,%2,%3};" \
                 : "+f"((d)[0]), "+f"((d)[1]), "+f"((d)[2]), "+f"((d)[3]) \
                 : "r"((a)[0]), "r"((a)[1]), "r"((a)[2]), "r"((a)[3]), \
                   "r"((b)[0]), "r"((b)[1]))

__device__ __forceinline__ uint32_t sw128(uint32_t off) {
    return off ^ ((off >> 3) & 0x70u);
}
__device__ __forceinline__ void split2(float a, float b,
                                       uint32_t& hi, uint32_t& lo) {
    __nv_bfloat162 h = __floats2bfloat162_rn(a, b);
    float ra = a - __bfloat162float(h.x);
    float rb = b - __bfloat162float(h.y);
    __nv_bfloat162 l = __floats2bfloat162_rn(ra, rb);
    hi = *(uint32_t*)&h;
    lo = *(uint32_t*)&l;
}
__device__ __forceinline__ uint32_t pack_h2(float a, float b) {
    __half2 h = __floats2half2_rn(a, b);
    return *(uint32_t*)&h;
}

// ---------------------------------------------------------------------------
// Split fp32 -> bf16 hi + bf16 lo
// ---------------------------------------------------------------------------
__global__ __launch_bounds__(256) void convert_x(
    const float* __restrict__ x, __nv_bfloat16* __restrict__ xh,
    __nv_bfloat16* __restrict__ xl)
{
    size_t i = ((size_t)blockIdx.x * blockDim.x + threadIdx.x) * 4;
    float4 v = *(const float4*)(x + i);
    uint32_t h0, l0, h1, l1;
    split2(v.x, v.y, h0, l0);
    split2(v.z, v.w, h1, l1);
    *(uint32_t*)(xh + i)     = h0;
    *(uint32_t*)(xh + i + 2) = h1;
    *(uint32_t*)(xl + i)     = l0;
    *(uint32_t*)(xl + i + 2) = l1;
}

// ---------------------------------------------------------------------------
// Generic transpose + split: src[R][C] fp32 -> dst[C][R] bf16 hi/lo
// ---------------------------------------------------------------------------
__global__ __launch_bounds__(256) void tsplit(
    const float* __restrict__ src, __nv_bfloat16* __restrict__ dh,
    __nv_bfloat16* __restrict__ dl, int R, int C)
{
    __shared__ float t[32][33];
    int c0 = blockIdx.x * 32, r0 = blockIdx.y * 32;
    int tx = threadIdx.x & 31, ty = threadIdx.x >> 5;
    #pragma unroll
    for (int j = 0; j < 4; j++)
        t[ty + j*8][tx] = src[(size_t)(r0 + ty + j*8) * C + c0 + tx];
    __syncthreads();
    #pragma unroll
    for (int j = 0; j < 4; j++) {
        int ro = c0 + ty + j*8;
        int co = r0 + tx;
        float v = t[tx][ty + j*8];
        __nv_bfloat16 h = __float2bfloat16(v);
        dh[(size_t)ro * R + co] = h;
        dl[(size_t)ro * R + co] = __float2bfloat16(v - __bfloat162float(h));
    }
}

// ---------------------------------------------------------------------------
// Fused Q+K+V projection: mma.sync bf16, 3-pass compensated split.
// Q/K -> bf16 hi/lo splits (Q pre-scaled 1/8); V -> fp16 single.
// ---------------------------------------------------------------------------
#define QK_STAGE 65536
#define QK_SMEM  (3 * QK_STAGE)

__global__ __launch_bounds__(256, 1) void qkv_gemm(
    const __nv_bfloat16* __restrict__ xh, const __nv_bfloat16* __restrict__ xl,
    const __nv_bfloat16* __restrict__ wth, const __nv_bfloat16* __restrict__ wtl,
    const float* __restrict__ bq, const float* __restrict__ bk,
    const float* __restrict__ bv,
    __nv_bfloat16* __restrict__ qh, __nv_bfloat16* __restrict__ ql,
    __nv_bfloat16* __restrict__ kh, __nv_bfloat16* __restrict__ kl,
    __half* __restrict__ vf)
{
    extern __shared__ char smem[];
    const uint32_t sb = su32(smem);
    const int tid = threadIdx.x;
    const int lane = tid & 31;
    const int wid = tid >> 5;
    const int warp_m = wid & 3;
    const int warp_n = wid >> 2;

    const int ntile = blockIdx.x;
    const int which = ntile >> 3;        // 0=Q, 1=K, 2=V
    const int n0 = (ntile & 7) * 128;
    const int m0 = blockIdx.y * 128;

    const __nv_bfloat16* wbh = wth + (size_t)which * HH * HH;
    const __nv_bfloat16* wbl = wtl + (size_t)which * HH * HH;

    float c[2][8][4];
    #pragma unroll
    for (int tm = 0; tm < 2; tm++)
        #pragma unroll
        for (int j = 0; j < 8; j++)
            #pragma unroll
            for (int r = 0; r < 4; r++) c[tm][j][r] = 0.f;

    auto load_stage = [&](int stage, int k0) {
        const uint32_t sa = sb + stage * QK_STAGE;
        #pragma unroll
        for (int i = 0; i < 4; i++) {
            int s = tid + (i << 8);
            int r = s >> 3, ch = s & 7;
            uint32_t off = sw128((uint32_t)(r * 128 + ch * 16));
            const size_t ga = (size_t)(m0 + r) * HH + k0 + ch * 8;
            const int br = (which == 2) ? (r & 63) : r;
            const size_t gb = (size_t)(n0 + br) * HH + k0 + ch * 8;
            CP16(sa + off,         xh + ga);
            CP16(sa + 16384 + off, xl + ga);
            CP16(sa + 32768 + off, wbh + gb);
            CP16(sa + 49152 + off, wbl + gb);
        }
        CP_COMMIT();
    };

    load_stage(0, 0);
    load_stage(1, 64);

    for (int cch = 0; cch < 16; cch++) {
        if (cch + 2 < 16) CP_WAIT1(); else CP_WAIT0();
        __syncthreads();
        if (cch + 2 < 16) load_stage((cch + 2) % 3, (cch + 2) * 64);

        const uint32_t sa = sb + (cch % 3) * QK_STAGE;
        #pragma unroll
        for (int kk = 0; kk < 4; kk++) {
            const int kc0 = kk * 2;
            uint32_t ah[2][4], al[2][4];
            {
                const int mat = lane >> 3, rin = lane & 7;
                #pragma unroll
                for (int tm = 0; tm < 2; tm++) {
                    int row = warp_m * 32 + tm * 16 + (mat & 1) * 8 + rin;
                    int ch  = kc0 + (mat >> 1);
                    uint32_t off = sw128((uint32_t)(row * 128 + ch * 16));
                    LDSM4(ah[tm][0], ah[tm][1], ah[tm][2], ah[tm][3], sa + off);
                    LDSM4(al[tm][0], al[tm][1], al[tm][2], al[tm][3],
                          sa + 16384 + off);
                }
            }
            uint32_t bh[8][2], bl[8][2];
            {
                const int mat = lane >> 3, rin = lane & 7;
                #pragma unroll
                for (int jp = 0; jp < 4; jp++) {
                    int grp = jp * 2 + (mat >> 1);
                    int ch  = kc0 + (mat & 1);
                    int row = warp_n * 64 + grp * 8 + rin;
                    uint32_t off = sw128((uint32_t)(row * 128 + ch * 16));
                    uint32_t r0, r1, r2, r3;
                    LDSM4(r0, r1, r2, r3, sa + 32768 + off);
                    bh[jp*2][0] = r0; bh[jp*2][1] = r1;
                    bh[jp*2+1][0] = r2; bh[jp*2+1][1] = r3;
                    LDSM4(r0, r1, r2, r3, sa + 49152 + off);
                    bl[jp*2][0] = r0; bl[jp*2][1] = r1;
                    bl[jp*2+1][0] = r2; bl[jp*2+1][1] = r3;
                }
            }
            #pragma unroll
            for (int tm = 0; tm < 2; tm++)
                #pragma unroll
                for (int j = 0; j < 8; j++) {
                    MMA16816(c[tm][j], ah[tm], bh[j]);
                    MMA16816(c[tm][j], ah[tm], bl[j]);
                    MMA16816(c[tm][j], al[tm], bh[j]);
                }
        }
    }

    // ---- epilogue ----
    if (which == 2) {
        // V: fp16 single, only first 64 cols (warp_n == 0)
        if (warp_n == 0) {
            #pragma unroll
            for (int tm = 0; tm < 2; tm++) {
                #pragma unroll
                for (int j = 0; j < 8; j++) {
                    int gnl = j * 8 + 2 * (lane & 3);
                    float2 bv2 = *(const float2*)&bv[gnl];
                    int gm0 = m0 + warp_m * 32 + tm * 16 + (lane >> 2);
                    uint32_t p0 = pack_h2(c[tm][j][0] + bv2.x,
                                          c[tm][j][1] + bv2.y);
                    uint32_t p1 = pack_h2(c[tm][j][2] + bv2.x,
                                          c[tm][j][3] + bv2.y);
                    *(uint32_t*)(vf + (size_t)gm0 * 64 + gnl)       = p0;
                    *(uint32_t*)(vf + (size_t)(gm0 + 8) * 64 + gnl) = p1;
                }
            }
        }
        return;
    }

    const float scale = (which == 0) ? 0.125f : 1.0f;
    const float* bias = (which == 0) ? bq : bk;
    __nv_bfloat16* oh = (which == 0) ? qh : kh;
    __nv_bfloat16* ol = (which == 0) ? ql : kl;

    #pragma unroll
    for (int tm = 0; tm < 2; tm++) {
        #pragma unroll
        for (int j = 0; j < 8; j++) {
            int gnl = warp_n * 64 + j * 8 + 2 * (lane & 3);
            float2 bv2 = *(const float2*)&bias[n0 + gnl];
            int gm0 = m0 + warp_m * 32 + tm * 16 + (lane >> 2);
            float v0 = (c[tm][j][0] + bv2.x) * scale;
            float v1 = (c[tm][j][1] + bv2.y) * scale;
            float v2 = (c[tm][j][2] + bv2.x) * scale;
            float v3 = (c[tm][j][3] + bv2.y) * scale;
            uint32_t h01, l01, h23, l23;
            split2(v0, v1, h01, l01);
            split2(v2, v3, h23, l23);
            size_t a0 = (size_t)gm0 * HH + n0 + gnl;
            size_t a1 = (size_t)(gm0 + 8) * HH + n0 + gnl;
            *(uint32_t*)(oh + a0) = h01;
            *(uint32_t*)(ol + a0) = l01;
            *(uint32_t*)(oh + a1) = h23;
            *(uint32_t*)(ol + a1) = l23;
        }
    }
}

// ---------------------------------------------------------------------------
// O projection: out[M,1024] = m[M,64] @ Wo[64,1024], bf16 3-pass mma, K=64.
// ---------------------------------------------------------------------------
#define OG_SMEM 65536

__global__ __launch_bounds__(256) void out_gemm(
    const __nv_bfloat16* __restrict__ mh, const __nv_bfloat16* __restrict__ ml,
    const __nv_bfloat16* __restrict__ wtoh, const __nv_bfloat16* __restrict__ wtol,
    float* __restrict__ out)
{
    extern __shared__ char smem[];
    const uint32_t sb = su32(smem);
    const int tid = threadIdx.x;
    const int lane = tid & 31;
    const int wid = tid >> 5;
    const int warp_m = wid & 3;
    const int warp_n = wid >> 2;
    const int n0 = blockIdx.x * 128;
    const int m0 = blockIdx.y * 128;

    #pragma unroll
    for (int i = 0; i < 4; i++) {
        int s = tid + (i << 8);
        int r = s >> 3, ch = s & 7;
        uint32_t off = sw128((uint32_t)(r * 128 + ch * 16));
        const size_t ga = (size_t)(m0 + r) * 64 + ch * 8;
        const size_t gb = (size_t)(n0 + r) * 64 + ch * 8;
        CP16(sb + off,         mh + ga);
        CP16(sb + 16384 + off, ml + ga);
        CP16(sb + 32768 + off, wtoh + gb);
        CP16(sb + 49152 + off, wtol + gb);
    }
    CP_COMMIT();
    CP_WAIT0();
    __syncthreads();

    float c[2][8][4];
    #pragma unroll
    for (int tm = 0; tm < 2; tm++)
        #pragma unroll
        for (int j = 0; j < 8; j++)
            #pragma unroll
            for (int r = 0; r < 4; r++) c[tm][j][r] = 0.f;

    #pragma unroll
    for (int kk = 0; kk < 4; kk++) {
        const int kc0 = kk * 2;
        uint32_t ah[2][4], al[2][4];
        {
            const int mat = lane >> 3, rin = lane & 7;
            #pragma unroll
            for (int tm = 0; tm < 2; tm++) {
                int row = warp_m * 32 + tm * 16 + (mat & 1) * 8 + rin;
                int ch  = kc0 + (mat >> 1);
                uint32_t off = sw128((uint32_t)(row * 128 + ch * 16));
                LDSM4(ah[tm][0], ah[tm][1], ah[tm][2], ah[tm][3], sb + off);
                LDSM4(al[tm][0], al[tm][1], al[tm][2], al[tm][3],
                      sb + 16384 + off);
            }
        }
        uint32_t bh[8][2], bl[8][2];
        {
            const int mat = lane >> 3, rin = lane & 7;
            #pragma unroll
            for (int jp = 0; jp < 4; jp++) {
                int grp = jp * 2 + (mat >> 1);
                int ch  = kc0 + (mat & 1);
                int row = warp_n * 64 + grp * 8 + rin;
                uint32_t off = sw128((uint32_t)(row * 128 + ch * 16));
                uint32_t r0, r1, r2, r3;
                LDSM4(r0, r1, r2, r3, sb + 32768 + off);
                bh[jp*2][0] = r0; bh[jp*2][1] = r1;
                bh[jp*2+1][0] = r2; bh[jp*2+1][1] = r3;
                LDSM4(r0, r1, r2, r3, sb + 49152 + off);
                bl[jp*2][0] = r0; bl[jp*2][1] = r1;
                bl[jp*2+1][0] = r2; bl[jp*2+1][1] = r3;
            }
        }
        #pragma unroll
        for (int tm = 0; tm < 2; tm++)
            #pragma unroll
            for (int j = 0; j < 8; j++) {
                MMA16816(c[tm][j], ah[tm], bh[j]);
                MMA16816(c[tm][j], ah[tm], bl[j]);
                MMA16816(c[tm][j], al[tm], bh[j]);
            }
    }

    #pragma unroll
    for (int tm = 0; tm < 2; tm++) {
        #pragma unroll
        for (int j = 0; j < 8; j++) {
            int gn = n0 + warp_n * 64 + j * 8 + 2 * (lane & 3);
            int gm0 = m0 + warp_m * 32 + tm * 16 + (lane >> 2);
            float2 o0, o1;
            o0.x = c[tm][j][0]; o0.y = c[tm][j][1];
            o1.x = c[tm][j][2]; o1.y = c[tm][j][3];
            *(float2*)&out[(size_t)gm0 * HH + gn]       = o0;
            *(float2*)&out[(size_t)(gm0 + 8) * HH + gn] = o1;
        }
    }
}

// ---------------------------------------------------------------------------
// Tensor-core causal flash attention.
// S = Q@K^T: 3-pass bf16. P@V: single-pass fp16 (P,V fp16).
// SMEM: 2 stages x [2 subtiles x (Kh 8K | Kl 8K | Vf 8K)] + 32KB Q staging.
// Longest-first qi ordering.
// ---------------------------------------------------------------------------
#define AT_SUB   24576
#define AT_STAGE (2 * AT_SUB)
#define AT_SMEM  (2 * AT_STAGE + 32768)   // 131072

__global__ __launch_bounds__(256) void attn_mma(
    const __nv_bfloat16* __restrict__ qh, const __nv_bfloat16* __restrict__ ql,
    const __nv_bfloat16* __restrict__ kh, const __nv_bfloat16* __restrict__ kl,
    const __half* __restrict__ vf,
    float* __restrict__ attn_out)
{
    extern __shared__ char smem[];
    const uint32_t sb = su32(smem);
    const uint32_t qb = sb + 2 * AT_STAGE;
    const int tid = threadIdx.x;
    const int lane = tid & 31;
    const int w = tid >> 5;

    const int b  = blockIdx.z;
    const int h  = blockIdx.y;
    const int qi = (TT / 128 - 1) - blockIdx.x;   // longest CTAs first
    const int q0 = qi * 128;

    // stage Q tile (hi/lo)
    #pragma unroll
    for (int i = 0; i < 4; i++) {
        int idx = tid + (i << 8);
        int r = idx >> 3, ch = idx & 7;
        uint32_t off = sw128((uint32_t)(r * 128 + ch * 16));
        size_t g = (size_t)(b * TT + q0 + r) * HH + h * 64 + ch * 8;
        CP16(qb + off,         qh + g);
        CP16(qb + 16384 + off, ql + g);
    }
    CP_COMMIT();

    // pair loader: 128 K rows (hi/lo) + 128 V rows (fp16) into one stage
    auto load_pair = [&](int stg, int p) {
        const uint32_t sa = sb + stg * AT_STAGE;
        const size_t rowb = (size_t)(b * TT + p * 128);
        #pragma unroll
        for (int i = 0; i < 4; i++) {
            int idx = tid + (i << 8);
            int r = idx >> 3, ch = idx & 7;
            uint32_t sub = (uint32_t)(r >> 6) * AT_SUB;
            uint32_t off = sub + sw128((uint32_t)((r & 63) * 128 + ch * 16));
            size_t gk = (rowb + r) * HH + h * 64 + ch * 8;
            size_t gv = (rowb + r) * 64 + ch * 8;
            CP16(sa + off,         kh + gk);
            CP16(sa + 8192 + off,  kl + gk);
            CP16(sa + 16384 + off, vf + gv);
        }
        CP_COMMIT();
    };

    load_pair(0, 0);

    // Q complete (pair0 may still be pending)
    CP_WAIT1();
    __syncthreads();

    uint32_t Aqh[4][4], Aql[4][4];
    {
        const int tile = lane >> 3, rin = lane & 7;
        #pragma unroll
        for (int g = 0; g < 4; g++) {
            int row = w * 16 + (tile & 1) * 8 + rin;
            int ch  = 2 * g + (tile >> 1);
            uint32_t off = sw128((uint32_t)(row * 128 + ch * 16));
            LDSM4(Aqh[g][0], Aqh[g][1], Aqh[g][2], Aqh[g][3], qb + off);
            LDSM4(Aql[g][0], Aql[g][1], Aql[g][2], Aql[g][3], qb + 16384 + off);
        }
    }

    float m0r = -1e30f, m1r = -1e30f, l0r = 0.f, l1r = 0.f;
    float o[8][4];
    #pragma unroll
    for (int j = 0; j < 8; j++)
        #pragma unroll
        for (int e = 0; e < 4; e++) o[j][e] = 0.f;

    const int npairs = qi + 1;

    for (int p = 0; p < npairs; p++) {
        CP_WAIT0();
        __syncthreads();
        if (p + 1 < npairs) load_pair((p + 1) & 1, p + 1);

        #pragma unroll
        for (int sub = 0; sub < 2; sub++) {
            const int kt = 2 * p + sub;
            const bool skip = (kt * 64) > (q0 + w * 16 + 15);
            if (skip) continue;

            const uint32_t sa = sb + (p & 1) * AT_STAGE + sub * AT_SUB;
            const int tile = lane >> 3, rin = lane & 7;

            float s[8][4];
            #pragma unroll
            for (int j = 0; j < 8; j++)
                #pragma unroll
                for (int e = 0; e < 4; e++) s[j][e] = 0.f;

            #pragma unroll
            for (int g = 0; g < 4; g++) {
                uint32_t bh[8][2], bl[8][2];
                #pragma unroll
                for (int pp = 0; pp < 4; pp++) {
                    int row = 16 * pp + (tile >> 1) * 8 + rin;
                    int ch  = 2 * g + (tile & 1);
                    uint32_t off = sw128((uint32_t)(row * 128 + ch * 16));
                    uint32_t r0, r1, r2, r3;
                    LDSM4(r0, r1, r2, r3, sa + off);
                    bh[2*pp][0] = r0; bh[2*pp][1] = r1;
                    bh[2*pp+1][0] = r2; bh[2*pp+1][1] = r3;
                    LDSM4(r0, r1, r2, r3, sa + 8192 + off);
                    bl[2*pp][0] = r0; bl[2*pp][1] = r1;
                    bl[2*pp+1][0] = r2; bl[2*pp+1][1] = r3;
                }
                #pragma unroll
                for (int j = 0; j < 8; j++) {
                    MMA16816(s[j], Aqh[g], bh[j]);
                    MMA16816(s[j], Aqh[g], bl[j]);
                    MMA16816(s[j], Aql[g], bh[j]);
                }
            }

            const int gr0 = q0 + w * 16 + (lane >> 2);
            if (kt * 64 + 63 > q0 + w * 16) {
                #pragma unroll
                for (int j = 0; j < 8; j++) {
                    int col = kt * 64 + j * 8 + 2 * (lane & 3);
                    if (col     > gr0)     s[j][0] = -1e30f;
                    if (col + 1 > gr0)     s[j][1] = -1e30f;
                    if (col     > gr0 + 8) s[j][2] = -1e30f;
                    if (col + 1 > gr0 + 8) s[j][3] = -1e30f;
                }
            }

            float mx0 = -1e30f, mx1 = -1e30f;
            #pragma unroll
            for (int j = 0; j < 8; j++) {
                mx0 = fmaxf(mx0, fmaxf(s[j][0], s[j][1]));
                mx1 = fmaxf(mx1, fmaxf(s[j][2], s[j][3]));
            }
            mx0 = fmaxf(mx0, __shfl_xor_sync(0xffffffffu, mx0, 1));
            mx0 = fmaxf(mx0, __shfl_xor_sync(0xffffffffu, mx0, 2));
            mx1 = fmaxf(mx1, __shfl_xor_sync(0xffffffffu, mx1, 1));
            mx1 = fmaxf(mx1, __shfl_xor_sync(0xffffffffu, mx1, 2));

            float mn0 = fmaxf(m0r, mx0), mn1 = fmaxf(m1r, mx1);
            float c0 = __expf(m0r - mn0), c1 = __expf(m1r - mn1);
            float sum0 = 0.f, sum1 = 0.f;
            #pragma unroll
            for (int j = 0; j < 8; j++) {
                s[j][0] = __expf(s[j][0] - mn0);
                s[j][1] = __expf(s[j][1] - mn0);
                s[j][2] = __expf(s[j][2] - mn1);
                s[j][3] = __expf(s[j][3] - mn1);
                sum0 += s[j][0] + s[j][1];
                sum1 += s[j][2] + s[j][3];
            }
            sum0 += __shfl_xor_sync(0xffffffffu, sum0, 1);
            sum0 += __shfl_xor_sync(0xffffffffu, sum0, 2);
            sum1 += __shfl_xor_sync(0xffffffffu, sum1, 1);
            sum1 += __shfl_xor_sync(0xffffffffu, sum1, 2);
            m0r = mn0; m1r = mn1;
            l0r = l0r * c0 + sum0;
            l1r = l1r * c1 + sum1;

            // pack P into fp16 A fragments (single precision pass)
            uint32_t Apf[4][4];
            #pragma unroll
            for (int g = 0; g < 4; g++) {
                Apf[g][0] = pack_h2(s[2*g][0],   s[2*g][1]);
                Apf[g][1] = pack_h2(s[2*g][2],   s[2*g][3]);
                Apf[g][2] = pack_h2(s[2*g+1][0], s[2*g+1][1]);
                Apf[g][3] = pack_h2(s[2*g+1][2], s[2*g+1][3]);
            }

            #pragma unroll
            for (int j = 0; j < 8; j++) {
                o[j][0] *= c0; o[j][1] *= c0;
                o[j][2] *= c1; o[j][3] *= c1;
            }

            // O += P @ V (fp16 single pass; V^T via ldmatrix.trans)
            #pragma unroll
            for (int g = 0; g < 4; g++) {
                uint32_t bvf[8][2];
                #pragma unroll
                for (int pp = 0; pp < 4; pp++) {
                    int row = 16 * g + (tile & 1) * 8 + rin;
                    int ch  = 2 * pp + (tile >> 1);
                    uint32_t off = sw128((uint32_t)(row * 128 + ch * 16));
                    uint32_t r0, r1, r2, r3;
                    LDSM4T(r0, r1, r2, r3, sa + 16384 + off);
                    bvf[2*pp][0] = r0; bvf[2*pp][1] = r1;
                    bvf[2*pp+1][0] = r2; bvf[2*pp+1][1] = r3;
                }
                #pragma unroll
                for (int j = 0; j < 8; j++)
                    MMAF16(o[j], Apf[g], bvf[j]);
            }
        }
    }

    const float inv0 = 1.f / l0r, inv1 = 1.f / l1r;
    const int gr0 = q0 + w * 16 + (lane >> 2);
    float* base = attn_out + (((size_t)b * NHH + h) * TT) * DHH;
    #pragma unroll
    for (int j = 0; j < 8; j++) {
        int col = j * 8 + 2 * (lane & 3);
        float2 v0, v1;
        v0.x = o[j][0] * inv0; v0.y = o[j][1] * inv0;
        v1.x = o[j][2] * inv1; v1.y = o[j][3] * inv1;
        *(float2*)(base + (size_t)gr0 * DHH + col)       = v0;
        *(float2*)(base + (size_t)(gr0 + 8) * DHH + col) = v1;
    }
}

// ---------------------------------------------------------------------------
// Head-mean pooling fused with bf16 hi/lo split output
// ---------------------------------------------------------------------------
__global__ __launch_bounds__(256) void head_mean_split(
    const float* __restrict__ attn, __nv_bfloat16* __restrict__ mh,
    __nv_bfloat16* __restrict__ ml)
{
    int idx = blockIdx.x * blockDim.x + threadIdx.x;
    int d4 = idx & 15;
    int bt = idx >> 4;
    int b  = bt / TT;
    int t  = bt % TT;
    float4 acc = make_float4(0.f, 0.f, 0.f, 0.f);
    #pragma unroll
    for (int h = 0; h < NHH; h++) {
        float4 vv = *(const float4*)&attn[(((size_t)b*NHH + h)*TT + t)*DHH + d4*4];
        acc.x += vv.x; acc.y += vv.y; acc.z += vv.z; acc.w += vv.w;
    }
    const float inv = 1.f / (float)NHH;
    uint32_t h01, l01, h23, l23;
    split2(acc.x * inv, acc.y * inv, h01, l01);
    split2(acc.z * inv, acc.w * inv, h23, l23);
    size_t o = (size_t)bt * DHH + d4 * 4;
    *(uint32_t*)(mh + o)     = h01;
    *(uint32_t*)(mh + o + 2) = h23;
    *(uint32_t*)(ml + o)     = l01;
    *(uint32_t*)(ml + o + 2) = l23;
}

// ---------------------------------------------------------------------------
extern "C" void kernel_launch(void* const* d_in, const int* in_sizes, int n_in,
                              void* d_out, int out_size)
{
    const float* x  = (const float*)d_in[0];
    const float* Wq = (const float*)d_in[1];
    const float* bq = (const float*)d_in[2];
    const float* Wk = (const float*)d_in[3];
    const float* bk = (const float*)d_in[4];
    const float* Wv = (const float*)d_in[5];
    const float* bv = (const float*)d_in[6];
    const float* Wo = (const float*)d_in[7];

    float* out  = (float*)d_out;                      // [32,512,1024]
    float* attn = out + (size_t)MTOT * HH;            // [32,16,512,64]

    float *qbuf, *kbuf, *vbuf, *mbuf;
    __nv_bfloat16 *xh, *xl, *wth, *wtl, *wtoh, *wtol;
    cudaGetSymbolAddress((void**)&qbuf, g_q);
    cudaGetSymbolAddress((void**)&kbuf, g_k);
    cudaGetSymbolAddress((void**)&vbuf, g_v);
    cudaGetSymbolAddress((void**)&mbuf, g_m);
    cudaGetSymbolAddress((void**)&xh, g_xh);
    cudaGetSymbolAddress((void**)&xl, g_xl);
    cudaGetSymbolAddress((void**)&wth, g_wth);
    cudaGetSymbolAddress((void**)&wtl, g_wtl);
    cudaGetSymbolAddress((void**)&wtoh, g_wtoh);
    cudaGetSymbolAddress((void**)&wtol, g_wtol);

    __nv_bfloat16* qh = (__nv_bfloat16*)qbuf;
    __nv_bfloat16* ql = qh + (size_t)MTOT * HH;
    __nv_bfloat16* kh = (__nv_bfloat16*)kbuf;
    __nv_bfloat16* kl = kh + (size_t)MTOT * HH;
    __half* vf = (__half*)vbuf;
    __nv_bfloat16* mh = (__nv_bfloat16*)mbuf;
    __nv_bfloat16* ml = mh + (size_t)MTOT * DHH;

    cudaFuncSetAttribute(qkv_gemm, cudaFuncAttributeMaxDynamicSharedMemorySize,
                         QK_SMEM);
    cudaFuncSetAttribute(attn_mma, cudaFuncAttributeMaxDynamicSharedMemorySize,
                         AT_SMEM);
    cudaFuncSetAttribute(out_gemm, cudaFuncAttributeMaxDynamicSharedMemorySize,
                         OG_SMEM);

    dim3 blk(256);

    // bf16 splits of x and all weights
    convert_x<<<dim3(((size_t)MTOT*HH/4)/256), blk>>>(x, xh, xl);
    tsplit<<<dim3(32, 32), blk>>>(Wq, wth, wtl, HH, HH);
    tsplit<<<dim3(32, 32), blk>>>(Wk, wth + (size_t)HH*HH, wtl + (size_t)HH*HH,
                                  HH, HH);
    tsplit<<<dim3(2, 32),  blk>>>(Wv, wth + (size_t)2*HH*HH,
                                  wtl + (size_t)2*HH*HH, HH, 64);
    tsplit<<<dim3(32, 2),  blk>>>(Wo, wtoh, wtol, 64, HH);

    // Q+K+V projections (tensor, 3-pass); V emitted as fp16 single
    qkv_gemm<<<dim3(17, MTOT/128), blk, QK_SMEM>>>(xh, xl, wth, wtl,
                                                   bq, bk, bv,
                                                   qh, ql, kh, kl, vf);

    // Tensor-core causal attention -> attn_vec (fp32)
    attn_mma<<<dim3(TT/128, NHH, BSZ), blk, AT_SMEM>>>(qh, ql, kh, kl,
                                                       vf, attn);

    // Head mean (+split) and O projection (tensor, 3-pass)
    head_mean_split<<<dim3((MTOT * (DHH/4)) / 256), blk>>>(attn, mh, ml);
    out_gemm<<<dim3(8, MTOT/128), blk, OG_SMEM>>>(mh, ml, wtoh, wtol, out);
}

// round 8
// speedup vs baseline: 4.9319x; 1.4601x over previous
#include <cuda_runtime.h>
#include <cuda_bf16.h>
#include <cuda_fp16.h>
#include <math.h>
#include <stdint.h>

#define BSZ 32
#define TT  512
#define HH  1024
#define DHH 64
#define NHH 16
#define MTOT (BSZ*TT)   // 16384

// ---------------------------------------------------------------------------
// Scratch (device globals: allocation-free contract)
// ---------------------------------------------------------------------------
__device__ float g_q[(size_t)MTOT * HH];             // -> qf fp16 (32 MB used)
__device__ float g_k[(size_t)MTOT * HH];             // -> kf fp16
__device__ float g_v[(size_t)MTOT * DHH];            // -> vf fp16
__device__ float g_m[(size_t)MTOT * DHH];            // -> mh|ml bf16 splits
__device__ __nv_bfloat16 g_xh[(size_t)MTOT * HH];    // -> xf fp16 (32 MB)
// W^T fp16 hi/lo: Wq^T | Wk^T | Wv^T rows, stride HH
__device__ __nv_bfloat16 g_wth[(size_t)2 * HH * HH + 64 * HH];
__device__ __nv_bfloat16 g_wtl[(size_t)2 * HH * HH + 64 * HH];
// Wo^T: bf16 hi/lo (out proj stays 3-pass bf16)
__device__ __nv_bfloat16 g_wtoh[(size_t)HH * 64];
__device__ __nv_bfloat16 g_wtol[(size_t)HH * 64];

// ---------------------------------------------------------------------------
// Baseline-ISA PTX helpers
// ---------------------------------------------------------------------------
__device__ __forceinline__ uint32_t su32(const void* p) {
    uint32_t a;
    asm("{ .reg .u64 t; cvta.to.shared.u64 t, %1; cvt.u32.u64 %0, t; }"
        : "=r"(a) : "l"(p));
    return a;
}
#define CP16(dst, src) \
    asm volatile("cp.async.cg.shared.global [%0], [%1], 16;" \
                 :: "r"(dst), "l"(src))
#define CP_COMMIT() asm volatile("cp.async.commit_group;" ::: "memory")
#define CP_WAIT1()  asm volatile("cp.async.wait_group 1;" ::: "memory")
#define CP_WAIT0()  asm volatile("cp.async.wait_group 0;" ::: "memory")
#define LDSM4(r0, r1, r2, r3, addr) \
    asm volatile("ldmatrix.sync.aligned.m8n8.x4.shared.b16 {%0,%1,%2,%3}, [%4];" \
                 : "=r"(r0), "=r"(r1), "=r"(r2), "=r"(r3) : "r"(addr))
#define LDSM4T(r0, r1, r2, r3, addr) \
    asm volatile("ldmatrix.sync.aligned.m8n8.x4.trans.shared.b16 {%0,%1,%2,%3}, [%4];" \
                 : "=r"(r0), "=r"(r1), "=r"(r2), "=r"(r3) : "r"(addr))
#define MMA16816(d, a, b) \
    asm volatile("mma.sync.aligned.m16n8k16.row.col.f32.bf16.bf16.f32 " \
                 "{%0,%1,%2,%3}, {%4,%5,%6,%7}, {%8,%9}, {%0,%1,%2,%3};" \
                 : "+f"((d)[0]), "+f"((d)[1]), "+f"((d)[2]), "+f"((d)[3]) \
                 : "r"((a)[0]), "r"((a)[1]), "r"((a)[2]), "r"((a)[3]), \
                   "r"((b)[0]), "r"((b)[1]))
#define MMAF16(d, a, b) \
    asm volatile("mma.sync.aligned.m16n8k16.row.col.f32.f16.f16.f32 " \
                 "{%0,%1,%2,%3}, {%4,%5,%6,%7}, {%8,%9}, {%0,%1,%2,%3};" \
                 : "+f"((d)[0]), "+f"((d)[1]), "+f"((d)[2]), "+f"((d)[3]) \
                 : "r"((a)[0]), "r"((a)[1]), "r"((a)[2]), "r"((a)[3]), \
                   "r"((b)[0]), "r"((b)[1]))

__device__ __forceinline__ uint32_t sw128(uint32_t off) {
    return off ^ ((off >> 3) & 0x70u);
}
__device__ __forceinline__ void split2(float a, float b,
                                       uint32_t& hi, uint32_t& lo) {
    __nv_bfloat162 h = __floats2bfloat162_rn(a, b);
    float ra = a - __bfloat162float(h.x);
    float rb = b - __bfloat162float(h.y);
    __nv_bfloat162 l = __floats2bfloat162_rn(ra, rb);
    hi = *(uint32_t*)&h;
    lo = *(uint32_t*)&l;
}
__device__ __forceinline__ uint32_t pack_h2(float a, float b) {
    __half2 h = __floats2half2_rn(a, b);
    return *(uint32_t*)&h;
}

// ---------------------------------------------------------------------------
// fp32 -> fp16 single
// ---------------------------------------------------------------------------
__global__ __launch_bounds__(256) void convert_xh(
    const float* __restrict__ x, __half* __restrict__ xf)
{
    size_t i = ((size_t)blockIdx.x * blockDim.x + threadIdx.x) * 4;
    float4 v = *(const float4*)(x + i);
    *(uint32_t*)(xf + i)     = pack_h2(v.x, v.y);
    *(uint32_t*)(xf + i + 2) = pack_h2(v.z, v.w);
}

// ---------------------------------------------------------------------------
// Transpose + fp16 hi/lo split: src[R][C] fp32 -> dst[C][R]
// ---------------------------------------------------------------------------
__global__ __launch_bounds__(256) void tsplit_h(
    const float* __restrict__ src, __half* __restrict__ dh,
    __half* __restrict__ dl, int R, int C)
{
    __shared__ float t[32][33];
    int c0 = blockIdx.x * 32, r0 = blockIdx.y * 32;
    int tx = threadIdx.x & 31, ty = threadIdx.x >> 5;
    #pragma unroll
    for (int j = 0; j < 4; j++)
        t[ty + j*8][tx] = src[(size_t)(r0 + ty + j*8) * C + c0 + tx];
    __syncthreads();
    #pragma unroll
    for (int j = 0; j < 4; j++) {
        int ro = c0 + ty + j*8;
        int co = r0 + tx;
        float v = t[tx][ty + j*8];
        __half h = __float2half(v);
        dh[(size_t)ro * R + co] = h;
        dl[(size_t)ro * R + co] = __float2half(v - __half2float(h));
    }
}

// ---------------------------------------------------------------------------
// Transpose + bf16 hi/lo split (Wo only)
// ---------------------------------------------------------------------------
__global__ __launch_bounds__(256) void tsplit(
    const float* __restrict__ src, __nv_bfloat16* __restrict__ dh,
    __nv_bfloat16* __restrict__ dl, int R, int C)
{
    __shared__ float t[32][33];
    int c0 = blockIdx.x * 32, r0 = blockIdx.y * 32;
    int tx = threadIdx.x & 31, ty = threadIdx.x >> 5;
    #pragma unroll
    for (int j = 0; j < 4; j++)
        t[ty + j*8][tx] = src[(size_t)(r0 + ty + j*8) * C + c0 + tx];
    __syncthreads();
    #pragma unroll
    for (int j = 0; j < 4; j++) {
        int ro = c0 + ty + j*8;
        int co = r0 + tx;
        float v = t[tx][ty + j*8];
        __nv_bfloat16 h = __float2bfloat16(v);
        dh[(size_t)ro * R + co] = h;
        dl[(size_t)ro * R + co] = __float2bfloat16(v - __bfloat162float(h));
    }
}

// ---------------------------------------------------------------------------
// Fused Q+K+V projection: 2-pass fp16 (x fp16 single, W fp16 hi/lo).
// Outputs q,k,v as fp16 singles (Q pre-scaled 1/8).
// Stage: A 16K | Bh 16K | Bl 16K = 48 KB; 3 stages.
// ---------------------------------------------------------------------------
#define QK_STAGE 49152
#define QK_SMEM  (3 * QK_STAGE)

__global__ __launch_bounds__(256, 1) void qkv_gemm(
    const __half* __restrict__ xf,
    const __half* __restrict__ wfh, const __half* __restrict__ wfl,
    const float* __restrict__ bq, const float* __restrict__ bk,
    const float* __restrict__ bv,
    __half* __restrict__ qf, __half* __restrict__ kf,
    __half* __restrict__ vf)
{
    extern __shared__ char smem[];
    const uint32_t sb = su32(smem);
    const int tid = threadIdx.x;
    const int lane = tid & 31;
    const int wid = tid >> 5;
    const int warp_m = wid & 3;
    const int warp_n = wid >> 2;

    const int ntile = blockIdx.x;
    const int which = ntile >> 3;        // 0=Q, 1=K, 2=V
    const int n0 = (ntile & 7) * 128;
    const int m0 = blockIdx.y * 128;

    const __half* wbh = wfh + (size_t)which * HH * HH;
    const __half* wbl = wfl + (size_t)which * HH * HH;

    float c[2][8][4];
    #pragma unroll
    for (int tm = 0; tm < 2; tm++)
        #pragma unroll
        for (int j = 0; j < 8; j++)
            #pragma unroll
            for (int r = 0; r < 4; r++) c[tm][j][r] = 0.f;

    auto load_stage = [&](int stage, int k0) {
        const uint32_t sa = sb + stage * QK_STAGE;
        #pragma unroll
        for (int i = 0; i < 4; i++) {
            int s = tid + (i << 8);
            int r = s >> 3, ch = s & 7;
            uint32_t off = sw128((uint32_t)(r * 128 + ch * 16));
            const size_t ga = (size_t)(m0 + r) * HH + k0 + ch * 8;
            const int br = (which == 2) ? (r & 63) : r;
            const size_t gb = (size_t)(n0 + br) * HH + k0 + ch * 8;
            CP16(sa + off,         xf + ga);
            CP16(sa + 16384 + off, wbh + gb);
            CP16(sa + 32768 + off, wbl + gb);
        }
        CP_COMMIT();
    };

    load_stage(0, 0);
    load_stage(1, 64);

    for (int cch = 0; cch < 16; cch++) {
        if (cch + 2 < 16) CP_WAIT1(); else CP_WAIT0();
        __syncthreads();
        if (cch + 2 < 16) load_stage((cch + 2) % 3, (cch + 2) * 64);

        const uint32_t sa = sb + (cch % 3) * QK_STAGE;
        #pragma unroll
        for (int kk = 0; kk < 4; kk++) {
            const int kc0 = kk * 2;
            uint32_t af[2][4];
            {
                const int mat = lane >> 3, rin = lane & 7;
                #pragma unroll
                for (int tm = 0; tm < 2; tm++) {
                    int row = warp_m * 32 + tm * 16 + (mat & 1) * 8 + rin;
                    int ch  = kc0 + (mat >> 1);
                    uint32_t off = sw128((uint32_t)(row * 128 + ch * 16));
                    LDSM4(af[tm][0], af[tm][1], af[tm][2], af[tm][3], sa + off);
                }
            }
            uint32_t bh[8][2], bl[8][2];
            {
                const int mat = lane >> 3, rin = lane & 7;
                #pragma unroll
                for (int jp = 0; jp < 4; jp++) {
                    int grp = jp * 2 + (mat >> 1);
                    int ch  = kc0 + (mat & 1);
                    int row = warp_n * 64 + grp * 8 + rin;
                    uint32_t off = sw128((uint32_t)(row * 128 + ch * 16));
                    uint32_t r0, r1, r2, r3;
                    LDSM4(r0, r1, r2, r3, sa + 16384 + off);
                    bh[jp*2][0] = r0; bh[jp*2][1] = r1;
                    bh[jp*2+1][0] = r2; bh[jp*2+1][1] = r3;
                    LDSM4(r0, r1, r2, r3, sa + 32768 + off);
                    bl[jp*2][0] = r0; bl[jp*2][1] = r1;
                    bl[jp*2+1][0] = r2; bl[jp*2+1][1] = r3;
                }
            }
            #pragma unroll
            for (int tm = 0; tm < 2; tm++)
                #pragma unroll
                for (int j = 0; j < 8; j++) {
                    MMAF16(c[tm][j], af[tm], bh[j]);
                    MMAF16(c[tm][j], af[tm], bl[j]);
                }
        }
    }

    // ---- epilogue: fp16 single outputs ----
    if (which == 2) {
        if (warp_n == 0) {
            #pragma unroll
            for (int tm = 0; tm < 2; tm++) {
                #pragma unroll
                for (int j = 0; j < 8; j++) {
                    int gnl = j * 8 + 2 * (lane & 3);
                    float2 bv2 = *(const float2*)&bv[gnl];
                    int gm0 = m0 + warp_m * 32 + tm * 16 + (lane >> 2);
                    uint32_t p0 = pack_h2(c[tm][j][0] + bv2.x,
                                          c[tm][j][1] + bv2.y);
                    uint32_t p1 = pack_h2(c[tm][j][2] + bv2.x,
                                          c[tm][j][3] + bv2.y);
                    *(uint32_t*)(vf + (size_t)gm0 * 64 + gnl)       = p0;
                    *(uint32_t*)(vf + (size_t)(gm0 + 8) * 64 + gnl) = p1;
                }
            }
        }
        return;
    }

    const float scale = (which == 0) ? 0.125f : 1.0f;
    const float* bias = (which == 0) ? bq : bk;
    __half* of = (which == 0) ? qf : kf;

    #pragma unroll
    for (int tm = 0; tm < 2; tm++) {
        #pragma unroll
        for (int j = 0; j < 8; j++) {
            int gnl = warp_n * 64 + j * 8 + 2 * (lane & 3);
            float2 bv2 = *(const float2*)&bias[n0 + gnl];
            int gm0 = m0 + warp_m * 32 + tm * 16 + (lane >> 2);
            uint32_t p0 = pack_h2((c[tm][j][0] + bv2.x) * scale,
                                  (c[tm][j][1] + bv2.y) * scale);
            uint32_t p1 = pack_h2((c[tm][j][2] + bv2.x) * scale,
                                  (c[tm][j][3] + bv2.y) * scale);
            *(uint32_t*)(of + (size_t)gm0 * HH + n0 + gnl)       = p0;
            *(uint32_t*)(of + (size_t)(gm0 + 8) * HH + n0 + gnl) = p1;
        }
    }
}

// ---------------------------------------------------------------------------
// O projection: out[M,1024] = m[M,64] @ Wo[64,1024], bf16 3-pass mma, K=64.
// ---------------------------------------------------------------------------
#define OG_SMEM 65536

__global__ __launch_bounds__(256) void out_gemm(
    const __nv_bfloat16* __restrict__ mh, const __nv_bfloat16* __restrict__ ml,
    const __nv_bfloat16* __restrict__ wtoh, const __nv_bfloat16* __restrict__ wtol,
    float* __restrict__ out)
{
    extern __shared__ char smem[];
    const uint32_t sb = su32(smem);
    const int tid = threadIdx.x;
    const int lane = tid & 31;
    const int wid = tid >> 5;
    const int warp_m = wid & 3;
    const int warp_n = wid >> 2;
    const int n0 = blockIdx.x * 128;
    const int m0 = blockIdx.y * 128;

    #pragma unroll
    for (int i = 0; i < 4; i++) {
        int s = tid + (i << 8);
        int r = s >> 3, ch = s & 7;
        uint32_t off = sw128((uint32_t)(r * 128 + ch * 16));
        const size_t ga = (size_t)(m0 + r) * 64 + ch * 8;
        const size_t gb = (size_t)(n0 + r) * 64 + ch * 8;
        CP16(sb + off,         mh + ga);
        CP16(sb + 16384 + off, ml + ga);
        CP16(sb + 32768 + off, wtoh + gb);
        CP16(sb + 49152 + off, wtol + gb);
    }
    CP_COMMIT();
    CP_WAIT0();
    __syncthreads();

    float c[2][8][4];
    #pragma unroll
    for (int tm = 0; tm < 2; tm++)
        #pragma unroll
        for (int j = 0; j < 8; j++)
            #pragma unroll
            for (int r = 0; r < 4; r++) c[tm][j][r] = 0.f;

    #pragma unroll
    for (int kk = 0; kk < 4; kk++) {
        const int kc0 = kk * 2;
        uint32_t ah[2][4], al[2][4];
        {
            const int mat = lane >> 3, rin = lane & 7;
            #pragma unroll
            for (int tm = 0; tm < 2; tm++) {
                int row = warp_m * 32 + tm * 16 + (mat & 1) * 8 + rin;
                int ch  = kc0 + (mat >> 1);
                uint32_t off = sw128((uint32_t)(row * 128 + ch * 16));
                LDSM4(ah[tm][0], ah[tm][1], ah[tm][2], ah[tm][3], sb + off);
                LDSM4(al[tm][0], al[tm][1], al[tm][2], al[tm][3],
                      sb + 16384 + off);
            }
        }
        uint32_t bh[8][2], bl[8][2];
        {
            const int mat = lane >> 3, rin = lane & 7;
            #pragma unroll
            for (int jp = 0; jp < 4; jp++) {
                int grp = jp * 2 + (mat >> 1);
                int ch  = kc0 + (mat & 1);
                int row = warp_n * 64 + grp * 8 + rin;
                uint32_t off = sw128((uint32_t)(row * 128 + ch * 16));
                uint32_t r0, r1, r2, r3;
                LDSM4(r0, r1, r2, r3, sb + 32768 + off);
                bh[jp*2][0] = r0; bh[jp*2][1] = r1;
                bh[jp*2+1][0] = r2; bh[jp*2+1][1] = r3;
                LDSM4(r0, r1, r2, r3, sb + 49152 + off);
                bl[jp*2][0] = r0; bl[jp*2][1] = r1;
                bl[jp*2+1][0] = r2; bl[jp*2+1][1] = r3;
            }
        }
        #pragma unroll
        for (int tm = 0; tm < 2; tm++)
            #pragma unroll
            for (int j = 0; j < 8; j++) {
                MMA16816(c[tm][j], ah[tm], bh[j]);
                MMA16816(c[tm][j], ah[tm], bl[j]);
                MMA16816(c[tm][j], al[tm], bh[j]);
            }
    }

    #pragma unroll
    for (int tm = 0; tm < 2; tm++) {
        #pragma unroll
        for (int j = 0; j < 8; j++) {
            int gn = n0 + warp_n * 64 + j * 8 + 2 * (lane & 3);
            int gm0 = m0 + warp_m * 32 + tm * 16 + (lane >> 2);
            float2 o0, o1;
            o0.x = c[tm][j][0]; o0.y = c[tm][j][1];
            o1.x = c[tm][j][2]; o1.y = c[tm][j][3];
            *(float2*)&out[(size_t)gm0 * HH + gn]       = o0;
            *(float2*)&out[(size_t)(gm0 + 8) * HH + gn] = o1;
        }
    }
}

// ---------------------------------------------------------------------------
// Tensor-core causal flash attention — all fp16 single-pass.
// SMEM: 2 stages x [2 subtiles x (Kf 8K | Vf 8K)] + 16KB Q = 80 KB.
// ---------------------------------------------------------------------------
#define AT_SUB   16384
#define AT_STAGE (2 * AT_SUB)
#define AT_SMEM  (2 * AT_STAGE + 16384)   // 81920

__global__ __launch_bounds__(256) void attn_mma(
    const __half* __restrict__ qf, const __half* __restrict__ kf,
    const __half* __restrict__ vf,
    float* __restrict__ attn_out)
{
    extern __shared__ char smem[];
    const uint32_t sb = su32(smem);
    const uint32_t qb = sb + 2 * AT_STAGE;
    const int tid = threadIdx.x;
    const int lane = tid & 31;
    const int w = tid >> 5;

    const int b  = blockIdx.z;
    const int h  = blockIdx.y;
    const int qi = (TT / 128 - 1) - blockIdx.x;   // longest CTAs first
    const int q0 = qi * 128;

    // stage Q tile (fp16 single, 16 KB)
    #pragma unroll
    for (int i = 0; i < 4; i++) {
        int idx = tid + (i << 8);
        int r = idx >> 3, ch = idx & 7;
        uint32_t off = sw128((uint32_t)(r * 128 + ch * 16));
        size_t g = (size_t)(b * TT + q0 + r) * HH + h * 64 + ch * 8;
        CP16(qb + off, qf + g);
    }
    CP_COMMIT();

    // pair loader: 128 K rows + 128 V rows (fp16) into one stage
    auto load_pair = [&](int stg, int p) {
        const uint32_t sa = sb + stg * AT_STAGE;
        const size_t rowb = (size_t)(b * TT + p * 128);
        #pragma unroll
        for (int i = 0; i < 4; i++) {
            int idx = tid + (i << 8);
            int r = idx >> 3, ch = idx & 7;
            uint32_t sub = (uint32_t)(r >> 6) * AT_SUB;
            uint32_t off = sub + sw128((uint32_t)((r & 63) * 128 + ch * 16));
            size_t gk = (rowb + r) * HH + h * 64 + ch * 8;
            size_t gv = (rowb + r) * 64 + ch * 8;
            CP16(sa + off,        kf + gk);
            CP16(sa + 8192 + off, vf + gv);
        }
        CP_COMMIT();
    };

    load_pair(0, 0);

    CP_WAIT1();   // Q complete
    __syncthreads();

    uint32_t Aqf[4][4];
    {
        const int tile = lane >> 3, rin = lane & 7;
        #pragma unroll
        for (int g = 0; g < 4; g++) {
            int row = w * 16 + (tile & 1) * 8 + rin;
            int ch  = 2 * g + (tile >> 1);
            uint32_t off = sw128((uint32_t)(row * 128 + ch * 16));
            LDSM4(Aqf[g][0], Aqf[g][1], Aqf[g][2], Aqf[g][3], qb + off);
        }
    }

    float m0r = -1e30f, m1r = -1e30f, l0r = 0.f, l1r = 0.f;
    float o[8][4];
    #pragma unroll
    for (int j = 0; j < 8; j++)
        #pragma unroll
        for (int e = 0; e < 4; e++) o[j][e] = 0.f;

    const int npairs = qi + 1;

    for (int p = 0; p < npairs; p++) {
        CP_WAIT0();
        __syncthreads();
        if (p + 1 < npairs) load_pair((p + 1) & 1, p + 1);

        #pragma unroll
        for (int sub = 0; sub < 2; sub++) {
            const int kt = 2 * p + sub;
            const bool skip = (kt * 64) > (q0 + w * 16 + 15);
            if (skip) continue;

            const uint32_t sa = sb + (p & 1) * AT_STAGE + sub * AT_SUB;
            const int tile = lane >> 3, rin = lane & 7;

            // ---- S = Q @ K^T (fp16 single pass) ----
            float s[8][4];
            #pragma unroll
            for (int j = 0; j < 8; j++)
                #pragma unroll
                for (int e = 0; e < 4; e++) s[j][e] = 0.f;

            #pragma unroll
            for (int g = 0; g < 4; g++) {
                uint32_t bh[8][2];
                #pragma unroll
                for (int pp = 0; pp < 4; pp++) {
                    int row = 16 * pp + (tile >> 1) * 8 + rin;
                    int ch  = 2 * g + (tile & 1);
                    uint32_t off = sw128((uint32_t)(row * 128 + ch * 16));
                    uint32_t r0, r1, r2, r3;
                    LDSM4(r0, r1, r2, r3, sa + off);
                    bh[2*pp][0] = r0; bh[2*pp][1] = r1;
                    bh[2*pp+1][0] = r2; bh[2*pp+1][1] = r3;
                }
                #pragma unroll
                for (int j = 0; j < 8; j++)
                    MMAF16(s[j], Aqf[g], bh[j]);
            }

            const int gr0 = q0 + w * 16 + (lane >> 2);
            if (kt * 64 + 63 > q0 + w * 16) {
                #pragma unroll
                for (int j = 0; j < 8; j++) {
                    int col = kt * 64 + j * 8 + 2 * (lane & 3);
                    if (col     > gr0)     s[j][0] = -1e30f;
                    if (col + 1 > gr0)     s[j][1] = -1e30f;
                    if (col     > gr0 + 8) s[j][2] = -1e30f;
                    if (col + 1 > gr0 + 8) s[j][3] = -1e30f;
                }
            }

            float mx0 = -1e30f, mx1 = -1e30f;
            #pragma unroll
            for (int j = 0; j < 8; j++) {
                mx0 = fmaxf(mx0, fmaxf(s[j][0], s[j][1]));
                mx1 = fmaxf(mx1, fmaxf(s[j][2], s[j][3]));
            }
            mx0 = fmaxf(mx0, __shfl_xor_sync(0xffffffffu, mx0, 1));
            mx0 = fmaxf(mx0, __shfl_xor_sync(0xffffffffu, mx0, 2));
            mx1 = fmaxf(mx1, __shfl_xor_sync(0xffffffffu, mx1, 1));
            mx1 = fmaxf(mx1, __shfl_xor_sync(0xffffffffu, mx1, 2));

            float mn0 = fmaxf(m0r, mx0), mn1 = fmaxf(m1r, mx1);
            float c0 = __expf(m0r - mn0), c1 = __expf(m1r - mn1);
            float sum0 = 0.f, sum1 = 0.f;
            #pragma unroll
            for (int j = 0; j < 8; j++) {
                s[j][0] = __expf(s[j][0] - mn0);
                s[j][1] = __expf(s[j][1] - mn0);
                s[j][2] = __expf(s[j][2] - mn1);
                s[j][3] = __expf(s[j][3] - mn1);
                sum0 += s[j][0] + s[j][1];
                sum1 += s[j][2] + s[j][3];
            }
            sum0 += __shfl_xor_sync(0xffffffffu, sum0, 1);
            sum0 += __shfl_xor_sync(0xffffffffu, sum0, 2);
            sum1 += __shfl_xor_sync(0xffffffffu, sum1, 1);
            sum1 += __shfl_xor_sync(0xffffffffu, sum1, 2);
            m0r = mn0; m1r = mn1;
            l0r = l0r * c0 + sum0;
            l1r = l1r * c1 + sum1;

            // pack P into fp16 A fragments
            uint32_t Apf[4][4];
            #pragma unroll
            for (int g = 0; g < 4; g++) {
                Apf[g][0] = pack_h2(s[2*g][0],   s[2*g][1]);
                Apf[g][1] = pack_h2(s[2*g][2],   s[2*g][3]);
                Apf[g][2] = pack_h2(s[2*g+1][0], s[2*g+1][1]);
                Apf[g][3] = pack_h2(s[2*g+1][2], s[2*g+1][3]);
            }

            #pragma unroll
            for (int j = 0; j < 8; j++) {
                o[j][0] *= c0; o[j][1] *= c0;
                o[j][2] *= c1; o[j][3] *= c1;
            }

            // ---- O += P @ V (fp16 single pass) ----
            #pragma unroll
            for (int g = 0; g < 4; g++) {
                uint32_t bvf[8][2];
                #pragma unroll
                for (int pp = 0; pp < 4; pp++) {
                    int row = 16 * g + (tile & 1) * 8 + rin;
                    int ch  = 2 * pp + (tile >> 1);
                    uint32_t off = sw128((uint32_t)(row * 128 + ch * 16));
                    uint32_t r0, r1, r2, r3;
                    LDSM4T(r0, r1, r2, r3, sa + 8192 + off);
                    bvf[2*pp][0] = r0; bvf[2*pp][1] = r1;
                    bvf[2*pp+1][0] = r2; bvf[2*pp+1][1] = r3;
                }
                #pragma unroll
                for (int j = 0; j < 8; j++)
                    MMAF16(o[j], Apf[g], bvf[j]);
            }
        }
    }

    const float inv0 = 1.f / l0r, inv1 = 1.f / l1r;
    const int gr0 = q0 + w * 16 + (lane >> 2);
    float* base = attn_out + (((size_t)b * NHH + h) * TT) * DHH;
    #pragma unroll
    for (int j = 0; j < 8; j++) {
        int col = j * 8 + 2 * (lane & 3);
        float2 v0, v1;
        v0.x = o[j][0] * inv0; v0.y = o[j][1] * inv0;
        v1.x = o[j][2] * inv1; v1.y = o[j][3] * inv1;
        *(float2*)(base + (size_t)gr0 * DHH + col)       = v0;
        *(float2*)(base + (size_t)(gr0 + 8) * DHH + col) = v1;
    }
}

// ---------------------------------------------------------------------------
// Head-mean pooling fused with bf16 hi/lo split output
// ---------------------------------------------------------------------------
__global__ __launch_bounds__(256) void head_mean_split(
    const float* __restrict__ attn, __nv_bfloat16* __restrict__ mh,
    __nv_bfloat16* __restrict__ ml)
{
    int idx = blockIdx.x * blockDim.x + threadIdx.x;
    int d4 = idx & 15;
    int bt = idx >> 4;
    int b  = bt / TT;
    int t  = bt % TT;
    float4 acc = make_float4(0.f, 0.f, 0.f, 0.f);
    #pragma unroll
    for (int h = 0; h < NHH; h++) {
        float4 vv = *(const float4*)&attn[(((size_t)b*NHH + h)*TT + t)*DHH + d4*4];
        acc.x += vv.x; acc.y += vv.y; acc.z += vv.z; acc.w += vv.w;
    }
    const float inv = 1.f / (float)NHH;
    uint32_t h01, l01, h23, l23;
    split2(acc.x * inv, acc.y * inv, h01, l01);
    split2(acc.z * inv, acc.w * inv, h23, l23);
    size_t o = (size_t)bt * DHH + d4 * 4;
    *(uint32_t*)(mh + o)     = h01;
    *(uint32_t*)(mh + o + 2) = h23;
    *(uint32_t*)(ml + o)     = l01;
    *(uint32_t*)(ml + o + 2) = l23;
}

// ---------------------------------------------------------------------------
extern "C" void kernel_launch(void* const* d_in, const int* in_sizes, int n_in,
                              void* d_out, int out_size)
{
    const float* x  = (const float*)d_in[0];
    const float* Wq = (const float*)d_in[1];
    const float* bq = (const float*)d_in[2];
    const float* Wk = (const float*)d_in[3];
    const float* bk = (const float*)d_in[4];
    const float* Wv = (const float*)d_in[5];
    const float* bv = (const float*)d_in[6];
    const float* Wo = (const float*)d_in[7];

    float* out  = (float*)d_out;                      // [32,512,1024]
    float* attn = out + (size_t)MTOT * HH;            // [32,16,512,64]

    float *qbuf, *kbuf, *vbuf, *mbuf;
    __nv_bfloat16 *xbuf, *wthb, *wtlb, *wtoh, *wtol;
    cudaGetSymbolAddress((void**)&qbuf, g_q);
    cudaGetSymbolAddress((void**)&kbuf, g_k);
    cudaGetSymbolAddress((void**)&vbuf, g_v);
    cudaGetSymbolAddress((void**)&mbuf, g_m);
    cudaGetSymbolAddress((void**)&xbuf, g_xh);
    cudaGetSymbolAddress((void**)&wthb, g_wth);
    cudaGetSymbolAddress((void**)&wtlb, g_wtl);
    cudaGetSymbolAddress((void**)&wtoh, g_wtoh);
    cudaGetSymbolAddress((void**)&wtol, g_wtol);

    __half* qf  = (__half*)qbuf;
    __half* kf  = (__half*)kbuf;
    __half* vf  = (__half*)vbuf;
    __half* xf  = (__half*)xbuf;
    __half* wfh = (__half*)wthb;
    __half* wfl = (__half*)wtlb;
    __nv_bfloat16* mh = (__nv_bfloat16*)mbuf;
    __nv_bfloat16* ml = mh + (size_t)MTOT * DHH;

    cudaFuncSetAttribute(qkv_gemm, cudaFuncAttributeMaxDynamicSharedMemorySize,
                         QK_SMEM);
    cudaFuncSetAttribute(attn_mma, cudaFuncAttributeMaxDynamicSharedMemorySize,
                         AT_SMEM);
    cudaFuncSetAttribute(out_gemm, cudaFuncAttributeMaxDynamicSharedMemorySize,
                         OG_SMEM);

    dim3 blk(256);

    // fp16 conversions
    convert_xh<<<dim3(((size_t)MTOT*HH/4)/256), blk>>>(x, xf);
    tsplit_h<<<dim3(32, 32), blk>>>(Wq, wfh, wfl, HH, HH);
    tsplit_h<<<dim3(32, 32), blk>>>(Wk, wfh + (size_t)HH*HH,
                                    wfl + (size_t)HH*HH, HH, HH);
    tsplit_h<<<dim3(2, 32),  blk>>>(Wv, wfh + (size_t)2*HH*HH,
                                    wfl + (size_t)2*HH*HH, HH, 64);
    tsplit<<<dim3(32, 2),  blk>>>(Wo, wtoh, wtol, 64, HH);

    // Q+K+V projections (fp16 2-pass) -> fp16 singles (Q pre-scaled 1/8)
    qkv_gemm<<<dim3(17, MTOT/128), blk, QK_SMEM>>>(xf, wfh, wfl,
                                                   bq, bk, bv, qf, kf, vf);

    // Tensor-core causal attention (fp16 single-pass) -> attn_vec (fp32)
    attn_mma<<<dim3(TT/128, NHH, BSZ), blk, AT_SMEM>>>(qf, kf, vf, attn);

    // Head mean (+bf16 split) and O projection (bf16 3-pass)
    head_mean_split<<<dim3((MTOT * (DHH/4)) / 256), blk>>>(attn, mh, ml);
    out_gemm<<<dim3(8, MTOT/128), blk, OG_SMEM>>>(mh, ml, wtoh, wtol, out);
}

// round 9
// speedup vs baseline: 6.8578x; 1.3905x over previous
#include <cuda_runtime.h>
#include <cuda_bf16.h>
#include <cuda_fp16.h>
#include <math.h>
#include <stdint.h>

#define BSZ 32
#define TT  512
#define HH  1024
#define DHH 64
#define NHH 16
#define MTOT (BSZ*TT)   // 16384

// ---------------------------------------------------------------------------
// Scratch (device globals: allocation-free contract)
// ---------------------------------------------------------------------------
__device__ float g_q[(size_t)MTOT * HH];             // -> qf fp16
__device__ float g_k[(size_t)MTOT * HH];             // -> kf fp16
__device__ float g_v[(size_t)MTOT * DHH];            // -> vf fp16
__device__ float g_m[(size_t)MTOT * DHH];            // -> mh|ml bf16 splits
__device__ __nv_bfloat16 g_xh[(size_t)MTOT * HH];    // -> xf fp16
// W^T fp16 single: Wq^T | Wk^T | Wv^T rows, stride HH
__device__ __nv_bfloat16 g_wth[(size_t)2 * HH * HH + 64 * HH];
// Wo^T: bf16 hi/lo (out proj stays 3-pass bf16)
__device__ __nv_bfloat16 g_wtoh[(size_t)HH * 64];
__device__ __nv_bfloat16 g_wtol[(size_t)HH * 64];

// ---------------------------------------------------------------------------
// Baseline-ISA PTX helpers
// ---------------------------------------------------------------------------
__device__ __forceinline__ uint32_t su32(const void* p) {
    uint32_t a;
    asm("{ .reg .u64 t; cvta.to.shared.u64 t, %1; cvt.u32.u64 %0, t; }"
        : "=r"(a) : "l"(p));
    return a;
}
#define CP16(dst, src) \
    asm volatile("cp.async.cg.shared.global [%0], [%1], 16;" \
                 :: "r"(dst), "l"(src))
#define CP_COMMIT() asm volatile("cp.async.commit_group;" ::: "memory")
#define CP_WAIT1()  asm volatile("cp.async.wait_group 1;" ::: "memory")
#define CP_WAIT0()  asm volatile("cp.async.wait_group 0;" ::: "memory")
#define LDSM4(r0, r1, r2, r3, addr) \
    asm volatile("ldmatrix.sync.aligned.m8n8.x4.shared.b16 {%0,%1,%2,%3}, [%4];" \
                 : "=r"(r0), "=r"(r1), "=r"(r2), "=r"(r3) : "r"(addr))
#define LDSM4T(r0, r1, r2, r3, addr) \
    asm volatile("ldmatrix.sync.aligned.m8n8.x4.trans.shared.b16 {%0,%1,%2,%3}, [%4];" \
                 : "=r"(r0), "=r"(r1), "=r"(r2), "=r"(r3) : "r"(addr))
#define MMA16816(d, a, b) \
    asm volatile("mma.sync.aligned.m16n8k16.row.col.f32.bf16.bf16.f32 " \
                 "{%0,%1,%2,%3}, {%4,%5,%6,%7}, {%8,%9}, {%0,%1,%2,%3};" \
                 : "+f"((d)[0]), "+f"((d)[1]), "+f"((d)[2]), "+f"((d)[3]) \
                 : "r"((a)[0]), "r"((a)[1]), "r"((a)[2]), "r"((a)[3]), \
                   "r"((b)[0]), "r"((b)[1]))
#define MMAF16(d, a, b) \
    asm volatile("mma.sync.aligned.m16n8k16.row.col.f32.f16.f16.f32 " \
                 "{%0,%1,%2,%3}, {%4,%5,%6,%7}, {%8,%9}, {%0,%1,%2,%3};" \
                 : "+f"((d)[0]), "+f"((d)[1]), "+f"((d)[2]), "+f"((d)[3]) \
                 : "r"((a)[0]), "r"((a)[1]), "r"((a)[2]), "r"((a)[3]), \
                   "r"((b)[0]), "r"((b)[1]))

__device__ __forceinline__ uint32_t sw128(uint32_t off) {
    return off ^ ((off >> 3) & 0x70u);
}
__device__ __forceinline__ void split2(float a, float b,
                                       uint32_t& hi, uint32_t& lo) {
    __nv_bfloat162 h = __floats2bfloat162_rn(a, b);
    float ra = a - __bfloat162float(h.x);
    float rb = b - __bfloat162float(h.y);
    __nv_bfloat162 l = __floats2bfloat162_rn(ra, rb);
    hi = *(uint32_t*)&h;
    lo = *(uint32_t*)&l;
}
__device__ __forceinline__ uint32_t pack_h2(float a, float b) {
    __half2 h = __floats2half2_rn(a, b);
    return *(uint32_t*)&h;
}

// ---------------------------------------------------------------------------
// fp32 -> fp16 single
// ---------------------------------------------------------------------------
__global__ __launch_bounds__(256) void convert_xh(
    const float* __restrict__ x, __half* __restrict__ xf)
{
    size_t i = ((size_t)blockIdx.x * blockDim.x + threadIdx.x) * 4;
    float4 v = *(const float4*)(x + i);
    *(uint32_t*)(xf + i)     = pack_h2(v.x, v.y);
    *(uint32_t*)(xf + i + 2) = pack_h2(v.z, v.w);
}

// ---------------------------------------------------------------------------
// Transpose to fp16 single: src[R][C] fp32 -> dst[C][R]
// ---------------------------------------------------------------------------
__global__ __launch_bounds__(256) void tconv_h(
    const float* __restrict__ src, __half* __restrict__ d, int R, int C)
{
    __shared__ float t[32][33];
    int c0 = blockIdx.x * 32, r0 = blockIdx.y * 32;
    int tx = threadIdx.x & 31, ty = threadIdx.x >> 5;
    #pragma unroll
    for (int j = 0; j < 4; j++)
        t[ty + j*8][tx] = src[(size_t)(r0 + ty + j*8) * C + c0 + tx];
    __syncthreads();
    #pragma unroll
    for (int j = 0; j < 4; j++) {
        int ro = c0 + ty + j*8;
        int co = r0 + tx;
        d[(size_t)ro * R + co] = __float2half(t[tx][ty + j*8]);
    }
}

// ---------------------------------------------------------------------------
// Transpose + bf16 hi/lo split (Wo only)
// ---------------------------------------------------------------------------
__global__ __launch_bounds__(256) void tsplit(
    const float* __restrict__ src, __nv_bfloat16* __restrict__ dh,
    __nv_bfloat16* __restrict__ dl, int R, int C)
{
    __shared__ float t[32][33];
    int c0 = blockIdx.x * 32, r0 = blockIdx.y * 32;
    int tx = threadIdx.x & 31, ty = threadIdx.x >> 5;
    #pragma unroll
    for (int j = 0; j < 4; j++)
        t[ty + j*8][tx] = src[(size_t)(r0 + ty + j*8) * C + c0 + tx];
    __syncthreads();
    #pragma unroll
    for (int j = 0; j < 4; j++) {
        int ro = c0 + ty + j*8;
        int co = r0 + tx;
        float v = t[tx][ty + j*8];
        __nv_bfloat16 h = __float2bfloat16(v);
        dh[(size_t)ro * R + co] = h;
        dl[(size_t)ro * R + co] = __float2bfloat16(v - __bfloat162float(h));
    }
}

// ---------------------------------------------------------------------------
// Fused Q+K+V projection: single-pass fp16 mma.
// Outputs q,k,v as fp16 singles (Q pre-scaled 1/8).
// Stage: A 16K | B 16K = 32 KB; 3 stages.
// ---------------------------------------------------------------------------
#define QK_STAGE 32768
#define QK_SMEM  (3 * QK_STAGE)

__global__ __launch_bounds__(256, 1) void qkv_gemm(
    const __half* __restrict__ xf, const __half* __restrict__ wf,
    const float* __restrict__ bq, const float* __restrict__ bk,
    const float* __restrict__ bv,
    __half* __restrict__ qf, __half* __restrict__ kf,
    __half* __restrict__ vf)
{
    extern __shared__ char smem[];
    const uint32_t sb = su32(smem);
    const int tid = threadIdx.x;
    const int lane = tid & 31;
    const int wid = tid >> 5;
    const int warp_m = wid & 3;
    const int warp_n = wid >> 2;

    const int ntile = blockIdx.x;
    const int which = ntile >> 3;        // 0=Q, 1=K, 2=V
    const int n0 = (ntile & 7) * 128;
    const int m0 = blockIdx.y * 128;

    const __half* wb = wf + (size_t)which * HH * HH;

    float c[2][8][4];
    #pragma unroll
    for (int tm = 0; tm < 2; tm++)
        #pragma unroll
        for (int j = 0; j < 8; j++)
            #pragma unroll
            for (int r = 0; r < 4; r++) c[tm][j][r] = 0.f;

    auto load_stage = [&](int stage, int k0) {
        const uint32_t sa = sb + stage * QK_STAGE;
        #pragma unroll
        for (int i = 0; i < 4; i++) {
            int s = tid + (i << 8);
            int r = s >> 3, ch = s & 7;
            uint32_t off = sw128((uint32_t)(r * 128 + ch * 16));
            const size_t ga = (size_t)(m0 + r) * HH + k0 + ch * 8;
            const int br = (which == 2) ? (r & 63) : r;
            const size_t gb = (size_t)(n0 + br) * HH + k0 + ch * 8;
            CP16(sa + off,         xf + ga);
            CP16(sa + 16384 + off, wb + gb);
        }
        CP_COMMIT();
    };

    load_stage(0, 0);
    load_stage(1, 64);

    for (int cch = 0; cch < 16; cch++) {
        if (cch + 2 < 16) CP_WAIT1(); else CP_WAIT0();
        __syncthreads();
        if (cch + 2 < 16) load_stage((cch + 2) % 3, (cch + 2) * 64);

        const uint32_t sa = sb + (cch % 3) * QK_STAGE;
        #pragma unroll
        for (int kk = 0; kk < 4; kk++) {
            const int kc0 = kk * 2;
            uint32_t af[2][4];
            {
                const int mat = lane >> 3, rin = lane & 7;
                #pragma unroll
                for (int tm = 0; tm < 2; tm++) {
                    int row = warp_m * 32 + tm * 16 + (mat & 1) * 8 + rin;
                    int ch  = kc0 + (mat >> 1);
                    uint32_t off = sw128((uint32_t)(row * 128 + ch * 16));
                    LDSM4(af[tm][0], af[tm][1], af[tm][2], af[tm][3], sa + off);
                }
            }
            uint32_t bf[8][2];
            {
                const int mat = lane >> 3, rin = lane & 7;
                #pragma unroll
                for (int jp = 0; jp < 4; jp++) {
                    int grp = jp * 2 + (mat >> 1);
                    int ch  = kc0 + (mat & 1);
                    int row = warp_n * 64 + grp * 8 + rin;
                    uint32_t off = sw128((uint32_t)(row * 128 + ch * 16));
                    uint32_t r0, r1, r2, r3;
                    LDSM4(r0, r1, r2, r3, sa + 16384 + off);
                    bf[jp*2][0] = r0; bf[jp*2][1] = r1;
                    bf[jp*2+1][0] = r2; bf[jp*2+1][1] = r3;
                }
            }
            #pragma unroll
            for (int tm = 0; tm < 2; tm++)
                #pragma unroll
                for (int j = 0; j < 8; j++)
                    MMAF16(c[tm][j], af[tm], bf[j]);
        }
    }

    // ---- epilogue: fp16 single outputs ----
    if (which == 2) {
        if (warp_n == 0) {
            #pragma unroll
            for (int tm = 0; tm < 2; tm++) {
                #pragma unroll
                for (int j = 0; j < 8; j++) {
                    int gnl = j * 8 + 2 * (lane & 3);
                    float2 bv2 = *(const float2*)&bv[gnl];
                    int gm0 = m0 + warp_m * 32 + tm * 16 + (lane >> 2);
                    uint32_t p0 = pack_h2(c[tm][j][0] + bv2.x,
                                          c[tm][j][1] + bv2.y);
                    uint32_t p1 = pack_h2(c[tm][j][2] + bv2.x,
                                          c[tm][j][3] + bv2.y);
                    *(uint32_t*)(vf + (size_t)gm0 * 64 + gnl)       = p0;
                    *(uint32_t*)(vf + (size_t)(gm0 + 8) * 64 + gnl) = p1;
                }
            }
        }
        return;
    }

    const float scale = (which == 0) ? 0.125f : 1.0f;
    const float* bias = (which == 0) ? bq : bk;
    __half* of = (which == 0) ? qf : kf;

    #pragma unroll
    for (int tm = 0; tm < 2; tm++) {
        #pragma unroll
        for (int j = 0; j < 8; j++) {
            int gnl = warp_n * 64 + j * 8 + 2 * (lane & 3);
            float2 bv2 = *(const float2*)&bias[n0 + gnl];
            int gm0 = m0 + warp_m * 32 + tm * 16 + (lane >> 2);
            uint32_t p0 = pack_h2((c[tm][j][0] + bv2.x) * scale,
                                  (c[tm][j][1] + bv2.y) * scale);
            uint32_t p1 = pack_h2((c[tm][j][2] + bv2.x) * scale,
                                  (c[tm][j][3] + bv2.y) * scale);
            *(uint32_t*)(of + (size_t)gm0 * HH + n0 + gnl)       = p0;
            *(uint32_t*)(of + (size_t)(gm0 + 8) * HH + n0 + gnl) = p1;
        }
    }
}

// ---------------------------------------------------------------------------
// O projection: out[M,1024] = m[M,64] @ Wo[64,1024], bf16 3-pass mma, K=64.
// ---------------------------------------------------------------------------
#define OG_SMEM 65536

__global__ __launch_bounds__(256) void out_gemm(
    const __nv_bfloat16* __restrict__ mh, const __nv_bfloat16* __restrict__ ml,
    const __nv_bfloat16* __restrict__ wtoh, const __nv_bfloat16* __restrict__ wtol,
    float* __restrict__ out)
{
    extern __shared__ char smem[];
    const uint32_t sb = su32(smem);
    const int tid = threadIdx.x;
    const int lane = tid & 31;
    const int wid = tid >> 5;
    const int warp_m = wid & 3;
    const int warp_n = wid >> 2;
    const int n0 = blockIdx.x * 128;
    const int m0 = blockIdx.y * 128;

    #pragma unroll
    for (int i = 0; i < 4; i++) {
        int s = tid + (i << 8);
        int r = s >> 3, ch = s & 7;
        uint32_t off = sw128((uint32_t)(r * 128 + ch * 16));
        const size_t ga = (size_t)(m0 + r) * 64 + ch * 8;
        const size_t gb = (size_t)(n0 + r) * 64 + ch * 8;
        CP16(sb + off,         mh + ga);
        CP16(sb + 16384 + off, ml + ga);
        CP16(sb + 32768 + off, wtoh + gb);
        CP16(sb + 49152 + off, wtol + gb);
    }
    CP_COMMIT();
    CP_WAIT0();
    __syncthreads();

    float c[2][8][4];
    #pragma unroll
    for (int tm = 0; tm < 2; tm++)
        #pragma unroll
        for (int j = 0; j < 8; j++)
            #pragma unroll
            for (int r = 0; r < 4; r++) c[tm][j][r] = 0.f;

    #pragma unroll
    for (int kk = 0; kk < 4; kk++) {
        const int kc0 = kk * 2;
        uint32_t ah[2][4], al[2][4];
        {
            const int mat = lane >> 3, rin = lane & 7;
            #pragma unroll
            for (int tm = 0; tm < 2; tm++) {
                int row = warp_m * 32 + tm * 16 + (mat & 1) * 8 + rin;
                int ch  = kc0 + (mat >> 1);
                uint32_t off = sw128((uint32_t)(row * 128 + ch * 16));
                LDSM4(ah[tm][0], ah[tm][1], ah[tm][2], ah[tm][3], sb + off);
                LDSM4(al[tm][0], al[tm][1], al[tm][2], al[tm][3],
                      sb + 16384 + off);
            }
        }
        uint32_t bh[8][2], bl[8][2];
        {
            const int mat = lane >> 3, rin = lane & 7;
            #pragma unroll
            for (int jp = 0; jp < 4; jp++) {
                int grp = jp * 2 + (mat >> 1);
                int ch  = kc0 + (mat & 1);
                int row = warp_n * 64 + grp * 8 + rin;
                uint32_t off = sw128((uint32_t)(row * 128 + ch * 16));
                uint32_t r0, r1, r2, r3;
                LDSM4(r0, r1, r2, r3, sb + 32768 + off);
                bh[jp*2][0] = r0; bh[jp*2][1] = r1;
                bh[jp*2+1][0] = r2; bh[jp*2+1][1] = r3;
                LDSM4(r0, r1, r2, r3, sb + 49152 + off);
                bl[jp*2][0] = r0; bl[jp*2][1] = r1;
                bl[jp*2+1][0] = r2; bl[jp*2+1][1] = r3;
            }
        }
        #pragma unroll
        for (int tm = 0; tm < 2; tm++)
            #pragma unroll
            for (int j = 0; j < 8; j++) {
                MMA16816(c[tm][j], ah[tm], bh[j]);
                MMA16816(c[tm][j], ah[tm], bl[j]);
                MMA16816(c[tm][j], al[tm], bh[j]);
            }
    }

    #pragma unroll
    for (int tm = 0; tm < 2; tm++) {
        #pragma unroll
        for (int j = 0; j < 8; j++) {
            int gn = n0 + warp_n * 64 + j * 8 + 2 * (lane & 3);
            int gm0 = m0 + warp_m * 32 + tm * 16 + (lane >> 2);
            float2 o0, o1;
            o0.x = c[tm][j][0]; o0.y = c[tm][j][1];
            o1.x = c[tm][j][2]; o1.y = c[tm][j][3];
            *(float2*)&out[(size_t)gm0 * HH + gn]       = o0;
            *(float2*)&out[(size_t)(gm0 + 8) * HH + gn] = o1;
        }
    }
}

// ---------------------------------------------------------------------------
// Tensor-core causal flash attention — all fp16 single-pass (unchanged R8).
// ---------------------------------------------------------------------------
#define AT_SUB   16384
#define AT_STAGE (2 * AT_SUB)
#define AT_SMEM  (2 * AT_STAGE + 16384)   // 81920

__global__ __launch_bounds__(256) void attn_mma(
    const __half* __restrict__ qf, const __half* __restrict__ kf,
    const __half* __restrict__ vf,
    float* __restrict__ attn_out)
{
    extern __shared__ char smem[];
    const uint32_t sb = su32(smem);
    const uint32_t qb = sb + 2 * AT_STAGE;
    const int tid = threadIdx.x;
    const int lane = tid & 31;
    const int w = tid >> 5;

    const int b  = blockIdx.z;
    const int h  = blockIdx.y;
    const int qi = (TT / 128 - 1) - blockIdx.x;
    const int q0 = qi * 128;

    #pragma unroll
    for (int i = 0; i < 4; i++) {
        int idx = tid + (i << 8);
        int r = idx >> 3, ch = idx & 7;
        uint32_t off = sw128((uint32_t)(r * 128 + ch * 16));
        size_t g = (size_t)(b * TT + q0 + r) * HH + h * 64 + ch * 8;
        CP16(qb + off, qf + g);
    }
    CP_COMMIT();

    auto load_pair = [&](int stg, int p) {
        const uint32_t sa = sb + stg * AT_STAGE;
        const size_t rowb = (size_t)(b * TT + p * 128);
        #pragma unroll
        for (int i = 0; i < 4; i++) {
            int idx = tid + (i << 8);
            int r = idx >> 3, ch = idx & 7;
            uint32_t sub = (uint32_t)(r >> 6) * AT_SUB;
            uint32_t off = sub + sw128((uint32_t)((r & 63) * 128 + ch * 16));
            size_t gk = (rowb + r) * HH + h * 64 + ch * 8;
            size_t gv = (rowb + r) * 64 + ch * 8;
            CP16(sa + off,        kf + gk);
            CP16(sa + 8192 + off, vf + gv);
        }
        CP_COMMIT();
    };

    load_pair(0, 0);

    CP_WAIT1();
    __syncthreads();

    uint32_t Aqf[4][4];
    {
        const int tile = lane >> 3, rin = lane & 7;
        #pragma unroll
        for (int g = 0; g < 4; g++) {
            int row = w * 16 + (tile & 1) * 8 + rin;
            int ch  = 2 * g + (tile >> 1);
            uint32_t off = sw128((uint32_t)(row * 128 + ch * 16));
            LDSM4(Aqf[g][0], Aqf[g][1], Aqf[g][2], Aqf[g][3], qb + off);
        }
    }

    float m0r = -1e30f, m1r = -1e30f, l0r = 0.f, l1r = 0.f;
    float o[8][4];
    #pragma unroll
    for (int j = 0; j < 8; j++)
        #pragma unroll
        for (int e = 0; e < 4; e++) o[j][e] = 0.f;

    const int npairs = qi + 1;

    for (int p = 0; p < npairs; p++) {
        CP_WAIT0();
        __syncthreads();
        if (p + 1 < npairs) load_pair((p + 1) & 1, p + 1);

        #pragma unroll
        for (int sub = 0; sub < 2; sub++) {
            const int kt = 2 * p + sub;
            const bool skip = (kt * 64) > (q0 + w * 16 + 15);
            if (skip) continue;

            const uint32_t sa = sb + (p & 1) * AT_STAGE + sub * AT_SUB;
            const int tile = lane >> 3, rin = lane & 7;

            float s[8][4];
            #pragma unroll
            for (int j = 0; j < 8; j++)
                #pragma unroll
                for (int e = 0; e < 4; e++) s[j][e] = 0.f;

            #pragma unroll
            for (int g = 0; g < 4; g++) {
                uint32_t bh[8][2];
                #pragma unroll
                for (int pp = 0; pp < 4; pp++) {
                    int row = 16 * pp + (tile >> 1) * 8 + rin;
                    int ch  = 2 * g + (tile & 1);
                    uint32_t off = sw128((uint32_t)(row * 128 + ch * 16));
                    uint32_t r0, r1, r2, r3;
                    LDSM4(r0, r1, r2, r3, sa + off);
                    bh[2*pp][0] = r0; bh[2*pp][1] = r1;
                    bh[2*pp+1][0] = r2; bh[2*pp+1][1] = r3;
                }
                #pragma unroll
                for (int j = 0; j < 8; j++)
                    MMAF16(s[j], Aqf[g], bh[j]);
            }

            const int gr0 = q0 + w * 16 + (lane >> 2);
            if (kt * 64 + 63 > q0 + w * 16) {
                #pragma unroll
                for (int j = 0; j < 8; j++) {
                    int col = kt * 64 + j * 8 + 2 * (lane & 3);
                    if (col     > gr0)     s[j][0] = -1e30f;
                    if (col + 1 > gr0)     s[j][1] = -1e30f;
                    if (col     > gr0 + 8) s[j][2] = -1e30f;
                    if (col + 1 > gr0 + 8) s[j][3] = -1e30f;
                }
            }

            float mx0 = -1e30f, mx1 = -1e30f;
            #pragma unroll
            for (int j = 0; j < 8; j++) {
                mx0 = fmaxf(mx0, fmaxf(s[j][0], s[j][1]));
                mx1 = fmaxf(mx1, fmaxf(s[j][2], s[j][3]));
            }
            mx0 = fmaxf(mx0, __shfl_xor_sync(0xffffffffu, mx0, 1));
            mx0 = fmaxf(mx0, __shfl_xor_sync(0xffffffffu, mx0, 2));
            mx1 = fmaxf(mx1, __shfl_xor_sync(0xffffffffu, mx1, 1));
            mx1 = fmaxf(mx1, __shfl_xor_sync(0xffffffffu, mx1, 2));

            float mn0 = fmaxf(m0r, mx0), mn1 = fmaxf(m1r, mx1);
            float c0 = __expf(m0r - mn0), c1 = __expf(m1r - mn1);
            float sum0 = 0.f, sum1 = 0.f;
            #pragma unroll
            for (int j = 0; j < 8; j++) {
                s[j][0] = __expf(s[j][0] - mn0);
                s[j][1] = __expf(s[j][1] - mn0);
                s[j][2] = __expf(s[j][2] - mn1);
                s[j][3] = __expf(s[j][3] - mn1);
                sum0 += s[j][0] + s[j][1];
                sum1 += s[j][2] + s[j][3];
            }
            sum0 += __shfl_xor_sync(0xffffffffu, sum0, 1);
            sum0 += __shfl_xor_sync(0xffffffffu, sum0, 2);
            sum1 += __shfl_xor_sync(0xffffffffu, sum1, 1);
            sum1 += __shfl_xor_sync(0xffffffffu, sum1, 2);
            m0r = mn0; m1r = mn1;
            l0r = l0r * c0 + sum0;
            l1r = l1r * c1 + sum1;

            uint32_t Apf[4][4];
            #pragma unroll
            for (int g = 0; g < 4; g++) {
                Apf[g][0] = pack_h2(s[2*g][0],   s[2*g][1]);
                Apf[g][1] = pack_h2(s[2*g][2],   s[2*g][3]);
                Apf[g][2] = pack_h2(s[2*g+1][0], s[2*g+1][1]);
                Apf[g][3] = pack_h2(s[2*g+1][2], s[2*g+1][3]);
            }

            #pragma unroll
            for (int j = 0; j < 8; j++) {
                o[j][0] *= c0; o[j][1] *= c0;
                o[j][2] *= c1; o[j][3] *= c1;
            }

            #pragma unroll
            for (int g = 0; g < 4; g++) {
                uint32_t bvf[8][2];
                #pragma unroll
                for (int pp = 0; pp < 4; pp++) {
                    int row = 16 * g + (tile & 1) * 8 + rin;
                    int ch  = 2 * pp + (tile >> 1);
                    uint32_t off = sw128((uint32_t)(row * 128 + ch * 16));
                    uint32_t r0, r1, r2, r3;
                    LDSM4T(r0, r1, r2, r3, sa + 8192 + off);
                    bvf[2*pp][0] = r0; bvf[2*pp][1] = r1;
                    bvf[2*pp+1][0] = r2; bvf[2*pp+1][1] = r3;
                }
                #pragma unroll
                for (int j = 0; j < 8; j++)
                    MMAF16(o[j], Apf[g], bvf[j]);
            }
        }
    }

    const float inv0 = 1.f / l0r, inv1 = 1.f / l1r;
    const int gr0 = q0 + w * 16 + (lane >> 2);
    float* base = attn_out + (((size_t)b * NHH + h) * TT) * DHH;
    #pragma unroll
    for (int j = 0; j < 8; j++) {
        int col = j * 8 + 2 * (lane & 3);
        float2 v0, v1;
        v0.x = o[j][0] * inv0; v0.y = o[j][1] * inv0;
        v1.x = o[j][2] * inv1; v1.y = o[j][3] * inv1;
        *(float2*)(base + (size_t)gr0 * DHH + col)       = v0;
        *(float2*)(base + (size_t)(gr0 + 8) * DHH + col) = v1;
    }
}

// ---------------------------------------------------------------------------
// Head-mean pooling fused with bf16 hi/lo split output
// ---------------------------------------------------------------------------
__global__ __launch_bounds__(256) void head_mean_split(
    const float* __restrict__ attn, __nv_bfloat16* __restrict__ mh,
    __nv_bfloat16* __restrict__ ml)
{
    int idx = blockIdx.x * blockDim.x + threadIdx.x;
    int d4 = idx & 15;
    int bt = idx >> 4;
    int b  = bt / TT;
    int t  = bt % TT;
    float4 acc = make_float4(0.f, 0.f, 0.f, 0.f);
    #pragma unroll
    for (int h = 0; h < NHH; h++) {
        float4 vv = *(const float4*)&attn[(((size_t)b*NHH + h)*TT + t)*DHH + d4*4];
        acc.x += vv.x; acc.y += vv.y; acc.z += vv.z; acc.w += vv.w;
    }
    const float inv = 1.f / (float)NHH;
    uint32_t h01, l01, h23, l23;
    split2(acc.x * inv, acc.y * inv, h01, l01);
    split2(acc.z * inv, acc.w * inv, h23, l23);
    size_t o = (size_t)bt * DHH + d4 * 4;
    *(uint32_t*)(mh + o)     = h01;
    *(uint32_t*)(mh + o + 2) = h23;
    *(uint32_t*)(ml + o)     = l01;
    *(uint32_t*)(ml + o + 2) = l23;
}

// ---------------------------------------------------------------------------
extern "C" void kernel_launch(void* const* d_in, const int* in_sizes, int n_in,
                              void* d_out, int out_size)
{
    const float* x  = (const float*)d_in[0];
    const float* Wq = (const float*)d_in[1];
    const float* bq = (const float*)d_in[2];
    const float* Wk = (const float*)d_in[3];
    const float* bk = (const float*)d_in[4];
    const float* Wv = (const float*)d_in[5];
    const float* bv = (const float*)d_in[6];
    const float* Wo = (const float*)d_in[7];

    float* out  = (float*)d_out;                      // [32,512,1024]
    float* attn = out + (size_t)MTOT * HH;            // [32,16,512,64]

    float *qbuf, *kbuf, *vbuf, *mbuf;
    __nv_bfloat16 *xbuf, *wthb, *wtoh, *wtol;
    cudaGetSymbolAddress((void**)&qbuf, g_q);
    cudaGetSymbolAddress((void**)&kbuf, g_k);
    cudaGetSymbolAddress((void**)&vbuf, g_v);
    cudaGetSymbolAddress((void**)&mbuf, g_m);
    cudaGetSymbolAddress((void**)&xbuf, g_xh);
    cudaGetSymbolAddress((void**)&wthb, g_wth);
    cudaGetSymbolAddress((void**)&wtoh, g_wtoh);
    cudaGetSymbolAddress((void**)&wtol, g_wtol);

    __half* qf = (__half*)qbuf;
    __half* kf = (__half*)kbuf;
    __half* vf = (__half*)vbuf;
    __half* xf = (__half*)xbuf;
    __half* wf = (__half*)wthb;
    __nv_bfloat16* mh = (__nv_bfloat16*)mbuf;
    __nv_bfloat16* ml = mh + (size_t)MTOT * DHH;

    cudaFuncSetAttribute(qkv_gemm, cudaFuncAttributeMaxDynamicSharedMemorySize,
                         QK_SMEM);
    cudaFuncSetAttribute(attn_mma, cudaFuncAttributeMaxDynamicSharedMemorySize,
                         AT_SMEM);
    cudaFuncSetAttribute(out_gemm, cudaFuncAttributeMaxDynamicSharedMemorySize,
                         OG_SMEM);

    dim3 blk(256);

    // fp16 conversions
    convert_xh<<<dim3(((size_t)MTOT*HH/4)/256), blk>>>(x, xf);
    tconv_h<<<dim3(32, 32), blk>>>(Wq, wf, HH, HH);
    tconv_h<<<dim3(32, 32), blk>>>(Wk, wf + (size_t)HH*HH, HH, HH);
    tconv_h<<<dim3(2, 32),  blk>>>(Wv, wf + (size_t)2*HH*HH, HH, 64);
    tsplit<<<dim3(32, 2),  blk>>>(Wo, wtoh, wtol, 64, HH);

    // Q+K+V projections (fp16 single-pass) -> fp16 singles (Q pre-scaled 1/8)
    qkv_gemm<<<dim3(17, MTOT/128), blk, QK_SMEM>>>(xf, wf,
                                                   bq, bk, bv, qf, kf, vf);

    // Tensor-core causal attention (fp16 single-pass) -> attn_vec (fp32)
    attn_mma<<<dim3(TT/128, NHH, BSZ), blk, AT_SMEM>>>(qf, kf, vf, attn);

    // Head mean (+bf16 split) and O projection (bf16 3-pass)
    head_mean_split<<<dim3((MTOT * (DHH/4)) / 256), blk>>>(attn, mh, ml);
    out_gemm<<<dim3(8, MTOT/128), blk, OG_SMEM>>>(mh, ml, wtoh, wtol, out);
}

// round 10
// speedup vs baseline: 7.5666x; 1.1034x over previous
#include <cuda_runtime.h>
#include <cuda_bf16.h>
#include <cuda_fp16.h>
#include <math.h>
#include <stdint.h>

#define BSZ 32
#define TT  512
#define HH  1024
#define DHH 64
#define NHH 16
#define MTOT (BSZ*TT)   // 16384

// ---------------------------------------------------------------------------
// Scratch (device globals: allocation-free contract)
// ---------------------------------------------------------------------------
__device__ float g_q[(size_t)MTOT * HH];             // -> qf fp16
__device__ float g_k[(size_t)MTOT * HH];             // -> kf fp16
__device__ float g_v[(size_t)MTOT * DHH];            // -> vf fp16
__device__ float g_m[(size_t)MTOT * DHH];            // -> mh|ml bf16 splits
__device__ __nv_bfloat16 g_xh[(size_t)MTOT * HH];    // -> xf fp16
// W^T fp16 single: Wq^T | Wk^T | Wv^T rows, stride HH
__device__ __nv_bfloat16 g_wth[(size_t)2 * HH * HH + 64 * HH];
// Wo^T: bf16 hi/lo (out proj stays 3-pass bf16)
__device__ __nv_bfloat16 g_wtoh[(size_t)HH * 64];
__device__ __nv_bfloat16 g_wtol[(size_t)HH * 64];

// ---------------------------------------------------------------------------
// Baseline-ISA PTX helpers
// ---------------------------------------------------------------------------
__device__ __forceinline__ uint32_t su32(const void* p) {
    uint32_t a;
    asm("{ .reg .u64 t; cvta.to.shared.u64 t, %1; cvt.u32.u64 %0, t; }"
        : "=r"(a) : "l"(p));
    return a;
}
#define CP16(dst, src) \
    asm volatile("cp.async.cg.shared.global [%0], [%1], 16;" \
                 :: "r"(dst), "l"(src))
#define CP_COMMIT() asm volatile("cp.async.commit_group;" ::: "memory")
#define CP_WAIT1()  asm volatile("cp.async.wait_group 1;" ::: "memory")
#define CP_WAIT0()  asm volatile("cp.async.wait_group 0;" ::: "memory")
#define LDSM4(r0, r1, r2, r3, addr) \
    asm volatile("ldmatrix.sync.aligned.m8n8.x4.shared.b16 {%0,%1,%2,%3}, [%4];" \
                 : "=r"(r0), "=r"(r1), "=r"(r2), "=r"(r3) : "r"(addr))
#define LDSM4T(r0, r1, r2, r3, addr) \
    asm volatile("ldmatrix.sync.aligned.m8n8.x4.trans.shared.b16 {%0,%1,%2,%3}, [%4];" \
                 : "=r"(r0), "=r"(r1), "=r"(r2), "=r"(r3) : "r"(addr))
#define MMA16816(d, a, b) \
    asm volatile("mma.sync.aligned.m16n8k16.row.col.f32.bf16.bf16.f32 " \
                 "{%0,%1,%2,%3}, {%4,%5,%6,%7}, {%8,%9}, {%0,%1,%2,%3};" \
                 : "+f"((d)[0]), "+f"((d)[1]), "+f"((d)[2]), "+f"((d)[3]) \
                 : "r"((a)[0]), "r"((a)[1]), "r"((a)[2]), "r"((a)[3]), \
                   "r"((b)[0]), "r"((b)[1]))
#define MMAF16(d, a, b) \
    asm volatile("mma.sync.aligned.m16n8k16.row.col.f32.f16.f16.f32 " \
                 "{%0,%1,%2,%3}, {%4,%5,%6,%7}, {%8,%9}, {%0,%1,%2,%3};" \
                 : "+f"((d)[0]), "+f"((d)[1]), "+f"((d)[2]), "+f"((d)[3]) \
                 : "r"((a)[0]), "r"((a)[1]), "r"((a)[2]), "r"((a)[3]), \
                   "r"((b)[0]), "r"((b)[1]))

__device__ __forceinline__ uint32_t sw128(uint32_t off) {
    return off ^ ((off >> 3) & 0x70u);
}
__device__ __forceinline__ void split2(float a, float b,
                                       uint32_t& hi, uint32_t& lo) {
    __nv_bfloat162 h = __floats2bfloat162_rn(a, b);
    float ra = a - __bfloat162float(h.x);
    float rb = b - __bfloat162float(h.y);
    __nv_bfloat162 l = __floats2bfloat162_rn(ra, rb);
    hi = *(uint32_t*)&h;
    lo = *(uint32_t*)&l;
}
__device__ __forceinline__ uint32_t pack_h2(float a, float b) {
    __half2 h = __floats2half2_rn(a, b);
    return *(uint32_t*)&h;
}

// ---------------------------------------------------------------------------
// fp32 -> fp16 single
// ---------------------------------------------------------------------------
__global__ __launch_bounds__(256) void convert_xh(
    const float* __restrict__ x, __half* __restrict__ xf)
{
    size_t i = ((size_t)blockIdx.x * blockDim.x + threadIdx.x) * 4;
    float4 v = *(const float4*)(x + i);
    *(uint32_t*)(xf + i)     = pack_h2(v.x, v.y);
    *(uint32_t*)(xf + i + 2) = pack_h2(v.z, v.w);
}

// ---------------------------------------------------------------------------
// Transpose to fp16 single: src[R][C] fp32 -> dst[C][R]
// ---------------------------------------------------------------------------
__global__ __launch_bounds__(256) void tconv_h(
    const float* __restrict__ src, __half* __restrict__ d, int R, int C)
{
    __shared__ float t[32][33];
    int c0 = blockIdx.x * 32, r0 = blockIdx.y * 32;
    int tx = threadIdx.x & 31, ty = threadIdx.x >> 5;
    #pragma unroll
    for (int j = 0; j < 4; j++)
        t[ty + j*8][tx] = src[(size_t)(r0 + ty + j*8) * C + c0 + tx];
    __syncthreads();
    #pragma unroll
    for (int j = 0; j < 4; j++) {
        int ro = c0 + ty + j*8;
        int co = r0 + tx;
        d[(size_t)ro * R + co] = __float2half(t[tx][ty + j*8]);
    }
}

// ---------------------------------------------------------------------------
// Transpose + bf16 hi/lo split (Wo only)
// ---------------------------------------------------------------------------
__global__ __launch_bounds__(256) void tsplit(
    const float* __restrict__ src, __nv_bfloat16* __restrict__ dh,
    __nv_bfloat16* __restrict__ dl, int R, int C)
{
    __shared__ float t[32][33];
    int c0 = blockIdx.x * 32, r0 = blockIdx.y * 32;
    int tx = threadIdx.x & 31, ty = threadIdx.x >> 5;
    #pragma unroll
    for (int j = 0; j < 4; j++)
        t[ty + j*8][tx] = src[(size_t)(r0 + ty + j*8) * C + c0 + tx];
    __syncthreads();
    #pragma unroll
    for (int j = 0; j < 4; j++) {
        int ro = c0 + ty + j*8;
        int co = r0 + tx;
        float v = t[tx][ty + j*8];
        __nv_bfloat16 h = __float2bfloat16(v);
        dh[(size_t)ro * R + co] = h;
        dl[(size_t)ro * R + co] = __float2bfloat16(v - __bfloat162float(h));
    }
}

// ---------------------------------------------------------------------------
// Fused Q+K+V projection: single-pass fp16 mma, 2 CTAs/SM.
// Outputs q,k,v as fp16 singles (Q pre-scaled 0.125*log2e for exp2 softmax).
// ---------------------------------------------------------------------------
#define QK_STAGE 32768
#define QK_SMEM  (3 * QK_STAGE)
#define QSCALE   (0.125f * 1.44269504088896f)

__global__ __launch_bounds__(256, 2) void qkv_gemm(
    const __half* __restrict__ xf, const __half* __restrict__ wf,
    const float* __restrict__ bq, const float* __restrict__ bk,
    const float* __restrict__ bv,
    __half* __restrict__ qf, __half* __restrict__ kf,
    __half* __restrict__ vf)
{
    extern __shared__ char smem[];
    const uint32_t sb = su32(smem);
    const int tid = threadIdx.x;
    const int lane = tid & 31;
    const int wid = tid >> 5;
    const int warp_m = wid & 3;
    const int warp_n = wid >> 2;

    const int ntile = blockIdx.x;
    const int which = ntile >> 3;        // 0=Q, 1=K, 2=V
    const int n0 = (ntile & 7) * 128;
    const int m0 = blockIdx.y * 128;

    const __half* wb = wf + (size_t)which * HH * HH;

    float c[2][8][4];
    #pragma unroll
    for (int tm = 0; tm < 2; tm++)
        #pragma unroll
        for (int j = 0; j < 8; j++)
            #pragma unroll
            for (int r = 0; r < 4; r++) c[tm][j][r] = 0.f;

    auto load_stage = [&](int stage, int k0) {
        const uint32_t sa = sb + stage * QK_STAGE;
        #pragma unroll
        for (int i = 0; i < 4; i++) {
            int s = tid + (i << 8);
            int r = s >> 3, ch = s & 7;
            uint32_t off = sw128((uint32_t)(r * 128 + ch * 16));
            const size_t ga = (size_t)(m0 + r) * HH + k0 + ch * 8;
            const int br = (which == 2) ? (r & 63) : r;
            const size_t gb = (size_t)(n0 + br) * HH + k0 + ch * 8;
            CP16(sa + off,         xf + ga);
            CP16(sa + 16384 + off, wb + gb);
        }
        CP_COMMIT();
    };

    load_stage(0, 0);
    load_stage(1, 64);

    for (int cch = 0; cch < 16; cch++) {
        if (cch + 2 < 16) CP_WAIT1(); else CP_WAIT0();
        __syncthreads();
        if (cch + 2 < 16) load_stage((cch + 2) % 3, (cch + 2) * 64);

        const uint32_t sa = sb + (cch % 3) * QK_STAGE;
        #pragma unroll
        for (int kk = 0; kk < 4; kk++) {
            const int kc0 = kk * 2;
            uint32_t af[2][4];
            {
                const int mat = lane >> 3, rin = lane & 7;
                #pragma unroll
                for (int tm = 0; tm < 2; tm++) {
                    int row = warp_m * 32 + tm * 16 + (mat & 1) * 8 + rin;
                    int ch  = kc0 + (mat >> 1);
                    uint32_t off = sw128((uint32_t)(row * 128 + ch * 16));
                    LDSM4(af[tm][0], af[tm][1], af[tm][2], af[tm][3], sa + off);
                }
            }
            uint32_t bf[8][2];
            {
                const int mat = lane >> 3, rin = lane & 7;
                #pragma unroll
                for (int jp = 0; jp < 4; jp++) {
                    int grp = jp * 2 + (mat >> 1);
                    int ch  = kc0 + (mat & 1);
                    int row = warp_n * 64 + grp * 8 + rin;
                    uint32_t off = sw128((uint32_t)(row * 128 + ch * 16));
                    uint32_t r0, r1, r2, r3;
                    LDSM4(r0, r1, r2, r3, sa + 16384 + off);
                    bf[jp*2][0] = r0; bf[jp*2][1] = r1;
                    bf[jp*2+1][0] = r2; bf[jp*2+1][1] = r3;
                }
            }
            #pragma unroll
            for (int tm = 0; tm < 2; tm++)
                #pragma unroll
                for (int j = 0; j < 8; j++)
                    MMAF16(c[tm][j], af[tm], bf[j]);
        }
    }

    // ---- epilogue: fp16 single outputs ----
    if (which == 2) {
        if (warp_n == 0) {
            #pragma unroll
            for (int tm = 0; tm < 2; tm++) {
                #pragma unroll
                for (int j = 0; j < 8; j++) {
                    int gnl = j * 8 + 2 * (lane & 3);
                    float2 bv2 = *(const float2*)&bv[gnl];
                    int gm0 = m0 + warp_m * 32 + tm * 16 + (lane >> 2);
                    uint32_t p0 = pack_h2(c[tm][j][0] + bv2.x,
                                          c[tm][j][1] + bv2.y);
                    uint32_t p1 = pack_h2(c[tm][j][2] + bv2.x,
                                          c[tm][j][3] + bv2.y);
                    *(uint32_t*)(vf + (size_t)gm0 * 64 + gnl)       = p0;
                    *(uint32_t*)(vf + (size_t)(gm0 + 8) * 64 + gnl) = p1;
                }
            }
        }
        return;
    }

    const float scale = (which == 0) ? QSCALE : 1.0f;
    const float* bias = (which == 0) ? bq : bk;
    __half* of = (which == 0) ? qf : kf;

    #pragma unroll
    for (int tm = 0; tm < 2; tm++) {
        #pragma unroll
        for (int j = 0; j < 8; j++) {
            int gnl = warp_n * 64 + j * 8 + 2 * (lane & 3);
            float2 bv2 = *(const float2*)&bias[n0 + gnl];
            int gm0 = m0 + warp_m * 32 + tm * 16 + (lane >> 2);
            uint32_t p0 = pack_h2((c[tm][j][0] + bv2.x) * scale,
                                  (c[tm][j][1] + bv2.y) * scale);
            uint32_t p1 = pack_h2((c[tm][j][2] + bv2.x) * scale,
                                  (c[tm][j][3] + bv2.y) * scale);
            *(uint32_t*)(of + (size_t)gm0 * HH + n0 + gnl)       = p0;
            *(uint32_t*)(of + (size_t)(gm0 + 8) * HH + n0 + gnl) = p1;
        }
    }
}

// ---------------------------------------------------------------------------
// O projection: out[M,1024] = m[M,64] @ Wo[64,1024], bf16 3-pass mma, K=64.
// ---------------------------------------------------------------------------
#define OG_SMEM 65536

__global__ __launch_bounds__(256) void out_gemm(
    const __nv_bfloat16* __restrict__ mh, const __nv_bfloat16* __restrict__ ml,
    const __nv_bfloat16* __restrict__ wtoh, const __nv_bfloat16* __restrict__ wtol,
    float* __restrict__ out)
{
    extern __shared__ char smem[];
    const uint32_t sb = su32(smem);
    const int tid = threadIdx.x;
    const int lane = tid & 31;
    const int wid = tid >> 5;
    const int warp_m = wid & 3;
    const int warp_n = wid >> 2;
    const int n0 = blockIdx.x * 128;
    const int m0 = blockIdx.y * 128;

    #pragma unroll
    for (int i = 0; i < 4; i++) {
        int s = tid + (i << 8);
        int r = s >> 3, ch = s & 7;
        uint32_t off = sw128((uint32_t)(r * 128 + ch * 16));
        const size_t ga = (size_t)(m0 + r) * 64 + ch * 8;
        const size_t gb = (size_t)(n0 + r) * 64 + ch * 8;
        CP16(sb + off,         mh + ga);
        CP16(sb + 16384 + off, ml + ga);
        CP16(sb + 32768 + off, wtoh + gb);
        CP16(sb + 49152 + off, wtol + gb);
    }
    CP_COMMIT();
    CP_WAIT0();
    __syncthreads();

    float c[2][8][4];
    #pragma unroll
    for (int tm = 0; tm < 2; tm++)
        #pragma unroll
        for (int j = 0; j < 8; j++)
            #pragma unroll
            for (int r = 0; r < 4; r++) c[tm][j][r] = 0.f;

    #pragma unroll
    for (int kk = 0; kk < 4; kk++) {
        const int kc0 = kk * 2;
        uint32_t ah[2][4], al[2][4];
        {
            const int mat = lane >> 3, rin = lane & 7;
            #pragma unroll
            for (int tm = 0; tm < 2; tm++) {
                int row = warp_m * 32 + tm * 16 + (mat & 1) * 8 + rin;
                int ch  = kc0 + (mat >> 1);
                uint32_t off = sw128((uint32_t)(row * 128 + ch * 16));
                LDSM4(ah[tm][0], ah[tm][1], ah[tm][2], ah[tm][3], sb + off);
                LDSM4(al[tm][0], al[tm][1], al[tm][2], al[tm][3],
                      sb + 16384 + off);
            }
        }
        uint32_t bh[8][2], bl[8][2];
        {
            const int mat = lane >> 3, rin = lane & 7;
            #pragma unroll
            for (int jp = 0; jp < 4; jp++) {
                int grp = jp * 2 + (mat >> 1);
                int ch  = kc0 + (mat & 1);
                int row = warp_n * 64 + grp * 8 + rin;
                uint32_t off = sw128((uint32_t)(row * 128 + ch * 16));
                uint32_t r0, r1, r2, r3;
                LDSM4(r0, r1, r2, r3, sb + 32768 + off);
                bh[jp*2][0] = r0; bh[jp*2][1] = r1;
                bh[jp*2+1][0] = r2; bh[jp*2+1][1] = r3;
                LDSM4(r0, r1, r2, r3, sb + 49152 + off);
                bl[jp*2][0] = r0; bl[jp*2][1] = r1;
                bl[jp*2+1][0] = r2; bl[jp*2+1][1] = r3;
            }
        }
        #pragma unroll
        for (int tm = 0; tm < 2; tm++)
            #pragma unroll
            for (int j = 0; j < 8; j++) {
                MMA16816(c[tm][j], ah[tm], bh[j]);
                MMA16816(c[tm][j], ah[tm], bl[j]);
                MMA16816(c[tm][j], al[tm], bh[j]);
            }
    }

    #pragma unroll
    for (int tm = 0; tm < 2; tm++) {
        #pragma unroll
        for (int j = 0; j < 8; j++) {
            int gn = n0 + warp_n * 64 + j * 8 + 2 * (lane & 3);
            int gm0 = m0 + warp_m * 32 + tm * 16 + (lane >> 2);
            float2 o0, o1;
            o0.x = c[tm][j][0]; o0.y = c[tm][j][1];
            o1.x = c[tm][j][2]; o1.y = c[tm][j][3];
            *(float2*)&out[(size_t)gm0 * HH + gn]       = o0;
            *(float2*)&out[(size_t)(gm0 + 8) * HH + gn] = o1;
        }
    }
}

// ---------------------------------------------------------------------------
// Tensor-core causal flash attention — fp16 single-pass, exp2 softmax,
// 2 CTAs/SM target.
// ---------------------------------------------------------------------------
#define AT_SUB   16384
#define AT_STAGE (2 * AT_SUB)
#define AT_SMEM  (2 * AT_STAGE + 16384)   // 81920

__global__ __launch_bounds__(256, 2) void attn_mma(
    const __half* __restrict__ qf, const __half* __restrict__ kf,
    const __half* __restrict__ vf,
    float* __restrict__ attn_out)
{
    extern __shared__ char smem[];
    const uint32_t sb = su32(smem);
    const uint32_t qb = sb + 2 * AT_STAGE;
    const int tid = threadIdx.x;
    const int lane = tid & 31;
    const int w = tid >> 5;

    const int b  = blockIdx.z;
    const int h  = blockIdx.y;
    const int qi = (TT / 128 - 1) - blockIdx.x;
    const int q0 = qi * 128;

    #pragma unroll
    for (int i = 0; i < 4; i++) {
        int idx = tid + (i << 8);
        int r = idx >> 3, ch = idx & 7;
        uint32_t off = sw128((uint32_t)(r * 128 + ch * 16));
        size_t g = (size_t)(b * TT + q0 + r) * HH + h * 64 + ch * 8;
        CP16(qb + off, qf + g);
    }
    CP_COMMIT();

    auto load_pair = [&](int stg, int p) {
        const uint32_t sa = sb + stg * AT_STAGE;
        const size_t rowb = (size_t)(b * TT + p * 128);
        #pragma unroll
        for (int i = 0; i < 4; i++) {
            int idx = tid + (i << 8);
            int r = idx >> 3, ch = idx & 7;
            uint32_t sub = (uint32_t)(r >> 6) * AT_SUB;
            uint32_t off = sub + sw128((uint32_t)((r & 63) * 128 + ch * 16));
            size_t gk = (rowb + r) * HH + h * 64 + ch * 8;
            size_t gv = (rowb + r) * 64 + ch * 8;
            CP16(sa + off,        kf + gk);
            CP16(sa + 8192 + off, vf + gv);
        }
        CP_COMMIT();
    };

    load_pair(0, 0);

    CP_WAIT1();
    __syncthreads();

    uint32_t Aqf[4][4];
    {
        const int tile = lane >> 3, rin = lane & 7;
        #pragma unroll
        for (int g = 0; g < 4; g++) {
            int row = w * 16 + (tile & 1) * 8 + rin;
            int ch  = 2 * g + (tile >> 1);
            uint32_t off = sw128((uint32_t)(row * 128 + ch * 16));
            LDSM4(Aqf[g][0], Aqf[g][1], Aqf[g][2], Aqf[g][3], qb + off);
        }
    }

    float m0r = -1e30f, m1r = -1e30f, l0r = 0.f, l1r = 0.f;
    float o[8][4];
    #pragma unroll
    for (int j = 0; j < 8; j++)
        #pragma unroll
        for (int e = 0; e < 4; e++) o[j][e] = 0.f;

    const int npairs = qi + 1;

    for (int p = 0; p < npairs; p++) {
        CP_WAIT0();
        __syncthreads();
        if (p + 1 < npairs) load_pair((p + 1) & 1, p + 1);

        #pragma unroll
        for (int sub = 0; sub < 2; sub++) {
            const int kt = 2 * p + sub;
            const bool skip = (kt * 64) > (q0 + w * 16 + 15);
            if (skip) continue;

            const uint32_t sa = sb + (p & 1) * AT_STAGE + sub * AT_SUB;
            const int tile = lane >> 3, rin = lane & 7;

            float s[8][4];
            #pragma unroll
            for (int j = 0; j < 8; j++)
                #pragma unroll
                for (int e = 0; e < 4; e++) s[j][e] = 0.f;

            #pragma unroll
            for (int g = 0; g < 4; g++) {
                uint32_t bh[8][2];
                #pragma unroll
                for (int pp = 0; pp < 4; pp++) {
                    int row = 16 * pp + (tile >> 1) * 8 + rin;
                    int ch  = 2 * g + (tile & 1);
                    uint32_t off = sw128((uint32_t)(row * 128 + ch * 16));
                    uint32_t r0, r1, r2, r3;
                    LDSM4(r0, r1, r2, r3, sa + off);
                    bh[2*pp][0] = r0; bh[2*pp][1] = r1;
                    bh[2*pp+1][0] = r2; bh[2*pp+1][1] = r3;
                }
                #pragma unroll
                for (int j = 0; j < 8; j++)
                    MMAF16(s[j], Aqf[g], bh[j]);
            }

            const int gr0 = q0 + w * 16 + (lane >> 2);
            if (kt * 64 + 63 > q0 + w * 16) {
                #pragma unroll
                for (int j = 0; j < 8; j++) {
                    int col = kt * 64 + j * 8 + 2 * (lane & 3);
                    if (col     > gr0)     s[j][0] = -1e30f;
                    if (col + 1 > gr0)     s[j][1] = -1e30f;
                    if (col     > gr0 + 8) s[j][2] = -1e30f;
                    if (col + 1 > gr0 + 8) s[j][3] = -1e30f;
                }
            }

            float mx0 = -1e30f, mx1 = -1e30f;
            #pragma unroll
            for (int j = 0; j < 8; j++) {
                mx0 = fmaxf(mx0, fmaxf(s[j][0], s[j][1]));
                mx1 = fmaxf(mx1, fmaxf(s[j][2], s[j][3]));
            }
            mx0 = fmaxf(mx0, __shfl_xor_sync(0xffffffffu, mx0, 1));
            mx0 = fmaxf(mx0, __shfl_xor_sync(0xffffffffu, mx0, 2));
            mx1 = fmaxf(mx1, __shfl_xor_sync(0xffffffffu, mx1, 1));
            mx1 = fmaxf(mx1, __shfl_xor_sync(0xffffffffu, mx1, 2));

            float mn0 = fmaxf(m0r, mx0), mn1 = fmaxf(m1r, mx1);
            float c0 = exp2f(m0r - mn0), c1 = exp2f(m1r - mn1);
            float sum0 = 0.f, sum1 = 0.f;
            #pragma unroll
            for (int j = 0; j < 8; j++) {
                s[j][0] = exp2f(s[j][0] - mn0);
                s[j][1] = exp2f(s[j][1] - mn0);
                s[j][2] = exp2f(s[j][2] - mn1);
                s[j][3] = exp2f(s[j][3] - mn1);
                sum0 += s[j][0] + s[j][1];
                sum1 += s[j][2] + s[j][3];
            }
            sum0 += __shfl_xor_sync(0xffffffffu, sum0, 1);
            sum0 += __shfl_xor_sync(0xffffffffu, sum0, 2);
            sum1 += __shfl_xor_sync(0xffffffffu, sum1, 1);
            sum1 += __shfl_xor_sync(0xffffffffu, sum1, 2);
            m0r = mn0; m1r = mn1;
            l0r = l0r * c0 + sum0;
            l1r = l1r * c1 + sum1;

            uint32_t Apf[4][4];
            #pragma unroll
            for (int g = 0; g < 4; g++) {
                Apf[g][0] = pack_h2(s[2*g][0],   s[2*g][1]);
                Apf[g][1] = pack_h2(s[2*g][2],   s[2*g][3]);
                Apf[g][2] = pack_h2(s[2*g+1][0], s[2*g+1][1]);
                Apf[g][3] = pack_h2(s[2*g+1][2], s[2*g+1][3]);
            }

            #pragma unroll
            for (int j = 0; j < 8; j++) {
                o[j][0] *= c0; o[j][1] *= c0;
                o[j][2] *= c1; o[j][3] *= c1;
            }

            #pragma unroll
            for (int g = 0; g < 4; g++) {
                uint32_t bvf[8][2];
                #pragma unroll
                for (int pp = 0; pp < 4; pp++) {
                    int row = 16 * g + (tile & 1) * 8 + rin;
                    int ch  = 2 * pp + (tile >> 1);
                    uint32_t off = sw128((uint32_t)(row * 128 + ch * 16));
                    uint32_t r0, r1, r2, r3;
                    LDSM4T(r0, r1, r2, r3, sa + 8192 + off);
                    bvf[2*pp][0] = r0; bvf[2*pp][1] = r1;
                    bvf[2*pp+1][0] = r2; bvf[2*pp+1][1] = r3;
                }
                #pragma unroll
                for (int j = 0; j < 8; j++)
                    MMAF16(o[j], Apf[g], bvf[j]);
            }
        }
    }

    const float inv0 = 1.f / l0r, inv1 = 1.f / l1r;
    const int gr0 = q0 + w * 16 + (lane >> 2);
    float* base = attn_out + (((size_t)b * NHH + h) * TT) * DHH;
    #pragma unroll
    for (int j = 0; j < 8; j++) {
        int col = j * 8 + 2 * (lane & 3);
        float2 v0, v1;
        v0.x = o[j][0] * inv0; v0.y = o[j][1] * inv0;
        v1.x = o[j][2] * inv1; v1.y = o[j][3] * inv1;
        *(float2*)(base + (size_t)gr0 * DHH + col)       = v0;
        *(float2*)(base + (size_t)(gr0 + 8) * DHH + col) = v1;
    }
}

// ---------------------------------------------------------------------------
// Head-mean pooling fused with bf16 hi/lo split output
// ---------------------------------------------------------------------------
__global__ __launch_bounds__(256) void head_mean_split(
    const float* __restrict__ attn, __nv_bfloat16* __restrict__ mh,
    __nv_bfloat16* __restrict__ ml)
{
    int idx = blockIdx.x * blockDim.x + threadIdx.x;
    int d4 = idx & 15;
    int bt = idx >> 4;
    int b  = bt / TT;
    int t  = bt % TT;
    float4 acc = make_float4(0.f, 0.f, 0.f, 0.f);
    #pragma unroll
    for (int h = 0; h < NHH; h++) {
        float4 vv = *(const float4*)&attn[(((size_t)b*NHH + h)*TT + t)*DHH + d4*4];
        acc.x += vv.x; acc.y += vv.y; acc.z += vv.z; acc.w += vv.w;
    }
    const float inv = 1.f / (float)NHH;
    uint32_t h01, l01, h23, l23;
    split2(acc.x * inv, acc.y * inv, h01, l01);
    split2(acc.z * inv, acc.w * inv, h23, l23);
    size_t o = (size_t)bt * DHH + d4 * 4;
    *(uint32_t*)(mh + o)     = h01;
    *(uint32_t*)(mh + o + 2) = h23;
    *(uint32_t*)(ml + o)     = l01;
    *(uint32_t*)(ml + o + 2) = l23;
}

// ---------------------------------------------------------------------------
extern "C" void kernel_launch(void* const* d_in, const int* in_sizes, int n_in,
                              void* d_out, int out_size)
{
    const float* x  = (const float*)d_in[0];
    const float* Wq = (const float*)d_in[1];
    const float* bq = (const float*)d_in[2];
    const float* Wk = (const float*)d_in[3];
    const float* bk = (const float*)d_in[4];
    const float* Wv = (const float*)d_in[5];
    const float* bv = (const float*)d_in[6];
    const float* Wo = (const float*)d_in[7];

    float* out  = (float*)d_out;                      // [32,512,1024]
    float* attn = out + (size_t)MTOT * HH;            // [32,16,512,64]

    float *qbuf, *kbuf, *vbuf, *mbuf;
    __nv_bfloat16 *xbuf, *wthb, *wtoh, *wtol;
    cudaGetSymbolAddress((void**)&qbuf, g_q);
    cudaGetSymbolAddress((void**)&kbuf, g_k);
    cudaGetSymbolAddress((void**)&vbuf, g_v);
    cudaGetSymbolAddress((void**)&mbuf, g_m);
    cudaGetSymbolAddress((void**)&xbuf, g_xh);
    cudaGetSymbolAddress((void**)&wthb, g_wth);
    cudaGetSymbolAddress((void**)&wtoh, g_wtoh);
    cudaGetSymbolAddress((void**)&wtol, g_wtol);

    __half* qf = (__half*)qbuf;
    __half* kf = (__half*)kbuf;
    __half* vf = (__half*)vbuf;
    __half* xf = (__half*)xbuf;
    __half* wf = (__half*)wthb;
    __nv_bfloat16* mh = (__nv_bfloat16*)mbuf;
    __nv_bfloat16* ml = mh + (size_t)MTOT * DHH;

    cudaFuncSetAttribute(qkv_gemm, cudaFuncAttributeMaxDynamicSharedMemorySize,
                         QK_SMEM);
    cudaFuncSetAttribute(attn_mma, cudaFuncAttributeMaxDynamicSharedMemorySize,
                         AT_SMEM);
    cudaFuncSetAttribute(out_gemm, cudaFuncAttributeMaxDynamicSharedMemorySize,
                         OG_SMEM);

    dim3 blk(256);

    // fp16 conversions
    convert_xh<<<dim3(((size_t)MTOT*HH/4)/256), blk>>>(x, xf);
    tconv_h<<<dim3(32, 32), blk>>>(Wq, wf, HH, HH);
    tconv_h<<<dim3(32, 32), blk>>>(Wk, wf + (size_t)HH*HH, HH, HH);
    tconv_h<<<dim3(2, 32),  blk>>>(Wv, wf + (size_t)2*HH*HH, HH, 64);
    tsplit<<<dim3(32, 2),  blk>>>(Wo, wtoh, wtol, 64, HH);

    // Q+K+V projections (fp16 single-pass, 2 CTAs/SM)
    qkv_gemm<<<dim3(17, MTOT/128), blk, QK_SMEM>>>(xf, wf,
                                                   bq, bk, bv, qf, kf, vf);

    // Tensor-core causal attention (fp16, exp2 softmax, 2 CTAs/SM)
    attn_mma<<<dim3(TT/128, NHH, BSZ), blk, AT_SMEM>>>(qf, kf, vf, attn);

    // Head mean (+bf16 split) and O projection (bf16 3-pass)
    head_mean_split<<<dim3((MTOT * (DHH/4)) / 256), blk>>>(attn, mh, ml);
    out_gemm<<<dim3(8, MTOT/128), blk, OG_SMEM>>>(mh, ml, wtoh, wtol, out);
}

// round 11
// speedup vs baseline: 7.7928x; 1.0299x over previous
#include <cuda_runtime.h>
#include <cuda_bf16.h>
#include <cuda_fp16.h>
#include <math.h>
#include <stdint.h>

#define BSZ 32
#define TT  512
#define HH  1024
#define DHH 64
#define NHH 16
#define MTOT (BSZ*TT)   // 16384

// ---------------------------------------------------------------------------
// Scratch (device globals: allocation-free contract)
// ---------------------------------------------------------------------------
__device__ float g_q[(size_t)MTOT * HH];             // -> qf fp16
__device__ float g_k[(size_t)MTOT * HH];             // -> kf fp16
__device__ float g_v[(size_t)MTOT * DHH];            // -> vf fp16
__device__ float g_m[(size_t)MTOT * DHH];            // -> mf fp16
__device__ __nv_bfloat16 g_xh[(size_t)MTOT * HH];    // -> xf fp16
// W^T fp16 single: Wq^T | Wk^T | Wv^T rows, stride HH
__device__ __nv_bfloat16 g_wth[(size_t)2 * HH * HH + 64 * HH];
// Wo^T fp16 single: 1024 rows x 64 cols
__device__ __nv_bfloat16 g_wtoh[(size_t)HH * 64];

// ---------------------------------------------------------------------------
// Baseline-ISA PTX helpers
// ---------------------------------------------------------------------------
__device__ __forceinline__ uint32_t su32(const void* p) {
    uint32_t a;
    asm("{ .reg .u64 t; cvta.to.shared.u64 t, %1; cvt.u32.u64 %0, t; }"
        : "=r"(a) : "l"(p));
    return a;
}
#define CP16(dst, src) \
    asm volatile("cp.async.cg.shared.global [%0], [%1], 16;" \
                 :: "r"(dst), "l"(src))
#define CP_COMMIT() asm volatile("cp.async.commit_group;" ::: "memory")
#define CP_WAIT1()  asm volatile("cp.async.wait_group 1;" ::: "memory")
#define CP_WAIT0()  asm volatile("cp.async.wait_group 0;" ::: "memory")
#define LDSM4(r0, r1, r2, r3, addr) \
    asm volatile("ldmatrix.sync.aligned.m8n8.x4.shared.b16 {%0,%1,%2,%3}, [%4];" \
                 : "=r"(r0), "=r"(r1), "=r"(r2), "=r"(r3) : "r"(addr))
#define LDSM4T(r0, r1, r2, r3, addr) \
    asm volatile("ldmatrix.sync.aligned.m8n8.x4.trans.shared.b16 {%0,%1,%2,%3}, [%4];" \
                 : "=r"(r0), "=r"(r1), "=r"(r2), "=r"(r3) : "r"(addr))
#define MMAF16(d, a, b) \
    asm volatile("mma.sync.aligned.m16n8k16.row.col.f32.f16.f16.f32 " \
                 "{%0,%1,%2,%3}, {%4,%5,%6,%7}, {%8,%9}, {%0,%1,%2,%3};" \
                 : "+f"((d)[0]), "+f"((d)[1]), "+f"((d)[2]), "+f"((d)[3]) \
                 : "r"((a)[0]), "r"((a)[1]), "r"((a)[2]), "r"((a)[3]), \
                   "r"((b)[0]), "r"((b)[1]))

__device__ __forceinline__ uint32_t sw128(uint32_t off) {
    return off ^ ((off >> 3) & 0x70u);
}
__device__ __forceinline__ uint32_t pack_h2(float a, float b) {
    __half2 h = __floats2half2_rn(a, b);
    return *(uint32_t*)&h;
}

// ---------------------------------------------------------------------------
// fp32 -> fp16 single
// ---------------------------------------------------------------------------
__global__ __launch_bounds__(256) void convert_xh(
    const float* __restrict__ x, __half* __restrict__ xf)
{
    size_t i = ((size_t)blockIdx.x * blockDim.x + threadIdx.x) * 4;
    float4 v = *(const float4*)(x + i);
    *(uint32_t*)(xf + i)     = pack_h2(v.x, v.y);
    *(uint32_t*)(xf + i + 2) = pack_h2(v.z, v.w);
}

// ---------------------------------------------------------------------------
// Fused weight transpose to fp16 single. blockIdx.z selects:
//   0: Wq [1024,1024] -> wf
//   1: Wk [1024,1024] -> wf + HH*HH
//   2: Wv [1024,64]   -> wf + 2*HH*HH   (grid.x covers 2 tiles only)
//   3: Wo [64,1024]   -> wof            (grid.y covers 2 tiles only)
// grid (32, 32, 4); excess tiles exit early.
// ---------------------------------------------------------------------------
__global__ __launch_bounds__(256) void tconv_all(
    const float* __restrict__ wq, const float* __restrict__ wk,
    const float* __restrict__ wv, const float* __restrict__ wo,
    __half* __restrict__ wf, __half* __restrict__ wof)
{
    const int z = blockIdx.z;
    const float* src;
    __half* dst;
    int R, C;
    if (z == 0)      { src = wq; dst = wf;                       R = HH; C = HH; }
    else if (z == 1) { src = wk; dst = wf + (size_t)HH * HH;     R = HH; C = HH; }
    else if (z == 2) { src = wv; dst = wf + (size_t)2 * HH * HH; R = HH; C = 64; }
    else             { src = wo; dst = wof;                      R = 64; C = HH; }

    int c0 = blockIdx.x * 32, r0 = blockIdx.y * 32;
    if (c0 >= C || r0 >= R) return;

    __shared__ float t[32][33];
    int tx = threadIdx.x & 31, ty = threadIdx.x >> 5;
    #pragma unroll
    for (int j = 0; j < 4; j++)
        t[ty + j*8][tx] = src[(size_t)(r0 + ty + j*8) * C + c0 + tx];
    __syncthreads();
    #pragma unroll
    for (int j = 0; j < 4; j++) {
        int ro = c0 + ty + j*8;
        int co = r0 + tx;
        dst[(size_t)ro * R + co] = __float2half(t[tx][ty + j*8]);
    }
}

// ---------------------------------------------------------------------------
// Fused Q+K+V projection: single-pass fp16 mma, 2 CTAs/SM.
// Outputs q,k,v as fp16 singles (Q pre-scaled 0.125*log2e for exp2 softmax).
// ---------------------------------------------------------------------------
#define QK_STAGE 32768
#define QK_SMEM  (3 * QK_STAGE)
#define QSCALE   (0.125f * 1.44269504088896f)

__global__ __launch_bounds__(256, 2) void qkv_gemm(
    const __half* __restrict__ xf, const __half* __restrict__ wf,
    const float* __restrict__ bq, const float* __restrict__ bk,
    const float* __restrict__ bv,
    __half* __restrict__ qf, __half* __restrict__ kf,
    __half* __restrict__ vf)
{
    extern __shared__ char smem[];
    const uint32_t sb = su32(smem);
    const int tid = threadIdx.x;
    const int lane = tid & 31;
    const int wid = tid >> 5;
    const int warp_m = wid & 3;
    const int warp_n = wid >> 2;

    const int ntile = blockIdx.x;
    const int which = ntile >> 3;        // 0=Q, 1=K, 2=V
    const int n0 = (ntile & 7) * 128;
    const int m0 = blockIdx.y * 128;

    const __half* wb = wf + (size_t)which * HH * HH;

    float c[2][8][4];
    #pragma unroll
    for (int tm = 0; tm < 2; tm++)
        #pragma unroll
        for (int j = 0; j < 8; j++)
            #pragma unroll
            for (int r = 0; r < 4; r++) c[tm][j][r] = 0.f;

    auto load_stage = [&](int stage, int k0) {
        const uint32_t sa = sb + stage * QK_STAGE;
        #pragma unroll
        for (int i = 0; i < 4; i++) {
            int s = tid + (i << 8);
            int r = s >> 3, ch = s & 7;
            uint32_t off = sw128((uint32_t)(r * 128 + ch * 16));
            const size_t ga = (size_t)(m0 + r) * HH + k0 + ch * 8;
            const int br = (which == 2) ? (r & 63) : r;
            const size_t gb = (size_t)(n0 + br) * HH + k0 + ch * 8;
            CP16(sa + off,         xf + ga);
            CP16(sa + 16384 + off, wb + gb);
        }
        CP_COMMIT();
    };

    load_stage(0, 0);
    load_stage(1, 64);

    for (int cch = 0; cch < 16; cch++) {
        if (cch + 2 < 16) CP_WAIT1(); else CP_WAIT0();
        __syncthreads();
        if (cch + 2 < 16) load_stage((cch + 2) % 3, (cch + 2) * 64);

        const uint32_t sa = sb + (cch % 3) * QK_STAGE;
        #pragma unroll
        for (int kk = 0; kk < 4; kk++) {
            const int kc0 = kk * 2;
            uint32_t af[2][4];
            {
                const int mat = lane >> 3, rin = lane & 7;
                #pragma unroll
                for (int tm = 0; tm < 2; tm++) {
                    int row = warp_m * 32 + tm * 16 + (mat & 1) * 8 + rin;
                    int ch  = kc0 + (mat >> 1);
                    uint32_t off = sw128((uint32_t)(row * 128 + ch * 16));
                    LDSM4(af[tm][0], af[tm][1], af[tm][2], af[tm][3], sa + off);
                }
            }
            uint32_t bf[8][2];
            {
                const int mat = lane >> 3, rin = lane & 7;
                #pragma unroll
                for (int jp = 0; jp < 4; jp++) {
                    int grp = jp * 2 + (mat >> 1);
                    int ch  = kc0 + (mat & 1);
                    int row = warp_n * 64 + grp * 8 + rin;
                    uint32_t off = sw128((uint32_t)(row * 128 + ch * 16));
                    uint32_t r0, r1, r2, r3;
                    LDSM4(r0, r1, r2, r3, sa + 16384 + off);
                    bf[jp*2][0] = r0; bf[jp*2][1] = r1;
                    bf[jp*2+1][0] = r2; bf[jp*2+1][1] = r3;
                }
            }
            #pragma unroll
            for (int tm = 0; tm < 2; tm++)
                #pragma unroll
                for (int j = 0; j < 8; j++)
                    MMAF16(c[tm][j], af[tm], bf[j]);
        }
    }

    // ---- epilogue: fp16 single outputs ----
    if (which == 2) {
        if (warp_n == 0) {
            #pragma unroll
            for (int tm = 0; tm < 2; tm++) {
                #pragma unroll
                for (int j = 0; j < 8; j++) {
                    int gnl = j * 8 + 2 * (lane & 3);
                    float2 bv2 = *(const float2*)&bv[gnl];
                    int gm0 = m0 + warp_m * 32 + tm * 16 + (lane >> 2);
                    uint32_t p0 = pack_h2(c[tm][j][0] + bv2.x,
                                          c[tm][j][1] + bv2.y);
                    uint32_t p1 = pack_h2(c[tm][j][2] + bv2.x,
                                          c[tm][j][3] + bv2.y);
                    *(uint32_t*)(vf + (size_t)gm0 * 64 + gnl)       = p0;
                    *(uint32_t*)(vf + (size_t)(gm0 + 8) * 64 + gnl) = p1;
                }
            }
        }
        return;
    }

    const float scale = (which == 0) ? QSCALE : 1.0f;
    const float* bias = (which == 0) ? bq : bk;
    __half* of = (which == 0) ? qf : kf;

    #pragma unroll
    for (int tm = 0; tm < 2; tm++) {
        #pragma unroll
        for (int j = 0; j < 8; j++) {
            int gnl = warp_n * 64 + j * 8 + 2 * (lane & 3);
            float2 bv2 = *(const float2*)&bias[n0 + gnl];
            int gm0 = m0 + warp_m * 32 + tm * 16 + (lane >> 2);
            uint32_t p0 = pack_h2((c[tm][j][0] + bv2.x) * scale,
                                  (c[tm][j][1] + bv2.y) * scale);
            uint32_t p1 = pack_h2((c[tm][j][2] + bv2.x) * scale,
                                  (c[tm][j][3] + bv2.y) * scale);
            *(uint32_t*)(of + (size_t)gm0 * HH + n0 + gnl)       = p0;
            *(uint32_t*)(of + (size_t)(gm0 + 8) * HH + n0 + gnl) = p1;
        }
    }
}

// ---------------------------------------------------------------------------
// O projection: out[M,1024] = m[M,64] @ Wo[64,1024], fp16 single-pass, K=64.
// Stage: A 16K | B 16K = 32 KB.
// ---------------------------------------------------------------------------
#define OG_SMEM 32768

__global__ __launch_bounds__(256, 2) void out_gemm(
    const __half* __restrict__ mf, const __half* __restrict__ wof,
    float* __restrict__ out)
{
    extern __shared__ char smem[];
    const uint32_t sb = su32(smem);
    const int tid = threadIdx.x;
    const int lane = tid & 31;
    const int wid = tid >> 5;
    const int warp_m = wid & 3;
    const int warp_n = wid >> 2;
    const int n0 = blockIdx.x * 128;
    const int m0 = blockIdx.y * 128;

    #pragma unroll
    for (int i = 0; i < 4; i++) {
        int s = tid + (i << 8);
        int r = s >> 3, ch = s & 7;
        uint32_t off = sw128((uint32_t)(r * 128 + ch * 16));
        const size_t ga = (size_t)(m0 + r) * 64 + ch * 8;
        const size_t gb = (size_t)(n0 + r) * 64 + ch * 8;
        CP16(sb + off,         mf + ga);
        CP16(sb + 16384 + off, wof + gb);
    }
    CP_COMMIT();
    CP_WAIT0();
    __syncthreads();

    float c[2][8][4];
    #pragma unroll
    for (int tm = 0; tm < 2; tm++)
        #pragma unroll
        for (int j = 0; j < 8; j++)
            #pragma unroll
            for (int r = 0; r < 4; r++) c[tm][j][r] = 0.f;

    #pragma unroll
    for (int kk = 0; kk < 4; kk++) {
        const int kc0 = kk * 2;
        uint32_t af[2][4];
        {
            const int mat = lane >> 3, rin = lane & 7;
            #pragma unroll
            for (int tm = 0; tm < 2; tm++) {
                int row = warp_m * 32 + tm * 16 + (mat & 1) * 8 + rin;
                int ch  = kc0 + (mat >> 1);
                uint32_t off = sw128((uint32_t)(row * 128 + ch * 16));
                LDSM4(af[tm][0], af[tm][1], af[tm][2], af[tm][3], sb + off);
            }
        }
        uint32_t bf[8][2];
        {
            const int mat = lane >> 3, rin = lane & 7;
            #pragma unroll
            for (int jp = 0; jp < 4; jp++) {
                int grp = jp * 2 + (mat >> 1);
                int ch  = kc0 + (mat & 1);
                int row = warp_n * 64 + grp * 8 + rin;
                uint32_t off = sw128((uint32_t)(row * 128 + ch * 16));
                uint32_t r0, r1, r2, r3;
                LDSM4(r0, r1, r2, r3, sb + 16384 + off);
                bf[jp*2][0] = r0; bf[jp*2][1] = r1;
                bf[jp*2+1][0] = r2; bf[jp*2+1][1] = r3;
            }
        }
        #pragma unroll
        for (int tm = 0; tm < 2; tm++)
            #pragma unroll
            for (int j = 0; j < 8; j++)
                MMAF16(c[tm][j], af[tm], bf[j]);
    }

    #pragma unroll
    for (int tm = 0; tm < 2; tm++) {
        #pragma unroll
        for (int j = 0; j < 8; j++) {
            int gn = n0 + warp_n * 64 + j * 8 + 2 * (lane & 3);
            int gm0 = m0 + warp_m * 32 + tm * 16 + (lane >> 2);
            float2 o0, o1;
            o0.x = c[tm][j][0]; o0.y = c[tm][j][1];
            o1.x = c[tm][j][2]; o1.y = c[tm][j][3];
            *(float2*)&out[(size_t)gm0 * HH + gn]       = o0;
            *(float2*)&out[(size_t)(gm0 + 8) * HH + gn] = o1;
        }
    }
}

// ---------------------------------------------------------------------------
// Tensor-core causal flash attention — fp16 single-pass, exp2 softmax,
// 2 CTAs/SM (unchanged from R10).
// ---------------------------------------------------------------------------
#define AT_SUB   16384
#define AT_STAGE (2 * AT_SUB)
#define AT_SMEM  (2 * AT_STAGE + 16384)   // 81920

__global__ __launch_bounds__(256, 2) void attn_mma(
    const __half* __restrict__ qf, const __half* __restrict__ kf,
    const __half* __restrict__ vf,
    float* __restrict__ attn_out)
{
    extern __shared__ char smem[];
    const uint32_t sb = su32(smem);
    const uint32_t qb = sb + 2 * AT_STAGE;
    const int tid = threadIdx.x;
    const int lane = tid & 31;
    const int w = tid >> 5;

    const int b  = blockIdx.z;
    const int h  = blockIdx.y;
    const int qi = (TT / 128 - 1) - blockIdx.x;
    const int q0 = qi * 128;

    #pragma unroll
    for (int i = 0; i < 4; i++) {
        int idx = tid + (i << 8);
        int r = idx >> 3, ch = idx & 7;
        uint32_t off = sw128((uint32_t)(r * 128 + ch * 16));
        size_t g = (size_t)(b * TT + q0 + r) * HH + h * 64 + ch * 8;
        CP16(qb + off, qf + g);
    }
    CP_COMMIT();

    auto load_pair = [&](int stg, int p) {
        const uint32_t sa = sb + stg * AT_STAGE;
        const size_t rowb = (size_t)(b * TT + p * 128);
        #pragma unroll
        for (int i = 0; i < 4; i++) {
            int idx = tid + (i << 8);
            int r = idx >> 3, ch = idx & 7;
            uint32_t sub = (uint32_t)(r >> 6) * AT_SUB;
            uint32_t off = sub + sw128((uint32_t)((r & 63) * 128 + ch * 16));
            size_t gk = (rowb + r) * HH + h * 64 + ch * 8;
            size_t gv = (rowb + r) * 64 + ch * 8;
            CP16(sa + off,        kf + gk);
            CP16(sa + 8192 + off, vf + gv);
        }
        CP_COMMIT();
    };

    load_pair(0, 0);

    CP_WAIT1();
    __syncthreads();

    uint32_t Aqf[4][4];
    {
        const int tile = lane >> 3, rin = lane & 7;
        #pragma unroll
        for (int g = 0; g < 4; g++) {
            int row = w * 16 + (tile & 1) * 8 + rin;
            int ch  = 2 * g + (tile >> 1);
            uint32_t off = sw128((uint32_t)(row * 128 + ch * 16));
            LDSM4(Aqf[g][0], Aqf[g][1], Aqf[g][2], Aqf[g][3], qb + off);
        }
    }

    float m0r = -1e30f, m1r = -1e30f, l0r = 0.f, l1r = 0.f;
    float o[8][4];
    #pragma unroll
    for (int j = 0; j < 8; j++)
        #pragma unroll
        for (int e = 0; e < 4; e++) o[j][e] = 0.f;

    const int npairs = qi + 1;

    for (int p = 0; p < npairs; p++) {
        CP_WAIT0();
        __syncthreads();
        if (p + 1 < npairs) load_pair((p + 1) & 1, p + 1);

        #pragma unroll
        for (int sub = 0; sub < 2; sub++) {
            const int kt = 2 * p + sub;
            const bool skip = (kt * 64) > (q0 + w * 16 + 15);
            if (skip) continue;

            const uint32_t sa = sb + (p & 1) * AT_STAGE + sub * AT_SUB;
            const int tile = lane >> 3, rin = lane & 7;

            float s[8][4];
            #pragma unroll
            for (int j = 0; j < 8; j++)
                #pragma unroll
                for (int e = 0; e < 4; e++) s[j][e] = 0.f;

            #pragma unroll
            for (int g = 0; g < 4; g++) {
                uint32_t bh[8][2];
                #pragma unroll
                for (int pp = 0; pp < 4; pp++) {
                    int row = 16 * pp + (tile >> 1) * 8 + rin;
                    int ch  = 2 * g + (tile & 1);
                    uint32_t off = sw128((uint32_t)(row * 128 + ch * 16));
                    uint32_t r0, r1, r2, r3;
                    LDSM4(r0, r1, r2, r3, sa + off);
                    bh[2*pp][0] = r0; bh[2*pp][1] = r1;
                    bh[2*pp+1][0] = r2; bh[2*pp+1][1] = r3;
                }
                #pragma unroll
                for (int j = 0; j < 8; j++)
                    MMAF16(s[j], Aqf[g], bh[j]);
            }

            const int gr0 = q0 + w * 16 + (lane >> 2);
            if (kt * 64 + 63 > q0 + w * 16) {
                #pragma unroll
                for (int j = 0; j < 8; j++) {
                    int col = kt * 64 + j * 8 + 2 * (lane & 3);
                    if (col     > gr0)     s[j][0] = -1e30f;
                    if (col + 1 > gr0)     s[j][1] = -1e30f;
                    if (col     > gr0 + 8) s[j][2] = -1e30f;
                    if (col + 1 > gr0 + 8) s[j][3] = -1e30f;
                }
            }

            float mx0 = -1e30f, mx1 = -1e30f;
            #pragma unroll
            for (int j = 0; j < 8; j++) {
                mx0 = fmaxf(mx0, fmaxf(s[j][0], s[j][1]));
                mx1 = fmaxf(mx1, fmaxf(s[j][2], s[j][3]));
            }
            mx0 = fmaxf(mx0, __shfl_xor_sync(0xffffffffu, mx0, 1));
            mx0 = fmaxf(mx0, __shfl_xor_sync(0xffffffffu, mx0, 2));
            mx1 = fmaxf(mx1, __shfl_xor_sync(0xffffffffu, mx1, 1));
            mx1 = fmaxf(mx1, __shfl_xor_sync(0xffffffffu, mx1, 2));

            float mn0 = fmaxf(m0r, mx0), mn1 = fmaxf(m1r, mx1);
            float c0 = exp2f(m0r - mn0), c1 = exp2f(m1r - mn1);
            float sum0 = 0.f, sum1 = 0.f;
            #pragma unroll
            for (int j = 0; j < 8; j++) {
                s[j][0] = exp2f(s[j][0] - mn0);
                s[j][1] = exp2f(s[j][1] - mn0);
                s[j][2] = exp2f(s[j][2] - mn1);
                s[j][3] = exp2f(s[j][3] - mn1);
                sum0 += s[j][0] + s[j][1];
                sum1 += s[j][2] + s[j][3];
            }
            sum0 += __shfl_xor_sync(0xffffffffu, sum0, 1);
            sum0 += __shfl_xor_sync(0xffffffffu, sum0, 2);
            sum1 += __shfl_xor_sync(0xffffffffu, sum1, 1);
            sum1 += __shfl_xor_sync(0xffffffffu, sum1, 2);
            m0r = mn0; m1r = mn1;
            l0r = l0r * c0 + sum0;
            l1r = l1r * c1 + sum1;

            uint32_t Apf[4][4];
            #pragma unroll
            for (int g = 0; g < 4; g++) {
                Apf[g][0] = pack_h2(s[2*g][0],   s[2*g][1]);
                Apf[g][1] = pack_h2(s[2*g][2],   s[2*g][3]);
                Apf[g][2] = pack_h2(s[2*g+1][0], s[2*g+1][1]);
                Apf[g][3] = pack_h2(s[2*g+1][2], s[2*g+1][3]);
            }

            #pragma unroll
            for (int j = 0; j < 8; j++) {
                o[j][0] *= c0; o[j][1] *= c0;
                o[j][2] *= c1; o[j][3] *= c1;
            }

            #pragma unroll
            for (int g = 0; g < 4; g++) {
                uint32_t bvf[8][2];
                #pragma unroll
                for (int pp = 0; pp < 4; pp++) {
                    int row = 16 * g + (tile & 1) * 8 + rin;
                    int ch  = 2 * pp + (tile >> 1);
                    uint32_t off = sw128((uint32_t)(row * 128 + ch * 16));
                    uint32_t r0, r1, r2, r3;
                    LDSM4T(r0, r1, r2, r3, sa + 8192 + off);
                    bvf[2*pp][0] = r0; bvf[2*pp][1] = r1;
                    bvf[2*pp+1][0] = r2; bvf[2*pp+1][1] = r3;
                }
                #pragma unroll
                for (int j = 0; j < 8; j++)
                    MMAF16(o[j], Apf[g], bvf[j]);
            }
        }
    }

    const float inv0 = 1.f / l0r, inv1 = 1.f / l1r;
    const int gr0 = q0 + w * 16 + (lane >> 2);
    float* base = attn_out + (((size_t)b * NHH + h) * TT) * DHH;
    #pragma unroll
    for (int j = 0; j < 8; j++) {
        int col = j * 8 + 2 * (lane & 3);
        float2 v0, v1;
        v0.x = o[j][0] * inv0; v0.y = o[j][1] * inv0;
        v1.x = o[j][2] * inv1; v1.y = o[j][3] * inv1;
        *(float2*)(base + (size_t)gr0 * DHH + col)       = v0;
        *(float2*)(base + (size_t)(gr0 + 8) * DHH + col) = v1;
    }
}

// ---------------------------------------------------------------------------
// Head-mean pooling -> fp16 output
// ---------------------------------------------------------------------------
__global__ __launch_bounds__(256) void head_mean_h(
    const float* __restrict__ attn, __half* __restrict__ mf)
{
    int idx = blockIdx.x * blockDim.x + threadIdx.x;
    int d4 = idx & 15;
    int bt = idx >> 4;
    int b  = bt / TT;
    int t  = bt % TT;
    float4 acc = make_float4(0.f, 0.f, 0.f, 0.f);
    #pragma unroll
    for (int h = 0; h < NHH; h++) {
        float4 vv = *(const float4*)&attn[(((size_t)b*NHH + h)*TT + t)*DHH + d4*4];
        acc.x += vv.x; acc.y += vv.y; acc.z += vv.z; acc.w += vv.w;
    }
    const float inv = 1.f / (float)NHH;
    size_t o = (size_t)bt * DHH + d4 * 4;
    *(uint32_t*)(mf + o)     = pack_h2(acc.x * inv, acc.y * inv);
    *(uint32_t*)(mf + o + 2) = pack_h2(acc.z * inv, acc.w * inv);
}

// ---------------------------------------------------------------------------
extern "C" void kernel_launch(void* const* d_in, const int* in_sizes, int n_in,
                              void* d_out, int out_size)
{
    const float* x  = (const float*)d_in[0];
    const float* Wq = (const float*)d_in[1];
    const float* bq = (const float*)d_in[2];
    const float* Wk = (const float*)d_in[3];
    const float* bk = (const float*)d_in[4];
    const float* Wv = (const float*)d_in[5];
    const float* bv = (const float*)d_in[6];
    const float* Wo = (const float*)d_in[7];

    float* out  = (float*)d_out;                      // [32,512,1024]
    float* attn = out + (size_t)MTOT * HH;            // [32,16,512,64]

    float *qbuf, *kbuf, *vbuf, *mbuf;
    __nv_bfloat16 *xbuf, *wthb, *wtob;
    cudaGetSymbolAddress((void**)&qbuf, g_q);
    cudaGetSymbolAddress((void**)&kbuf, g_k);
    cudaGetSymbolAddress((void**)&vbuf, g_v);
    cudaGetSymbolAddress((void**)&mbuf, g_m);
    cudaGetSymbolAddress((void**)&xbuf, g_xh);
    cudaGetSymbolAddress((void**)&wthb, g_wth);
    cudaGetSymbolAddress((void**)&wtob, g_wtoh);

    __half* qf  = (__half*)qbuf;
    __half* kf  = (__half*)kbuf;
    __half* vf  = (__half*)vbuf;
    __half* mf  = (__half*)mbuf;
    __half* xf  = (__half*)xbuf;
    __half* wf  = (__half*)wthb;
    __half* wof = (__half*)wtob;

    cudaFuncSetAttribute(qkv_gemm, cudaFuncAttributeMaxDynamicSharedMemorySize,
                         QK_SMEM);
    cudaFuncSetAttribute(attn_mma, cudaFuncAttributeMaxDynamicSharedMemorySize,
                         AT_SMEM);
    cudaFuncSetAttribute(out_gemm, cudaFuncAttributeMaxDynamicSharedMemorySize,
                         OG_SMEM);

    dim3 blk(256);

    // fp16 conversions (x + all four weights in one grid)
    convert_xh<<<dim3(((size_t)MTOT*HH/4)/256), blk>>>(x, xf);
    tconv_all<<<dim3(32, 32, 4), blk>>>(Wq, Wk, Wv, Wo, wf, wof);

    // Q+K+V projections (fp16 single-pass, 2 CTAs/SM)
    qkv_gemm<<<dim3(17, MTOT/128), blk, QK_SMEM>>>(xf, wf,
                                                   bq, bk, bv, qf, kf, vf);

    // Tensor-core causal attention (fp16, exp2 softmax, 2 CTAs/SM)
    attn_mma<<<dim3(TT/128, NHH, BSZ), blk, AT_SMEM>>>(qf, kf, vf, attn);

    // Head mean (fp16) and O projection (fp16 single-pass)
    head_mean_h<<<dim3((MTOT * (DHH/4)) / 256), blk>>>(attn, mf);
    out_gemm<<<dim3(8, MTOT/128), blk, OG_SMEM>>>(mf, wof, out);
}